// round 1
// baseline (speedup 1.0000x reference)
#include <cuda_runtime.h>
#include <math.h>

#define NN 40000
#define NE 640000
#define NG 1024
#define DD 128

// ---------------- scratch (device globals; no allocations allowed) -------------
__device__ float g_h   [NN * 128];
__device__ float g_yab [NN * 256];   // A|B table per layer; reused as fc1 output
__device__ float g_agg [NN * 128];
__device__ float g_pre [NN * 128];
__device__ float g_wab [3 * 128 * 256];
__device__ float g_bab [3 * 256];
__device__ float g_M   [3 * 16 * 128];
__device__ int   g_deg [NN];
__device__ int   g_row [NN + 1];
__device__ int   g_cur [NN];
__device__ int   g_psrc[NE];
__device__ int   g_peid[NE];
__device__ float g_gsum[NG];
__device__ float g_gcnt[NG];

// ---------------- small utility kernels ----------------------------------------
__global__ void k_zero() {
    int i = blockIdx.x * blockDim.x + threadIdx.x;
    if (i < NN) g_deg[i] = 0;
    if (i < NG) { g_gsum[i] = 0.f; g_gcnt[i] = 0.f; }
}

__global__ void k_hist(const int* __restrict__ batch) {
    int i = blockIdx.x * blockDim.x + threadIdx.x;
    if (i < NN) atomicAdd(&g_gcnt[batch[i]], 1.0f);
}

__global__ void k_deg(const int* __restrict__ dst) {
    int e = blockIdx.x * blockDim.x + threadIdx.x;
    if (e < NE) atomicAdd(&g_deg[dst[e]], 1);
}

__global__ void k_scan() {
    __shared__ int ssum[1024];
    const int CH = 40;                       // 1024*40 >= 40000
    int t = threadIdx.x;
    int base = t * CH;
    int s = 0;
    for (int i = 0; i < CH; i++) {
        int idx = base + i;
        if (idx < NN) s += g_deg[idx];
    }
    ssum[t] = s;
    __syncthreads();
    for (int off = 1; off < 1024; off <<= 1) {
        int v = 0;
        if (t >= off) v = ssum[t - off];
        __syncthreads();
        ssum[t] += v;
        __syncthreads();
    }
    int run = ssum[t] - s;                   // exclusive
    for (int i = 0; i < CH; i++) {
        int idx = base + i;
        if (idx < NN) {
            g_row[idx] = run;
            g_cur[idx] = run;
            run += g_deg[idx];
        }
    }
    if (t == 1023) g_row[NN] = ssum[1023];
}

__global__ void k_fill(const int* __restrict__ src, const int* __restrict__ dst) {
    int e = blockIdx.x * blockDim.x + threadIdx.x;
    if (e < NE) {
        int d = dst[e];
        int p = atomicAdd(&g_cur[d], 1);
        g_psrc[p] = src[e];
        g_peid[p] = e;
    }
}

// pack Wab[l][k][c]: c<128 -> W1 (src part), c>=128 -> W2 (dst part)
__global__ void k_pack_wab(const float* __restrict__ msgW) {
    int idx = blockIdx.x * blockDim.x + threadIdx.x;
    if (idx >= 3 * 128 * 256) return;
    int l = idx / (128 * 256);
    int k = (idx / 256) & 127;
    int c = idx & 255;
    const float* Wl = msgW + (size_t)l * 384 * 128;
    g_wab[idx] = (c < 128) ? Wl[k * 128 + c] : Wl[(128 + k) * 128 + (c - 128)];
}

// M[l] = bonds_W @ W3[l] (16x128), bias_a[l] = msg_b[l] + bonds_b @ W3[l]
__global__ void k_pack_mb(const float* __restrict__ bondsW, const float* __restrict__ bondsb,
                          const float* __restrict__ msgW, const float* __restrict__ msgb) {
    int idx = blockIdx.x * blockDim.x + threadIdx.x;
    if (idx < 3 * 16 * 128) {
        int l = idx / 2048;
        int k = (idx / 128) & 15;
        int d = idx & 127;
        const float* W3 = msgW + (size_t)l * 384 * 128 + 256 * 128;
        float s = 0.f;
        for (int j = 0; j < 128; j++) s += bondsW[k * 128 + j] * W3[j * 128 + d];
        g_M[idx] = s;
    } else if (idx < 3 * 16 * 128 + 3 * 128) {
        int i2 = idx - 3 * 16 * 128;
        int l = i2 / 128;
        int d = i2 & 127;
        const float* W3 = msgW + (size_t)l * 384 * 128 + 256 * 128;
        float s = msgb[l * 128 + d];
        for (int j = 0; j < 128; j++) s += bondsb[j] * W3[j * 128 + d];
        g_bab[l * 256 + d] = s;
        g_bab[l * 256 + 128 + d] = 0.f;
    }
}

// ---------------- fp32 SGEMM: Y[nrows x ncols] = [X1|X2] @ W + bias (opt relu) --
// 128x128 tile, 256 threads, 8x8 per thread. K1,K2 multiples of 32.
__global__ void __launch_bounds__(256) k_gemm(
    const float* __restrict__ X1, int K1,
    const float* __restrict__ X2, int K2,
    const float* __restrict__ W, const float* __restrict__ bias,
    float* __restrict__ Y, int nrows, int ncols, int act)
{
    __shared__ float Xs[32][132];
    __shared__ float Ws[32][128];
    int rbase = blockIdx.x * 128;
    int cbase = blockIdx.y * 128;
    int tid = threadIdx.x;
    int tx = tid & 15, ty = tid >> 4;
    int lr = tid >> 3, lc4 = tid & 7;        // X tile loads
    int wr = tid >> 5, wc4 = tid & 31;       // W tile loads
    float acc[8][8];
#pragma unroll
    for (int i = 0; i < 8; i++)
#pragma unroll
        for (int j = 0; j < 8; j++) acc[i][j] = 0.f;

    int Ktot = K1 + K2;
    for (int k0 = 0; k0 < Ktot; k0 += 32) {
        const float* Xp; int xs, kk0;
        if (k0 < K1) { Xp = X1; xs = K1; kk0 = k0; }
        else         { Xp = X2; xs = K2; kk0 = k0 - K1; }
#pragma unroll
        for (int i = 0; i < 4; i++) {
            int r = lr + 32 * i;
            int gr = rbase + r;
            float4 v = make_float4(0.f, 0.f, 0.f, 0.f);
            if (gr < nrows) v = *(const float4*)(Xp + (size_t)gr * xs + kk0 + 4 * lc4);
            Xs[4 * lc4 + 0][r] = v.x;
            Xs[4 * lc4 + 1][r] = v.y;
            Xs[4 * lc4 + 2][r] = v.z;
            Xs[4 * lc4 + 3][r] = v.w;
        }
#pragma unroll
        for (int i = 0; i < 4; i++) {
            int k = wr + 8 * i;
            *(float4*)(&Ws[k][4 * wc4]) = *(const float4*)(W + (size_t)(k0 + k) * ncols + cbase + 4 * wc4);
        }
        __syncthreads();
#pragma unroll 8
        for (int kk = 0; kk < 32; kk++) {
            float a[8], b[8];
            *(float4*)(a)     = *(const float4*)(&Xs[kk][ty * 8]);
            *(float4*)(a + 4) = *(const float4*)(&Xs[kk][ty * 8 + 4]);
            *(float4*)(b)     = *(const float4*)(&Ws[kk][tx * 8]);
            *(float4*)(b + 4) = *(const float4*)(&Ws[kk][tx * 8 + 4]);
#pragma unroll
            for (int i = 0; i < 8; i++)
#pragma unroll
                for (int j = 0; j < 8; j++) acc[i][j] += a[i] * b[j];
        }
        __syncthreads();
    }
#pragma unroll
    for (int i = 0; i < 8; i++) {
        int gr = rbase + ty * 8 + i;
        if (gr >= nrows) break;
#pragma unroll
        for (int j = 0; j < 8; j += 4) {
            float4 v;
            v.x = acc[i][j + 0] + bias[cbase + tx * 8 + j + 0];
            v.y = acc[i][j + 1] + bias[cbase + tx * 8 + j + 1];
            v.z = acc[i][j + 2] + bias[cbase + tx * 8 + j + 2];
            v.w = acc[i][j + 3] + bias[cbase + tx * 8 + j + 3];
            if (act == 1) {
                v.x = fmaxf(v.x, 0.f); v.y = fmaxf(v.y, 0.f);
                v.z = fmaxf(v.z, 0.f); v.w = fmaxf(v.w, 0.f);
            }
            *(float4*)(Y + (size_t)gr * ncols + cbase + tx * 8 + j) = v;
        }
    }
}

// ---------------- fused message + LN + tanh + aggregate (warp per dst node) ----
__device__ __forceinline__ float fast_tanh(float y) {
    y = fminf(fmaxf(y, -15.f), 15.f);
    float t = __expf(2.f * y);
    return __fdividef(t - 1.f, t + 1.f);
}

__global__ void __launch_bounds__(256) k_msg(
    const float* __restrict__ yab, const float* __restrict__ Mw,
    const float* __restrict__ lnw, const float* __restrict__ lnb,
    const float* __restrict__ raw, float* __restrict__ agg)
{
    int warp = (blockIdx.x * blockDim.x + threadIdx.x) >> 5;
    int lane = threadIdx.x & 31;
    if (warp >= NN) return;

    float Mreg[16][4];
#pragma unroll
    for (int k = 0; k < 16; k++)
#pragma unroll
        for (int j = 0; j < 4; j++) Mreg[k][j] = Mw[k * 128 + lane + 32 * j];

    float bj[4], lw[4], lb[4], accj[4];
#pragma unroll
    for (int j = 0; j < 4; j++) {
        bj[j] = yab[(size_t)warp * 256 + 128 + lane + 32 * j];
        lw[j] = lnw[lane + 32 * j];
        lb[j] = lnb[lane + 32 * j];
        accj[j] = 0.f;
    }

    int p0 = g_row[warp], p1 = g_row[warp + 1];
    for (int p = p0; p < p1; p++) {
        int src = g_psrc[p];
        int eid = g_peid[p];
        const float* ar = yab + (size_t)src * 256;
        const float4* rp = (const float4*)(raw + (size_t)eid * 16);
        float4 r0 = rp[0], r1 = rp[1], r2 = rp[2], r3 = rp[3];
        float rv[16] = {r0.x, r0.y, r0.z, r0.w, r1.x, r1.y, r1.z, r1.w,
                        r2.x, r2.y, r2.z, r2.w, r3.x, r3.y, r3.z, r3.w};
        float pre[4];
#pragma unroll
        for (int j = 0; j < 4; j++) {
            float c = bj[j] + ar[lane + 32 * j];
#pragma unroll
            for (int k = 0; k < 16; k++) c = fmaf(rv[k], Mreg[k][j], c);
            pre[j] = c;
        }
        float s = pre[0] + pre[1] + pre[2] + pre[3];
        float q = pre[0] * pre[0];
        q = fmaf(pre[1], pre[1], q);
        q = fmaf(pre[2], pre[2], q);
        q = fmaf(pre[3], pre[3], q);
#pragma unroll
        for (int off = 16; off > 0; off >>= 1) {
            s += __shfl_xor_sync(0xffffffffu, s, off);
            q += __shfl_xor_sync(0xffffffffu, q, off);
        }
        float mean = s * (1.f / 128.f);
        float var = q * (1.f / 128.f) - mean * mean;
        float rstd = rsqrtf(var + 1e-5f);
#pragma unroll
        for (int j = 0; j < 4; j++) {
            float y = (pre[j] - mean) * rstd * lw[j] + lb[j];
            accj[j] += fast_tanh(y);
        }
    }
#pragma unroll
    for (int j = 0; j < 4; j++) agg[(size_t)warp * 128 + lane + 32 * j] = accj[j];
}

// ---------------- per-node LayerNorm + tanh (warp per node) ---------------------
__global__ void __launch_bounds__(256) k_lntanh(
    const float* __restrict__ pre, const float* __restrict__ lnw,
    const float* __restrict__ lnb, float* __restrict__ out)
{
    int warp = (blockIdx.x * blockDim.x + threadIdx.x) >> 5;
    int lane = threadIdx.x & 31;
    if (warp >= NN) return;
    float v[4];
#pragma unroll
    for (int j = 0; j < 4; j++) v[j] = pre[(size_t)warp * 128 + lane + 32 * j];
    float s = v[0] + v[1] + v[2] + v[3];
    float q = v[0] * v[0];
    q = fmaf(v[1], v[1], q);
    q = fmaf(v[2], v[2], q);
    q = fmaf(v[3], v[3], q);
#pragma unroll
    for (int off = 16; off > 0; off >>= 1) {
        s += __shfl_xor_sync(0xffffffffu, s, off);
        q += __shfl_xor_sync(0xffffffffu, q, off);
    }
    float mean = s * (1.f / 128.f);
    float var = q * (1.f / 128.f) - mean * mean;
    float rstd = rsqrtf(var + 1e-5f);
#pragma unroll
    for (int j = 0; j < 4; j++) {
        float y = (v[j] - mean) * rstd * lnw[lane + 32 * j] + lnb[lane + 32 * j];
        out[(size_t)warp * 128 + lane + 32 * j] = fast_tanh(y);
    }
}

// ---------------- fc2 dot + graph pooling ---------------------------------------
__global__ void __launch_bounds__(256) k_fc2pool(
    const float* __restrict__ R, const float* __restrict__ fc2w,
    const float* __restrict__ fc2b, const int* __restrict__ batch)
{
    int warp = (blockIdx.x * blockDim.x + threadIdx.x) >> 5;
    int lane = threadIdx.x & 31;
    if (warp >= NN) return;
    float s = 0.f;
#pragma unroll
    for (int j = 0; j < 8; j++)
        s = fmaf(R[(size_t)warp * 256 + lane + 32 * j], fc2w[lane + 32 * j], s);
#pragma unroll
    for (int off = 16; off > 0; off >>= 1) s += __shfl_xor_sync(0xffffffffu, s, off);
    if (lane == 0) atomicAdd(&g_gsum[batch[warp]], s + fc2b[0]);
}

__global__ void k_final(float* __restrict__ out) {
    int g = blockIdx.x * blockDim.x + threadIdx.x;
    if (g < NG) out[g] = g_gsum[g] / fmaxf(g_gcnt[g], 1.0f);
}

// ---------------- host orchestration --------------------------------------------
extern "C" void kernel_launch(void* const* d_in, const int* in_sizes, int n_in,
                              void* d_out, int out_size)
{
    const float* x      = (const float*)d_in[0];
    const int*   ei     = (const int*)  d_in[1];
    const float* raw    = (const float*)d_in[2];
    const int*   batch  = (const int*)  d_in[3];
    const float* atomsW = (const float*)d_in[4];
    const float* atomsb = (const float*)d_in[5];
    const float* bondsW = (const float*)d_in[6];
    const float* bondsb = (const float*)d_in[7];
    const float* msgW   = (const float*)d_in[8];
    const float* msgb   = (const float*)d_in[9];
    const float* msglnw = (const float*)d_in[10];
    const float* msglnb = (const float*)d_in[11];
    const float* updW   = (const float*)d_in[12];
    const float* updb   = (const float*)d_in[13];
    const float* updlnw = (const float*)d_in[14];
    const float* updlnb = (const float*)d_in[15];
    const float* fc1W   = (const float*)d_in[16];
    const float* fc1b   = (const float*)d_in[17];
    const float* fc2w   = (const float*)d_in[18];
    const float* fc2b   = (const float*)d_in[19];
    float* out = (float*)d_out;

    const int* src = ei;
    const int* dst = ei + NE;

    float *p_h, *p_yab, *p_agg, *p_pre, *p_wab, *p_bab, *p_M;
    cudaGetSymbolAddress((void**)&p_h,   g_h);
    cudaGetSymbolAddress((void**)&p_yab, g_yab);
    cudaGetSymbolAddress((void**)&p_agg, g_agg);
    cudaGetSymbolAddress((void**)&p_pre, g_pre);
    cudaGetSymbolAddress((void**)&p_wab, g_wab);
    cudaGetSymbolAddress((void**)&p_bab, g_bab);
    cudaGetSymbolAddress((void**)&p_M,   g_M);

    // init + weight packing + CSR build
    k_zero<<<(NN + 255) / 256, 256>>>();
    k_pack_wab<<<(3 * 128 * 256 + 255) / 256, 256>>>(msgW);
    k_pack_mb<<<(3 * 16 * 128 + 3 * 128 + 255) / 256, 256>>>(bondsW, bondsb, msgW, msgb);
    k_hist<<<(NN + 255) / 256, 256>>>(batch);
    k_deg<<<(NE + 255) / 256, 256>>>(dst);
    k_scan<<<1, 1024>>>();
    k_fill<<<(NE + 255) / 256, 256>>>(src, dst);

    dim3 g128((NN + 127) / 128, 1);
    dim3 g256((NN + 127) / 128, 2);

    // embed: h = x @ atoms_W + atoms_b
    k_gemm<<<g128, 256>>>(x, 64, (const float*)0, 0, atomsW, atomsb, p_h, NN, 128, 0);

    for (int l = 0; l < 3; l++) {
        // A|B = h @ [W1|W2] (+folded bias in A half)
        k_gemm<<<g256, 256>>>(p_h, 128, (const float*)0, 0,
                              p_wab + (size_t)l * 128 * 256, p_bab + l * 256,
                              p_yab, NN, 256, 0);
        // message + LN + tanh + aggregate
        k_msg<<<(NN * 32 + 255) / 256, 256>>>(p_yab, p_M + l * 16 * 128,
                                              msglnw + l * 128, msglnb + l * 128,
                                              raw, p_agg);
        // update: pre = [agg|h] @ upd_W + upd_b
        k_gemm<<<g128, 256>>>(p_agg, 128, p_h, 128,
                              updW + (size_t)l * 256 * 128, updb + l * 128,
                              p_pre, NN, 128, 0);
        // h = tanh(LN(pre))
        k_lntanh<<<(NN * 32 + 255) / 256, 256>>>(p_pre, updlnw + l * 128, updlnb + l * 128, p_h);
    }

    // readout: R = relu(h @ fc1 + b1); out = segment_mean(R @ fc2 + b2)
    k_gemm<<<g256, 256>>>(p_h, 128, (const float*)0, 0, fc1W, fc1b, p_yab, NN, 256, 1);
    k_fc2pool<<<(NN * 32 + 255) / 256, 256>>>(p_yab, fc2w, fc2b, batch);
    k_final<<<(NG + 255) / 256, 256>>>(out);
}

// round 2
// speedup vs baseline: 1.1911x; 1.1911x over previous
#include <cuda_runtime.h>
#include <cuda_bf16.h>
#include <math.h>
#include <stdint.h>

#define NN 40000
#define NE 640000
#define NG 1024

// ---------------- scratch (device globals; no allocations allowed) -------------
__device__ float g_yab [NN * 256];   // A|B table per layer; reused as fc1 output
__device__ float g_pre [NN * 128];
__device__ float g_bab [3 * 256];
__device__ float g_M   [3 * 16 * 128];

__device__ __nv_bfloat16 g_xh  [NN * 64],  g_xl  [NN * 64];
__device__ __nv_bfloat16 g_hh  [NN * 128], g_hl  [NN * 128];
__device__ __nv_bfloat16 g_aggh[NN * 128], g_aggl[NN * 128];
__device__ __nv_bfloat16 g_wabt_h[3 * 256 * 128], g_wabt_l[3 * 256 * 128];
__device__ __nv_bfloat16 g_updt_h[3 * 128 * 256], g_updt_l[3 * 128 * 256];
__device__ __nv_bfloat16 g_fc1t_h[256 * 128],     g_fc1t_l[256 * 128];
__device__ __nv_bfloat16 g_atmt_h[128 * 64],      g_atmt_l[128 * 64];

__device__ int   g_deg [NN];
__device__ int   g_row [NN + 1];
__device__ int   g_cur [NN];
__device__ int   g_psrc[NE];
__device__ int   g_peid[NE];
__device__ float g_gsum[NG];
__device__ float g_gcnt[NG];

// ---------------- small utility kernels ----------------------------------------
__global__ void k_zero() {
    int i = blockIdx.x * blockDim.x + threadIdx.x;
    if (i < NN) g_deg[i] = 0;
    if (i < NG) { g_gsum[i] = 0.f; g_gcnt[i] = 0.f; }
}

__global__ void k_hist(const int* __restrict__ batch) {
    int i = blockIdx.x * blockDim.x + threadIdx.x;
    if (i < NN) atomicAdd(&g_gcnt[batch[i]], 1.0f);
}

__global__ void k_deg(const int* __restrict__ dst) {
    int e = blockIdx.x * blockDim.x + threadIdx.x;
    if (e < NE) atomicAdd(&g_deg[dst[e]], 1);
}

__global__ void k_scan() {
    __shared__ int ssum[1024];
    const int CH = 40;
    int t = threadIdx.x;
    int base = t * CH;
    int s = 0;
    for (int i = 0; i < CH; i++) {
        int idx = base + i;
        if (idx < NN) s += g_deg[idx];
    }
    ssum[t] = s;
    __syncthreads();
    for (int off = 1; off < 1024; off <<= 1) {
        int v = 0;
        if (t >= off) v = ssum[t - off];
        __syncthreads();
        ssum[t] += v;
        __syncthreads();
    }
    int run = ssum[t] - s;
    for (int i = 0; i < CH; i++) {
        int idx = base + i;
        if (idx < NN) {
            g_row[idx] = run;
            g_cur[idx] = run;
            run += g_deg[idx];
        }
    }
    if (t == 1023) g_row[NN] = ssum[1023];
}

__global__ void k_fill(const int* __restrict__ src, const int* __restrict__ dst) {
    int e = blockIdx.x * blockDim.x + threadIdx.x;
    if (e < NE) {
        int d = dst[e];
        int p = atomicAdd(&g_cur[d], 1);
        g_psrc[p] = src[e];
        g_peid[p] = e;
    }
}

// ---------------- fp32 -> bf16 hi/lo split helpers -------------------------------
__device__ __forceinline__ void split_bf16(float v, __nv_bfloat16& h, __nv_bfloat16& l) {
    h = __float2bfloat16(v);
    l = __float2bfloat16(v - __bfloat162float(h));
}

__global__ void k_split(const float* __restrict__ in, __nv_bfloat16* __restrict__ hi,
                        __nv_bfloat16* __restrict__ lo, int n) {
    int i = blockIdx.x * blockDim.x + threadIdx.x;
    if (i < n) { __nv_bfloat16 h, l; split_bf16(in[i], h, l); hi[i] = h; lo[i] = l; }
}

// transpose+split: W[K][N] row-major  ->  out[N][K] bf16 hi/lo
__global__ void k_tsplit(const float* __restrict__ W, int K, int N,
                         __nv_bfloat16* __restrict__ hi, __nv_bfloat16* __restrict__ lo) {
    int idx = blockIdx.x * blockDim.x + threadIdx.x;
    if (idx >= N * K) return;
    int n = idx / K, k = idx % K;
    __nv_bfloat16 h, l; split_bf16(W[(size_t)k * N + n], h, l);
    hi[idx] = h; lo[idx] = l;
}

// pack [W1|W2] transposed: out[l][n(256)][k(128)]
__global__ void k_pack_wabt(const float* __restrict__ msgW) {
    int idx = blockIdx.x * blockDim.x + threadIdx.x;
    if (idx >= 3 * 256 * 128) return;
    int l = idx / (256 * 128);
    int r = idx % (256 * 128);
    int n = r / 128, k = r % 128;
    const float* Wl = msgW + (size_t)l * 384 * 128;
    float v = (n < 128) ? Wl[k * 128 + n] : Wl[(128 + k) * 128 + (n - 128)];
    __nv_bfloat16 h, lo; split_bf16(v, h, lo);
    g_wabt_h[idx] = h; g_wabt_l[idx] = lo;
}

// M[l] = bonds_W @ W3[l] (16x128), bias_a[l] = msg_b[l] + bonds_b @ W3[l]
__global__ void k_pack_mb(const float* __restrict__ bondsW, const float* __restrict__ bondsb,
                          const float* __restrict__ msgW, const float* __restrict__ msgb) {
    int idx = blockIdx.x * blockDim.x + threadIdx.x;
    if (idx < 3 * 16 * 128) {
        int l = idx / 2048;
        int k = (idx / 128) & 15;
        int d = idx & 127;
        const float* W3 = msgW + (size_t)l * 384 * 128 + 256 * 128;
        float s = 0.f;
        for (int j = 0; j < 128; j++) s += bondsW[k * 128 + j] * W3[j * 128 + d];
        g_M[idx] = s;
    } else if (idx < 3 * 16 * 128 + 3 * 128) {
        int i2 = idx - 3 * 16 * 128;
        int l = i2 / 128;
        int d = i2 & 127;
        const float* W3 = msgW + (size_t)l * 384 * 128 + 256 * 128;
        float s = msgb[l * 128 + d];
        for (int j = 0; j < 128; j++) s += bondsb[j] * W3[j * 128 + d];
        g_bab[l * 256 + d] = s;
        g_bab[l * 256 + 128 + d] = 0.f;
    }
}

// ---------------- bf16x3 tensor-core GEMM ----------------------------------------
// Y[nrows x ncols] = [X1|X2] @ W^T + bias, W stored [ncols][Ktot] (n-major).
// X given as bf16 hi/lo pairs; result = Ah*Bh + Ah*Bl + Al*Bh (fp32 accum).
// 128x128 tile, 256 threads (2x4 warps, each 64x32), m16n8k16.
#define MMA_BF16(d, a, b0, b1) \
    asm volatile("mma.sync.aligned.m16n8k16.row.col.f32.bf16.bf16.f32 " \
        "{%0,%1,%2,%3}, {%4,%5,%6,%7}, {%8,%9}, {%0,%1,%2,%3};" \
        : "+f"(d[0]), "+f"(d[1]), "+f"(d[2]), "+f"(d[3]) \
        : "r"(a[0]), "r"(a[1]), "r"(a[2]), "r"(a[3]), "r"(b0), "r"(b1));

__global__ void __launch_bounds__(256) k_mgemm(
    const __nv_bfloat16* __restrict__ X1h, const __nv_bfloat16* __restrict__ X1l, int K1,
    const __nv_bfloat16* __restrict__ X2h, const __nv_bfloat16* __restrict__ X2l, int K2,
    const __nv_bfloat16* __restrict__ Wh,  const __nv_bfloat16* __restrict__ Wl,
    const float* __restrict__ bias, float* __restrict__ Y,
    __nv_bfloat16* __restrict__ Yh, __nv_bfloat16* __restrict__ Yl,
    int nrows, int ncols, int act)
{
    __shared__ __nv_bfloat16 As_h[128][40], As_l[128][40], Bs_h[128][40], Bs_l[128][40];
    const int tid = threadIdx.x;
    const int wid = tid >> 5, lane = tid & 31;
    const int wm = wid & 1, wn = wid >> 1;          // warp grid 2(m) x 4(n)
    const int g = lane >> 2, t = lane & 3;
    const int rbase = blockIdx.x * 128, cbase = blockIdx.y * 128;
    const int Ktot = K1 + K2;
    const int lr = tid >> 1;       // 0..127
    const int lh = (tid & 1) * 16; // k sub-offset 0/16

    float acc[4][4][4];
#pragma unroll
    for (int i = 0; i < 4; i++)
#pragma unroll
        for (int j = 0; j < 4; j++)
#pragma unroll
            for (int q = 0; q < 4; q++) acc[i][j][q] = 0.f;

    for (int k0 = 0; k0 < Ktot; k0 += 32) {
        // ---- stage A tile (rows of X) ----
        {
            const __nv_bfloat16 *Xh, *Xl; int xs, kk;
            if (k0 < K1) { Xh = X1h; Xl = X1l; xs = K1; kk = k0; }
            else         { Xh = X2h; Xl = X2l; xs = K2; kk = k0 - K1; }
            int gr = rbase + lr;
            uint4 vh0 = {0,0,0,0}, vh1 = {0,0,0,0}, vl0 = {0,0,0,0}, vl1 = {0,0,0,0};
            if (gr < nrows) {
                const __nv_bfloat16* ph = Xh + (size_t)gr * xs + kk + lh;
                const __nv_bfloat16* pl = Xl + (size_t)gr * xs + kk + lh;
                vh0 = *(const uint4*)(ph);
                vh1 = *(const uint4*)(ph + 8);
                vl0 = *(const uint4*)(pl);
                vl1 = *(const uint4*)(pl + 8);
            }
            *(uint4*)&As_h[lr][lh]     = vh0;
            *(uint4*)&As_h[lr][lh + 8] = vh1;
            *(uint4*)&As_l[lr][lh]     = vl0;
            *(uint4*)&As_l[lr][lh + 8] = vl1;
        }
        // ---- stage B tile (rows of W^T, i.e. output columns) ----
        {
            int gn = cbase + lr;
            const size_t off = (size_t)gn * Ktot + k0 + lh;
            *(uint4*)&Bs_h[lr][lh]     = *(const uint4*)(Wh + off);
            *(uint4*)&Bs_h[lr][lh + 8] = *(const uint4*)(Wh + off + 8);
            *(uint4*)&Bs_l[lr][lh]     = *(const uint4*)(Wl + off);
            *(uint4*)&Bs_l[lr][lh + 8] = *(const uint4*)(Wl + off + 8);
        }
        __syncthreads();

#pragma unroll
        for (int s = 0; s < 2; s++) {
            const int ks = 16 * s + 2 * t;
            uint32_t ah[4][4], al[4][4];
#pragma unroll
            for (int mt = 0; mt < 4; mt++) {
                int r0 = wm * 64 + mt * 16 + g;
                ah[mt][0] = *(const uint32_t*)&As_h[r0    ][ks];
                ah[mt][1] = *(const uint32_t*)&As_h[r0 + 8][ks];
                ah[mt][2] = *(const uint32_t*)&As_h[r0    ][ks + 8];
                ah[mt][3] = *(const uint32_t*)&As_h[r0 + 8][ks + 8];
                al[mt][0] = *(const uint32_t*)&As_l[r0    ][ks];
                al[mt][1] = *(const uint32_t*)&As_l[r0 + 8][ks];
                al[mt][2] = *(const uint32_t*)&As_l[r0    ][ks + 8];
                al[mt][3] = *(const uint32_t*)&As_l[r0 + 8][ks + 8];
            }
#pragma unroll
            for (int nt = 0; nt < 4; nt++) {
                int n0 = wn * 32 + nt * 8 + g;
                uint32_t bh0 = *(const uint32_t*)&Bs_h[n0][ks];
                uint32_t bh1 = *(const uint32_t*)&Bs_h[n0][ks + 8];
                uint32_t bl0 = *(const uint32_t*)&Bs_l[n0][ks];
                uint32_t bl1 = *(const uint32_t*)&Bs_l[n0][ks + 8];
#pragma unroll
                for (int mt = 0; mt < 4; mt++) {
                    MMA_BF16(acc[mt][nt], ah[mt], bh0, bh1);
                    MMA_BF16(acc[mt][nt], ah[mt], bl0, bl1);
                    MMA_BF16(acc[mt][nt], al[mt], bh0, bh1);
                }
            }
        }
        __syncthreads();
    }

    // ---- epilogue ----
#pragma unroll
    for (int mt = 0; mt < 4; mt++) {
#pragma unroll
        for (int half = 0; half < 2; half++) {
            int row = rbase + wm * 64 + mt * 16 + g + 8 * half;
            if (row >= nrows) continue;
#pragma unroll
            for (int nt = 0; nt < 4; nt++) {
                int col = cbase + wn * 32 + nt * 8 + 2 * t;
                float v0 = acc[mt][nt][2 * half + 0] + bias[col];
                float v1 = acc[mt][nt][2 * half + 1] + bias[col + 1];
                if (act == 1) { v0 = fmaxf(v0, 0.f); v1 = fmaxf(v1, 0.f); }
                if (Y) {
                    float2 v; v.x = v0; v.y = v1;
                    *(float2*)(Y + (size_t)row * ncols + col) = v;
                }
                if (Yh) {
                    __nv_bfloat16 h0, l0, h1, l1;
                    split_bf16(v0, h0, l0);
                    split_bf16(v1, h1, l1);
                    __nv_bfloat162 hp; hp.x = h0; hp.y = h1;
                    __nv_bfloat162 lp; lp.x = l0; lp.y = l1;
                    *(__nv_bfloat162*)(Yh + (size_t)row * ncols + col) = hp;
                    *(__nv_bfloat162*)(Yl + (size_t)row * ncols + col) = lp;
                }
            }
        }
    }
}

// ---------------- fused message + LN + tanh + aggregate (warp per dst node) ----
__device__ __forceinline__ float fast_tanh(float y) {
    y = fminf(fmaxf(y, -15.f), 15.f);
    float t = __expf(2.f * y);
    return __fdividef(t - 1.f, t + 1.f);
}

__global__ void __launch_bounds__(256) k_msg(
    const float* __restrict__ yab, const float* __restrict__ Mw,
    const float* __restrict__ lnw, const float* __restrict__ lnb,
    const float* __restrict__ raw,
    __nv_bfloat16* __restrict__ aggh, __nv_bfloat16* __restrict__ aggl)
{
    int warp = (blockIdx.x * blockDim.x + threadIdx.x) >> 5;
    int lane = threadIdx.x & 31;
    if (warp >= NN) return;

    float Mreg[16][4];
#pragma unroll
    for (int k = 0; k < 16; k++)
#pragma unroll
        for (int j = 0; j < 4; j++) Mreg[k][j] = Mw[k * 128 + lane + 32 * j];

    float bj[4], lw[4], lb[4], accj[4];
#pragma unroll
    for (int j = 0; j < 4; j++) {
        bj[j] = yab[(size_t)warp * 256 + 128 + lane + 32 * j];
        lw[j] = lnw[lane + 32 * j];
        lb[j] = lnb[lane + 32 * j];
        accj[j] = 0.f;
    }

    int p0 = g_row[warp], p1 = g_row[warp + 1];
    for (int p = p0; p < p1; p++) {
        int src = g_psrc[p];
        int eid = g_peid[p];
        const float* ar = yab + (size_t)src * 256;
        const float4* rp = (const float4*)(raw + (size_t)eid * 16);
        float4 r0 = rp[0], r1 = rp[1], r2 = rp[2], r3 = rp[3];
        float rv[16] = {r0.x, r0.y, r0.z, r0.w, r1.x, r1.y, r1.z, r1.w,
                        r2.x, r2.y, r2.z, r2.w, r3.x, r3.y, r3.z, r3.w};
        float pre[4];
#pragma unroll
        for (int j = 0; j < 4; j++) {
            float c = bj[j] + ar[lane + 32 * j];
#pragma unroll
            for (int k = 0; k < 16; k++) c = fmaf(rv[k], Mreg[k][j], c);
            pre[j] = c;
        }
        float s = pre[0] + pre[1] + pre[2] + pre[3];
        float q = pre[0] * pre[0];
        q = fmaf(pre[1], pre[1], q);
        q = fmaf(pre[2], pre[2], q);
        q = fmaf(pre[3], pre[3], q);
#pragma unroll
        for (int off = 16; off > 0; off >>= 1) {
            s += __shfl_xor_sync(0xffffffffu, s, off);
            q += __shfl_xor_sync(0xffffffffu, q, off);
        }
        float mean = s * (1.f / 128.f);
        float var = q * (1.f / 128.f) - mean * mean;
        float rstd = rsqrtf(var + 1e-5f);
#pragma unroll
        for (int j = 0; j < 4; j++) {
            float y = (pre[j] - mean) * rstd * lw[j] + lb[j];
            accj[j] += fast_tanh(y);
        }
    }
#pragma unroll
    for (int j = 0; j < 4; j++) {
        __nv_bfloat16 h, l; split_bf16(accj[j], h, l);
        aggh[(size_t)warp * 128 + lane + 32 * j] = h;
        aggl[(size_t)warp * 128 + lane + 32 * j] = l;
    }
}

// ---------------- per-node LayerNorm + tanh (warp per node), split output -------
__global__ void __launch_bounds__(256) k_lntanh(
    const float* __restrict__ pre, const float* __restrict__ lnw,
    const float* __restrict__ lnb,
    __nv_bfloat16* __restrict__ outh, __nv_bfloat16* __restrict__ outl)
{
    int warp = (blockIdx.x * blockDim.x + threadIdx.x) >> 5;
    int lane = threadIdx.x & 31;
    if (warp >= NN) return;
    float v[4];
#pragma unroll
    for (int j = 0; j < 4; j++) v[j] = pre[(size_t)warp * 128 + lane + 32 * j];
    float s = v[0] + v[1] + v[2] + v[3];
    float q = v[0] * v[0];
    q = fmaf(v[1], v[1], q);
    q = fmaf(v[2], v[2], q);
    q = fmaf(v[3], v[3], q);
#pragma unroll
    for (int off = 16; off > 0; off >>= 1) {
        s += __shfl_xor_sync(0xffffffffu, s, off);
        q += __shfl_xor_sync(0xffffffffu, q, off);
    }
    float mean = s * (1.f / 128.f);
    float var = q * (1.f / 128.f) - mean * mean;
    float rstd = rsqrtf(var + 1e-5f);
#pragma unroll
    for (int j = 0; j < 4; j++) {
        float y = (v[j] - mean) * rstd * lnw[lane + 32 * j] + lnb[lane + 32 * j];
        __nv_bfloat16 h, l; split_bf16(fast_tanh(y), h, l);
        outh[(size_t)warp * 128 + lane + 32 * j] = h;
        outl[(size_t)warp * 128 + lane + 32 * j] = l;
    }
}

// ---------------- fc2 dot + graph pooling ---------------------------------------
__global__ void __launch_bounds__(256) k_fc2pool(
    const float* __restrict__ R, const float* __restrict__ fc2w,
    const float* __restrict__ fc2b, const int* __restrict__ batch)
{
    int warp = (blockIdx.x * blockDim.x + threadIdx.x) >> 5;
    int lane = threadIdx.x & 31;
    if (warp >= NN) return;
    float s = 0.f;
#pragma unroll
    for (int j = 0; j < 8; j++)
        s = fmaf(R[(size_t)warp * 256 + lane + 32 * j], fc2w[lane + 32 * j], s);
#pragma unroll
    for (int off = 16; off > 0; off >>= 1) s += __shfl_xor_sync(0xffffffffu, s, off);
    if (lane == 0) atomicAdd(&g_gsum[batch[warp]], s + fc2b[0]);
}

__global__ void k_final(float* __restrict__ out) {
    int g = blockIdx.x * blockDim.x + threadIdx.x;
    if (g < NG) out[g] = g_gsum[g] / fmaxf(g_gcnt[g], 1.0f);
}

// ---------------- host orchestration --------------------------------------------
extern "C" void kernel_launch(void* const* d_in, const int* in_sizes, int n_in,
                              void* d_out, int out_size)
{
    const float* x      = (const float*)d_in[0];
    const int*   ei     = (const int*)  d_in[1];
    const float* raw    = (const float*)d_in[2];
    const int*   batch  = (const int*)  d_in[3];
    const float* atomsW = (const float*)d_in[4];
    const float* atomsb = (const float*)d_in[5];
    const float* bondsW = (const float*)d_in[6];
    const float* bondsb = (const float*)d_in[7];
    const float* msgW   = (const float*)d_in[8];
    const float* msgb   = (const float*)d_in[9];
    const float* msglnw = (const float*)d_in[10];
    const float* msglnb = (const float*)d_in[11];
    const float* updW   = (const float*)d_in[12];
    const float* updb   = (const float*)d_in[13];
    const float* updlnw = (const float*)d_in[14];
    const float* updlnb = (const float*)d_in[15];
    const float* fc1W   = (const float*)d_in[16];
    const float* fc1b   = (const float*)d_in[17];
    const float* fc2w   = (const float*)d_in[18];
    const float* fc2b   = (const float*)d_in[19];
    float* out = (float*)d_out;

    const int* src = ei;
    const int* dst = ei + NE;

    float *p_yab, *p_pre, *p_bab, *p_M;
    cudaGetSymbolAddress((void**)&p_yab, g_yab);
    cudaGetSymbolAddress((void**)&p_pre, g_pre);
    cudaGetSymbolAddress((void**)&p_bab, g_bab);
    cudaGetSymbolAddress((void**)&p_M,   g_M);
    __nv_bfloat16 *p_xh, *p_xl, *p_hh, *p_hl, *p_aggh, *p_aggl;
    __nv_bfloat16 *p_wabh, *p_wabl, *p_updh, *p_updl, *p_fc1h, *p_fc1l, *p_atmh, *p_atml;
    cudaGetSymbolAddress((void**)&p_xh,   g_xh);
    cudaGetSymbolAddress((void**)&p_xl,   g_xl);
    cudaGetSymbolAddress((void**)&p_hh,   g_hh);
    cudaGetSymbolAddress((void**)&p_hl,   g_hl);
    cudaGetSymbolAddress((void**)&p_aggh, g_aggh);
    cudaGetSymbolAddress((void**)&p_aggl, g_aggl);
    cudaGetSymbolAddress((void**)&p_wabh, g_wabt_h);
    cudaGetSymbolAddress((void**)&p_wabl, g_wabt_l);
    cudaGetSymbolAddress((void**)&p_updh, g_updt_h);
    cudaGetSymbolAddress((void**)&p_updl, g_updt_l);
    cudaGetSymbolAddress((void**)&p_fc1h, g_fc1t_h);
    cudaGetSymbolAddress((void**)&p_fc1l, g_fc1t_l);
    cudaGetSymbolAddress((void**)&p_atmh, g_atmt_h);
    cudaGetSymbolAddress((void**)&p_atml, g_atmt_l);

    // init + weight packing + CSR build
    k_zero<<<(NN + 255) / 256, 256>>>();
    k_pack_wabt<<<(3 * 256 * 128 + 255) / 256, 256>>>(msgW);
    k_pack_mb<<<(3 * 16 * 128 + 3 * 128 + 255) / 256, 256>>>(bondsW, bondsb, msgW, msgb);
    k_tsplit<<<(128 * 64 + 255) / 256, 256>>>(atomsW, 64, 128, p_atmh, p_atml);
    for (int l = 0; l < 3; l++)
        k_tsplit<<<(128 * 256 + 255) / 256, 256>>>(updW + (size_t)l * 256 * 128, 256, 128,
                                                   p_updh + (size_t)l * 128 * 256,
                                                   p_updl + (size_t)l * 128 * 256);
    k_tsplit<<<(256 * 128 + 255) / 256, 256>>>(fc1W, 128, 256, p_fc1h, p_fc1l);
    k_split<<<(NN * 64 + 255) / 256, 256>>>(x, p_xh, p_xl, NN * 64);
    k_hist<<<(NN + 255) / 256, 256>>>(batch);
    k_deg<<<(NE + 255) / 256, 256>>>(dst);
    k_scan<<<1, 1024>>>();
    k_fill<<<(NE + 255) / 256, 256>>>(src, dst);

    const int RB = (NN + 127) / 128;
    dim3 g128(RB, 1), g256(RB, 2);

    // embed: h = x @ atoms_W + atoms_b  (split output only)
    k_mgemm<<<g128, 256>>>(p_xh, p_xl, 64, (const __nv_bfloat16*)0, (const __nv_bfloat16*)0, 0,
                           p_atmh, p_atml, atomsb, (float*)0, p_hh, p_hl, NN, 128, 0);

    for (int l = 0; l < 3; l++) {
        // A|B = h @ [W1|W2] (+folded bias in A half) -> fp32 yab
        k_mgemm<<<g256, 256>>>(p_hh, p_hl, 128, (const __nv_bfloat16*)0, (const __nv_bfloat16*)0, 0,
                               p_wabh + (size_t)l * 256 * 128, p_wabl + (size_t)l * 256 * 128,
                               p_bab + l * 256, p_yab,
                               (__nv_bfloat16*)0, (__nv_bfloat16*)0, NN, 256, 0);
        // message + LN + tanh + aggregate -> agg (split)
        k_msg<<<(NN * 32 + 255) / 256, 256>>>(p_yab, p_M + l * 16 * 128,
                                              msglnw + l * 128, msglnb + l * 128,
                                              raw, p_aggh, p_aggl);
        // update: pre = [agg|h] @ upd_W + upd_b -> fp32 pre
        k_mgemm<<<g128, 256>>>(p_aggh, p_aggl, 128, p_hh, p_hl, 128,
                               p_updh + (size_t)l * 128 * 256, p_updl + (size_t)l * 128 * 256,
                               updb + l * 128, p_pre,
                               (__nv_bfloat16*)0, (__nv_bfloat16*)0, NN, 128, 0);
        // h = tanh(LN(pre)) (split output)
        k_lntanh<<<(NN * 32 + 255) / 256, 256>>>(p_pre, updlnw + l * 128, updlnb + l * 128,
                                                 p_hh, p_hl);
    }

    // readout: R = relu(h @ fc1 + b1) -> fp32 yab
    k_mgemm<<<g256, 256>>>(p_hh, p_hl, 128, (const __nv_bfloat16*)0, (const __nv_bfloat16*)0, 0,
                           p_fc1h, p_fc1l, fc1b, p_yab,
                           (__nv_bfloat16*)0, (__nv_bfloat16*)0, NN, 256, 1);
    k_fc2pool<<<(NN * 32 + 255) / 256, 256>>>(p_yab, fc2w, fc2b, batch);
    k_final<<<(NG + 255) / 256, 256>>>(out);
}

// round 5
// speedup vs baseline: 1.2518x; 1.0509x over previous
#include <cuda_runtime.h>
#include <cuda_bf16.h>
#include <math.h>
#include <stdint.h>

#define NN 40000
#define NE 640000
#define NG 1024

// ---------------- scratch (device globals; no allocations allowed) -------------
__device__ float g_yab [NN * 256];
__device__ float g_pre [NN * 128];
__device__ float g_bab [3 * 256];
__device__ float g_M   [3 * 16 * 128];

__device__ __nv_bfloat16 g_xh  [NN * 64],  g_xl  [NN * 64];
__device__ __nv_bfloat16 g_hh  [NN * 128], g_hl  [NN * 128];
__device__ __nv_bfloat16 g_aggh[NN * 128], g_aggl[NN * 128];
__device__ __nv_bfloat16 g_wabt_h[3 * 256 * 128], g_wabt_l[3 * 256 * 128];
__device__ __nv_bfloat16 g_updt_h[3 * 128 * 256], g_updt_l[3 * 128 * 256];
__device__ __nv_bfloat16 g_fc1t_h[256 * 128],     g_fc1t_l[256 * 128];
__device__ __nv_bfloat16 g_atmt_h[128 * 64],      g_atmt_l[128 * 64];

__device__ int   g_deg [NN];
__device__ int   g_row [NN + 1];
__device__ int   g_cur [NN];
__device__ int   g_psrc[NE];
__device__ int   g_peid[NE];
__device__ float g_gsum[NG];
__device__ float g_gcnt[NG];

// ---------------- small utility kernels ----------------------------------------
__global__ void k_zero() {
    int i = blockIdx.x * blockDim.x + threadIdx.x;
    if (i < NN) g_deg[i] = 0;
    if (i < NG) { g_gsum[i] = 0.f; g_gcnt[i] = 0.f; }
}
__global__ void k_hist(const int* __restrict__ batch) {
    int i = blockIdx.x * blockDim.x + threadIdx.x;
    if (i < NN) atomicAdd(&g_gcnt[batch[i]], 1.0f);
}
__global__ void k_deg(const int* __restrict__ dst) {
    int e = blockIdx.x * blockDim.x + threadIdx.x;
    if (e < NE) atomicAdd(&g_deg[dst[e]], 1);
}
__global__ void k_scan() {
    __shared__ int ssum[1024];
    const int CH = 40;
    int t = threadIdx.x;
    int base = t * CH;
    int s = 0;
    for (int i = 0; i < CH; i++) { int idx = base + i; if (idx < NN) s += g_deg[idx]; }
    ssum[t] = s;
    __syncthreads();
    for (int off = 1; off < 1024; off <<= 1) {
        int v = 0;
        if (t >= off) v = ssum[t - off];
        __syncthreads();
        ssum[t] += v;
        __syncthreads();
    }
    int run = ssum[t] - s;
    for (int i = 0; i < CH; i++) {
        int idx = base + i;
        if (idx < NN) { g_row[idx] = run; g_cur[idx] = run; run += g_deg[idx]; }
    }
    if (t == 1023) g_row[NN] = ssum[1023];
}
__global__ void k_fill(const int* __restrict__ src, const int* __restrict__ dst) {
    int e = blockIdx.x * blockDim.x + threadIdx.x;
    if (e < NE) {
        int d = dst[e];
        int p = atomicAdd(&g_cur[d], 1);
        g_psrc[p] = src[e];
        g_peid[p] = e;
    }
}

// ---------------- fp32 -> bf16 hi/lo split helpers -------------------------------
__device__ __forceinline__ void split_bf16(float v, __nv_bfloat16& h, __nv_bfloat16& l) {
    h = __float2bfloat16(v);
    l = __float2bfloat16(v - __bfloat162float(h));
}
__global__ void k_split(const float* __restrict__ in, __nv_bfloat16* __restrict__ hi,
                        __nv_bfloat16* __restrict__ lo, int n) {
    int i = blockIdx.x * blockDim.x + threadIdx.x;
    if (i < n) { __nv_bfloat16 h, l; split_bf16(in[i], h, l); hi[i] = h; lo[i] = l; }
}
__global__ void k_tsplit(const float* __restrict__ W, int K, int N,
                         __nv_bfloat16* __restrict__ hi, __nv_bfloat16* __restrict__ lo) {
    int idx = blockIdx.x * blockDim.x + threadIdx.x;
    if (idx >= N * K) return;
    int n = idx / K, k = idx % K;
    __nv_bfloat16 h, l; split_bf16(W[(size_t)k * N + n], h, l);
    hi[idx] = h; lo[idx] = l;
}
__global__ void k_pack_wabt(const float* __restrict__ msgW) {
    int idx = blockIdx.x * blockDim.x + threadIdx.x;
    if (idx >= 3 * 256 * 128) return;
    int l = idx / (256 * 128);
    int r = idx % (256 * 128);
    int n = r / 128, k = r % 128;
    const float* Wl = msgW + (size_t)l * 384 * 128;
    float v = (n < 128) ? Wl[k * 128 + n] : Wl[(128 + k) * 128 + (n - 128)];
    __nv_bfloat16 h, lo; split_bf16(v, h, lo);
    g_wabt_h[idx] = h; g_wabt_l[idx] = lo;
}
__global__ void k_pack_mb(const float* __restrict__ bondsW, const float* __restrict__ bondsb,
                          const float* __restrict__ msgW, const float* __restrict__ msgb) {
    int idx = blockIdx.x * blockDim.x + threadIdx.x;
    if (idx < 3 * 16 * 128) {
        int l = idx / 2048;
        int k = (idx / 128) & 15;
        int d = idx & 127;
        const float* W3 = msgW + (size_t)l * 384 * 128 + 256 * 128;
        float s = 0.f;
        for (int j = 0; j < 128; j++) s += bondsW[k * 128 + j] * W3[j * 128 + d];
        g_M[idx] = s;
    } else if (idx < 3 * 16 * 128 + 3 * 128) {
        int i2 = idx - 3 * 16 * 128;
        int l = i2 / 128;
        int d = i2 & 127;
        const float* W3 = msgW + (size_t)l * 384 * 128 + 256 * 128;
        float s = msgb[l * 128 + d];
        for (int j = 0; j < 128; j++) s += bondsb[j] * W3[j * 128 + d];
        g_bab[l * 256 + d] = s;
        g_bab[l * 256 + 128 + d] = 0.f;
    }
}

// ================= bf16x3 mma.sync GEMM with ldmatrix + cp.async =================
// Y[nrows x ncols] = [X1|X2] @ W^T + bias ; W stored [ncols][Ktot] (n-major).
// 128x128 tile per CTA, 8 warps (2m x 4n, 64x32 each), k-chunk 32, double-buffered.
#define MMA_BF16(d, a, b0, b1) \
    asm volatile("mma.sync.aligned.m16n8k16.row.col.f32.bf16.bf16.f32 " \
        "{%0,%1,%2,%3}, {%4,%5,%6,%7}, {%8,%9}, {%0,%1,%2,%3};" \
        : "+f"(d[0]), "+f"(d[1]), "+f"(d[2]), "+f"(d[3]) \
        : "r"(a[0]), "r"(a[1]), "r"(a[2]), "r"(a[3]), "r"(b0), "r"(b1));

#define LDSM_X4(r, a) \
    asm volatile("ldmatrix.sync.aligned.m8n8.x4.shared.b16 {%0,%1,%2,%3}, [%4];" \
        : "=r"((r)[0]), "=r"((r)[1]), "=r"((r)[2]), "=r"((r)[3]) : "r"(a))

#define CP_ASYNC(sa, ga, sz) \
    asm volatile("cp.async.ca.shared.global [%0], [%1], 16, %2;" :: "r"(sa), "l"(ga), "r"(sz))
#define CP_COMMIT() asm volatile("cp.async.commit_group;" ::: "memory")
#define CP_WAIT(n)  asm volatile("cp.async.wait_group %0;" :: "n"(n) : "memory")

__device__ __forceinline__ uint32_t smem_u32(const void* p) {
    uint32_t a;
    asm("{ .reg .u64 t; cvta.to.shared.u64 t, %1; cvt.u32.u64 %0, t; }" : "=r"(a) : "l"(p));
    return a;
}

// smem layout per buffer (40960B): A_h[128][40] | A_l | B_h | B_l  (stride 80B/row)
#define GEMM_SMEM (2 * 40960)

__global__ void __launch_bounds__(256) k_mgemm(
    const __nv_bfloat16* __restrict__ X1h, const __nv_bfloat16* __restrict__ X1l, int K1,
    const __nv_bfloat16* __restrict__ X2h, const __nv_bfloat16* __restrict__ X2l, int K2,
    const __nv_bfloat16* __restrict__ Wh,  const __nv_bfloat16* __restrict__ Wl,
    const float* __restrict__ bias, float* __restrict__ Y,
    __nv_bfloat16* __restrict__ Yh, __nv_bfloat16* __restrict__ Yl,
    int nrows, int ncols, int act)
{
    extern __shared__ char smem[];
    const uint32_t sb = smem_u32(smem);
    const int tid = threadIdx.x;
    const int wid = tid >> 5, lane = tid & 31;
    const int wm = wid & 1, wn = wid >> 1;
    const int g = lane >> 2, t = lane & 3;
    const int rbase = blockIdx.x * 128, cbase = blockIdx.y * 128;
    const int Ktot = K1 + K2;
    const int nch = Ktot >> 5;

    // staging mapping: each thread loads 2 rows-worth halves (2x16B per tensor)
    const int srow = tid >> 1;            // 0..127
    const int sseg = (tid & 1) * 2;       // 16B segs {0,1} or {2,3}

    float acc[4][4][4];
#pragma unroll
    for (int i = 0; i < 4; i++)
#pragma unroll
        for (int j = 0; j < 4; j++)
#pragma unroll
            for (int q = 0; q < 4; q++) acc[i][j][q] = 0.f;

    // ldmatrix per-lane address components
    const int quad = lane >> 3, li = lane & 7;
    const int a_row = (quad & 1) * 8 + li;       // within 16-row mt tile
    const int a_col = (quad >> 1) * 8;           // within 16-k step
    const int b_row = (quad >> 1) * 8 + li;      // within 16-col nt-pair
    const int b_col = (quad & 1) * 8;

    // ---- staging lambda ----
    auto stage = [&](int ch, int buf) {
        const int kk = ch << 5;
        const uint32_t base = sb + buf * 40960;
        // A rows
        {
            const __nv_bfloat16 *Xh, *Xl; int xs, kx;
            if (kk < K1) { Xh = X1h; Xl = X1l; xs = K1; kx = kk; }
            else         { Xh = X2h; Xl = X2l; xs = K2; kx = kk - K1; }
            int gr = rbase + srow;
            uint32_t sz = (gr < nrows) ? 16u : 0u;
            if (gr >= nrows) gr = nrows - 1;
            const __nv_bfloat16* ph = Xh + (size_t)gr * xs + kx;
            const __nv_bfloat16* pl = Xl + (size_t)gr * xs + kx;
#pragma unroll
            for (int q = 0; q < 2; q++) {
                const int seg = sseg + q;
                const uint32_t so = base + srow * 80 + seg * 16;
                CP_ASYNC(so,         ph + seg * 8, sz);
                CP_ASYNC(so + 10240, pl + seg * 8, sz);
            }
        }
        // B rows (output columns)
        {
            const int gn = cbase + srow;
            const __nv_bfloat16* ph = Wh + (size_t)gn * Ktot + kk;
            const __nv_bfloat16* pl = Wl + (size_t)gn * Ktot + kk;
#pragma unroll
            for (int q = 0; q < 2; q++) {
                const int seg = sseg + q;
                const uint32_t so = base + 20480 + srow * 80 + seg * 16;
                CP_ASYNC(so,         ph + seg * 8, 16u);
                CP_ASYNC(so + 10240, pl + seg * 8, 16u);
            }
        }
        CP_COMMIT();
    };

    stage(0, 0);
    for (int ch = 0; ch < nch; ch++) {
        const int buf = ch & 1;
        const bool more = (ch + 1 < nch);
        if (more) stage(ch + 1, buf ^ 1);
        if (more) { CP_WAIT(1); } else { CP_WAIT(0); }
        __syncthreads();

        const uint32_t base = sb + buf * 40960;
        const uint32_t aah = base + (wm * 64 + a_row) * 80 + a_col * 2;
        const uint32_t bbh = base + 20480 + (wn * 32 + b_row) * 80 + b_col * 2;
#pragma unroll
        for (int s = 0; s < 2; s++) {
            const uint32_t ks2 = s * 32;     // ks*2 bytes
            uint32_t ah[4][4], al[4][4];
#pragma unroll
            for (int mt = 0; mt < 4; mt++) {
                LDSM_X4(ah[mt], aah + mt * 1280 + ks2);
                LDSM_X4(al[mt], aah + 10240 + mt * 1280 + ks2);
            }
            uint32_t bh[4][2], bl[4][2];
#pragma unroll
            for (int pr = 0; pr < 2; pr++) {
                uint32_t tmp[4];
                LDSM_X4(tmp, bbh + pr * 1280 + ks2);
                bh[2 * pr][0] = tmp[0]; bh[2 * pr][1] = tmp[1];
                bh[2 * pr + 1][0] = tmp[2]; bh[2 * pr + 1][1] = tmp[3];
                LDSM_X4(tmp, bbh + 10240 + pr * 1280 + ks2);
                bl[2 * pr][0] = tmp[0]; bl[2 * pr][1] = tmp[1];
                bl[2 * pr + 1][0] = tmp[2]; bl[2 * pr + 1][1] = tmp[3];
            }
#pragma unroll
            for (int nt = 0; nt < 4; nt++)
#pragma unroll
                for (int mt = 0; mt < 4; mt++) {
                    MMA_BF16(acc[mt][nt], ah[mt], bh[nt][0], bh[nt][1]);
                    MMA_BF16(acc[mt][nt], ah[mt], bl[nt][0], bl[nt][1]);
                    MMA_BF16(acc[mt][nt], al[mt], bh[nt][0], bh[nt][1]);
                }
        }
        __syncthreads();
    }

    // ---- epilogue (register fragments -> global) ----
#pragma unroll
    for (int mt = 0; mt < 4; mt++) {
#pragma unroll
        for (int half = 0; half < 2; half++) {
            int row = rbase + wm * 64 + mt * 16 + g + 8 * half;
            if (row >= nrows) continue;
#pragma unroll
            for (int nt = 0; nt < 4; nt++) {
                int col = cbase + wn * 32 + nt * 8 + 2 * t;
                float v0 = acc[mt][nt][2 * half + 0] + bias[col];
                float v1 = acc[mt][nt][2 * half + 1] + bias[col + 1];
                if (act == 1) { v0 = fmaxf(v0, 0.f); v1 = fmaxf(v1, 0.f); }
                if (Y) {
                    float2 v; v.x = v0; v.y = v1;
                    *(float2*)(Y + (size_t)row * ncols + col) = v;
                }
                if (Yh) {
                    __nv_bfloat16 h0, l0, h1, l1;
                    split_bf16(v0, h0, l0);
                    split_bf16(v1, h1, l1);
                    __nv_bfloat162 hp; hp.x = h0; hp.y = h1;
                    __nv_bfloat162 lp; lp.x = l0; lp.y = l1;
                    *(__nv_bfloat162*)(Yh + (size_t)row * ncols + col) = hp;
                    *(__nv_bfloat162*)(Yl + (size_t)row * ncols + col) = lp;
                }
            }
        }
    }
}

// ---------------- fused message + LN + tanh + aggregate (warp per dst node) ----
__device__ __forceinline__ float fast_tanh(float y) {
    y = fminf(fmaxf(y, -15.f), 15.f);
    float t = __expf(2.f * y);
    return __fdividef(t - 1.f, t + 1.f);
}

__global__ void __launch_bounds__(256) k_msg(
    const float* __restrict__ yab, const float* __restrict__ Mw,
    const float* __restrict__ lnw, const float* __restrict__ lnb,
    const float* __restrict__ raw,
    __nv_bfloat16* __restrict__ aggh, __nv_bfloat16* __restrict__ aggl)
{
    int warp = (blockIdx.x * blockDim.x + threadIdx.x) >> 5;
    int lane = threadIdx.x & 31;
    if (warp >= NN) return;

    float Mreg[16][4];
#pragma unroll
    for (int k = 0; k < 16; k++)
#pragma unroll
        for (int j = 0; j < 4; j++) Mreg[k][j] = Mw[k * 128 + lane + 32 * j];

    float bj[4], lw[4], lb[4], accj[4];
#pragma unroll
    for (int j = 0; j < 4; j++) {
        bj[j] = yab[(size_t)warp * 256 + 128 + lane + 32 * j];
        lw[j] = lnw[lane + 32 * j];
        lb[j] = lnb[lane + 32 * j];
        accj[j] = 0.f;
    }

    int p0 = g_row[warp], p1 = g_row[warp + 1];
    for (int p = p0; p < p1; p++) {
        int src = g_psrc[p];
        int eid = g_peid[p];
        const float* ar = yab + (size_t)src * 256;
        const float4* rp = (const float4*)(raw + (size_t)eid * 16);
        float4 r0 = rp[0], r1 = rp[1], r2 = rp[2], r3 = rp[3];
        float rv[16] = {r0.x, r0.y, r0.z, r0.w, r1.x, r1.y, r1.z, r1.w,
                        r2.x, r2.y, r2.z, r2.w, r3.x, r3.y, r3.z, r3.w};
        float pre[4];
#pragma unroll
        for (int j = 0; j < 4; j++) {
            float c = bj[j] + ar[lane + 32 * j];
#pragma unroll
            for (int k = 0; k < 16; k++) c = fmaf(rv[k], Mreg[k][j], c);
            pre[j] = c;
        }
        float s = pre[0] + pre[1] + pre[2] + pre[3];
        float q = pre[0] * pre[0];
        q = fmaf(pre[1], pre[1], q);
        q = fmaf(pre[2], pre[2], q);
        q = fmaf(pre[3], pre[3], q);
#pragma unroll
        for (int off = 16; off > 0; off >>= 1) {
            s += __shfl_xor_sync(0xffffffffu, s, off);
            q += __shfl_xor_sync(0xffffffffu, q, off);
        }
        float mean = s * (1.f / 128.f);
        float var = q * (1.f / 128.f) - mean * mean;
        float rstd = rsqrtf(var + 1e-5f);
#pragma unroll
        for (int j = 0; j < 4; j++) {
            float y = (pre[j] - mean) * rstd * lw[j] + lb[j];
            accj[j] += fast_tanh(y);
        }
    }
#pragma unroll
    for (int j = 0; j < 4; j++) {
        __nv_bfloat16 h, l; split_bf16(accj[j], h, l);
        aggh[(size_t)warp * 128 + lane + 32 * j] = h;
        aggl[(size_t)warp * 128 + lane + 32 * j] = l;
    }
}

// ---------------- per-node LayerNorm + tanh (warp per node), split output -------
__global__ void __launch_bounds__(256) k_lntanh(
    const float* __restrict__ pre, const float* __restrict__ lnw,
    const float* __restrict__ lnb,
    __nv_bfloat16* __restrict__ outh, __nv_bfloat16* __restrict__ outl)
{
    int warp = (blockIdx.x * blockDim.x + threadIdx.x) >> 5;
    int lane = threadIdx.x & 31;
    if (warp >= NN) return;
    float v[4];
#pragma unroll
    for (int j = 0; j < 4; j++) v[j] = pre[(size_t)warp * 128 + lane + 32 * j];
    float s = v[0] + v[1] + v[2] + v[3];
    float q = v[0] * v[0];
    q = fmaf(v[1], v[1], q);
    q = fmaf(v[2], v[2], q);
    q = fmaf(v[3], v[3], q);
#pragma unroll
    for (int off = 16; off > 0; off >>= 1) {
        s += __shfl_xor_sync(0xffffffffu, s, off);
        q += __shfl_xor_sync(0xffffffffu, q, off);
    }
    float mean = s * (1.f / 128.f);
    float var = q * (1.f / 128.f) - mean * mean;
    float rstd = rsqrtf(var + 1e-5f);
#pragma unroll
    for (int j = 0; j < 4; j++) {
        float y = (v[j] - mean) * rstd * lnw[lane + 32 * j] + lnb[lane + 32 * j];
        __nv_bfloat16 h, l; split_bf16(fast_tanh(y), h, l);
        outh[(size_t)warp * 128 + lane + 32 * j] = h;
        outl[(size_t)warp * 128 + lane + 32 * j] = l;
    }
}

// ---------------- fc2 dot + graph pooling ---------------------------------------
__global__ void __launch_bounds__(256) k_fc2pool(
    const float* __restrict__ R, const float* __restrict__ fc2w,
    const float* __restrict__ fc2b, const int* __restrict__ batch)
{
    int warp = (blockIdx.x * blockDim.x + threadIdx.x) >> 5;
    int lane = threadIdx.x & 31;
    if (warp >= NN) return;
    float s = 0.f;
#pragma unroll
    for (int j = 0; j < 8; j++)
        s = fmaf(R[(size_t)warp * 256 + lane + 32 * j], fc2w[lane + 32 * j], s);
#pragma unroll
    for (int off = 16; off > 0; off >>= 1) s += __shfl_xor_sync(0xffffffffu, s, off);
    if (lane == 0) atomicAdd(&g_gsum[batch[warp]], s + fc2b[0]);
}

__global__ void k_final(float* __restrict__ out) {
    int g = blockIdx.x * blockDim.x + threadIdx.x;
    if (g < NG) out[g] = g_gsum[g] / fmaxf(g_gcnt[g], 1.0f);
}

// ---------------- host orchestration --------------------------------------------
extern "C" void kernel_launch(void* const* d_in, const int* in_sizes, int n_in,
                              void* d_out, int out_size)
{
    const float* x      = (const float*)d_in[0];
    const int*   ei     = (const int*)  d_in[1];
    const float* raw    = (const float*)d_in[2];
    const int*   batch  = (const int*)  d_in[3];
    const float* atomsW = (const float*)d_in[4];
    const float* atomsb = (const float*)d_in[5];
    const float* bondsW = (const float*)d_in[6];
    const float* bondsb = (const float*)d_in[7];
    const float* msgW   = (const float*)d_in[8];
    const float* msgb   = (const float*)d_in[9];
    const float* msglnw = (const float*)d_in[10];
    const float* msglnb = (const float*)d_in[11];
    const float* updW   = (const float*)d_in[12];
    const float* updb   = (const float*)d_in[13];
    const float* updlnw = (const float*)d_in[14];
    const float* updlnb = (const float*)d_in[15];
    const float* fc1W   = (const float*)d_in[16];
    const float* fc1b   = (const float*)d_in[17];
    const float* fc2w   = (const float*)d_in[18];
    const float* fc2b   = (const float*)d_in[19];
    float* out = (float*)d_out;

    const int* src = ei;
    const int* dst = ei + NE;

    cudaFuncSetAttribute(k_mgemm, cudaFuncAttributeMaxDynamicSharedMemorySize, GEMM_SMEM);

    float *p_yab, *p_pre, *p_bab, *p_M;
    cudaGetSymbolAddress((void**)&p_yab, g_yab);
    cudaGetSymbolAddress((void**)&p_pre, g_pre);
    cudaGetSymbolAddress((void**)&p_bab, g_bab);
    cudaGetSymbolAddress((void**)&p_M,   g_M);
    __nv_bfloat16 *p_xh, *p_xl, *p_hh, *p_hl, *p_aggh, *p_aggl;
    __nv_bfloat16 *p_wabh, *p_wabl, *p_updh, *p_updl, *p_fc1h, *p_fc1l, *p_atmh, *p_atml;
    cudaGetSymbolAddress((void**)&p_xh,   g_xh);
    cudaGetSymbolAddress((void**)&p_xl,   g_xl);
    cudaGetSymbolAddress((void**)&p_hh,   g_hh);
    cudaGetSymbolAddress((void**)&p_hl,   g_hl);
    cudaGetSymbolAddress((void**)&p_aggh, g_aggh);
    cudaGetSymbolAddress((void**)&p_aggl, g_aggl);
    cudaGetSymbolAddress((void**)&p_wabh, g_wabt_h);
    cudaGetSymbolAddress((void**)&p_wabl, g_wabt_l);
    cudaGetSymbolAddress((void**)&p_updh, g_updt_h);
    cudaGetSymbolAddress((void**)&p_updl, g_updt_l);
    cudaGetSymbolAddress((void**)&p_fc1h, g_fc1t_h);
    cudaGetSymbolAddress((void**)&p_fc1l, g_fc1t_l);
    cudaGetSymbolAddress((void**)&p_atmh, g_atmt_h);
    cudaGetSymbolAddress((void**)&p_atml, g_atmt_l);

    // init + weight packing + CSR build
    k_zero<<<(NN + 255) / 256, 256>>>();
    k_pack_wabt<<<(3 * 256 * 128 + 255) / 256, 256>>>(msgW);
    k_pack_mb<<<(3 * 16 * 128 + 3 * 128 + 255) / 256, 256>>>(bondsW, bondsb, msgW, msgb);
    k_tsplit<<<(128 * 64 + 255) / 256, 256>>>(atomsW, 64, 128, p_atmh, p_atml);
    for (int l = 0; l < 3; l++)
        k_tsplit<<<(128 * 256 + 255) / 256, 256>>>(updW + (size_t)l * 256 * 128, 256, 128,
                                                   p_updh + (size_t)l * 128 * 256,
                                                   p_updl + (size_t)l * 128 * 256);
    k_tsplit<<<(256 * 128 + 255) / 256, 256>>>(fc1W, 128, 256, p_fc1h, p_fc1l);
    k_split<<<(NN * 64 + 255) / 256, 256>>>(x, p_xh, p_xl, NN * 64);
    k_hist<<<(NN + 255) / 256, 256>>>(batch);
    k_deg<<<(NE + 255) / 256, 256>>>(dst);
    k_scan<<<1, 1024>>>();
    k_fill<<<(NE + 255) / 256, 256>>>(src, dst);

    const int RB = (NN + 127) / 128;
    dim3 g128(RB, 1), g256(RB, 2);

    // embed: h = x @ atoms_W + atoms_b  (split output only)
    k_mgemm<<<g128, 256, GEMM_SMEM>>>(p_xh, p_xl, 64,
                                      (const __nv_bfloat16*)0, (const __nv_bfloat16*)0, 0,
                                      p_atmh, p_atml, atomsb, (float*)0, p_hh, p_hl, NN, 128, 0);

    for (int l = 0; l < 3; l++) {
        // A|B = h @ [W1|W2] (+folded bias in A half) -> fp32 yab
        k_mgemm<<<g256, 256, GEMM_SMEM>>>(p_hh, p_hl, 128,
                                          (const __nv_bfloat16*)0, (const __nv_bfloat16*)0, 0,
                                          p_wabh + (size_t)l * 256 * 128, p_wabl + (size_t)l * 256 * 128,
                                          p_bab + l * 256, p_yab,
                                          (__nv_bfloat16*)0, (__nv_bfloat16*)0, NN, 256, 0);
        // message + LN + tanh + aggregate -> agg (split)
        k_msg<<<(NN * 32 + 255) / 256, 256>>>(p_yab, p_M + l * 16 * 128,
                                              msglnw + l * 128, msglnb + l * 128,
                                              raw, p_aggh, p_aggl);
        // update: pre = [agg|h] @ upd_W + upd_b -> fp32 pre
        k_mgemm<<<g128, 256, GEMM_SMEM>>>(p_aggh, p_aggl, 128, p_hh, p_hl, 128,
                                          p_updh + (size_t)l * 128 * 256, p_updl + (size_t)l * 128 * 256,
                                          updb + l * 128, p_pre,
                                          (__nv_bfloat16*)0, (__nv_bfloat16*)0, NN, 128, 0);
        // h = tanh(LN(pre)) (split output)
        k_lntanh<<<(NN * 32 + 255) / 256, 256>>>(p_pre, updlnw + l * 128, updlnb + l * 128,
                                                 p_hh, p_hl);
    }

    // readout: R = relu(h @ fc1 + b1) -> fp32 yab
    k_mgemm<<<g256, 256, GEMM_SMEM>>>(p_hh, p_hl, 128,
                                      (const __nv_bfloat16*)0, (const __nv_bfloat16*)0, 0,
                                      p_fc1h, p_fc1l, fc1b, p_yab,
                                      (__nv_bfloat16*)0, (__nv_bfloat16*)0, NN, 256, 1);
    k_fc2pool<<<(NN * 32 + 255) / 256, 256>>>(p_yab, fc2w, fc2b, batch);
    k_final<<<(NG + 255) / 256, 256>>>(out);
}

// round 6
// speedup vs baseline: 1.3256x; 1.0590x over previous
#include <cuda_runtime.h>
#include <cuda_bf16.h>
#include <math.h>
#include <stdint.h>

#define NN 40000
#define NE 640000
#define NG 1024

// ---------------- scratch (device globals; no allocations allowed) -------------
__device__ float g_yab [NN * 256];
__device__ float g_pre [NN * 128];
__device__ float g_bab [3 * 256];
__device__ float g_M   [3 * 16 * 128];

__device__ __nv_bfloat16 g_xh  [NN * 64],  g_xl  [NN * 64];
__device__ __nv_bfloat16 g_hh  [NN * 128], g_hl  [NN * 128];
__device__ __nv_bfloat16 g_aggh[NN * 128], g_aggl[NN * 128];
__device__ __nv_bfloat16 g_wabt_h[3 * 256 * 128], g_wabt_l[3 * 256 * 128];
__device__ __nv_bfloat16 g_updt_h[3 * 128 * 256], g_updt_l[3 * 128 * 256];
__device__ __nv_bfloat16 g_fc1t_h[256 * 128],     g_fc1t_l[256 * 128];
__device__ __nv_bfloat16 g_atmt_h[128 * 64],      g_atmt_l[128 * 64];

__device__ int   g_deg [NN];
__device__ int   g_row [NN + 1];
__device__ int   g_cur [NN];
__device__ int   g_psrc[NE];
__device__ int   g_peid[NE];
__device__ float g_gsum[NG];
__device__ float g_gcnt[NG];

// ---------------- helpers --------------------------------------------------------
__device__ __forceinline__ void split_bf16(float v, __nv_bfloat16& h, __nv_bfloat16& l) {
    h = __float2bfloat16(v);
    l = __float2bfloat16(v - __bfloat162float(h));
}
__device__ __forceinline__ float tanh_fast(float x) {
    float y;
    asm("tanh.approx.f32 %0, %1;" : "=f"(y) : "f"(x));
    return y;
}

// ---------------- merged elementwise packing kernel ------------------------------
// ranges:
//  [0, 98304)            pack [W1|W2]^T split      -> g_wabt
//  [98304, 104832)       M = bondsW@W3, folded bias-> g_M, g_bab
//  [104832, 113024)      atomsW^T split            -> g_atmt
//  [113024, 211328)      updW^T split              -> g_updt
//  [211328, 244096)      fc1W^T split              -> g_fc1t
//  [244096, 2804096)     x split                   -> g_xh/g_xl
#define PACK_TOTAL 2804096
__global__ void k_pack_all(const float* __restrict__ msgW, const float* __restrict__ bondsW,
                           const float* __restrict__ bondsb, const float* __restrict__ msgb,
                           const float* __restrict__ atomsW, const float* __restrict__ updW,
                           const float* __restrict__ fc1W, const float* __restrict__ x)
{
    int idx = blockIdx.x * blockDim.x + threadIdx.x;
    if (idx < 98304) {
        int l = idx / 32768, r = idx % 32768;
        int n = r / 128, k = r % 128;
        const float* Wl = msgW + (size_t)l * 384 * 128;
        float v = (n < 128) ? Wl[k * 128 + n] : Wl[(128 + k) * 128 + (n - 128)];
        __nv_bfloat16 h, lo; split_bf16(v, h, lo);
        g_wabt_h[idx] = h; g_wabt_l[idx] = lo;
    } else if (idx < 104832) {
        int i2 = idx - 98304;
        if (i2 < 3 * 16 * 128) {
            int l = i2 / 2048, k = (i2 / 128) & 15, d = i2 & 127;
            const float* W3 = msgW + (size_t)l * 384 * 128 + 256 * 128;
            float s = 0.f;
            for (int j = 0; j < 128; j++) s += bondsW[k * 128 + j] * W3[j * 128 + d];
            g_M[i2] = s;
        } else {
            int i3 = i2 - 3 * 16 * 128;
            int l = i3 / 128, d = i3 & 127;
            const float* W3 = msgW + (size_t)l * 384 * 128 + 256 * 128;
            float s = msgb[l * 128 + d];
            for (int j = 0; j < 128; j++) s += bondsb[j] * W3[j * 128 + d];
            g_bab[l * 256 + d] = s;
            g_bab[l * 256 + 128 + d] = 0.f;
        }
    } else if (idx < 113024) {
        int i = idx - 104832;                 // K=64, N=128
        int n = i / 64, k = i % 64;
        __nv_bfloat16 h, l; split_bf16(atomsW[k * 128 + n], h, l);
        g_atmt_h[i] = h; g_atmt_l[i] = l;
    } else if (idx < 211328) {
        int i = idx - 113024;                 // per layer 32768; K=256, N=128
        int l = i / 32768, r = i % 32768;
        int n = r / 256, k = r % 256;
        const float* Wl = updW + (size_t)l * 256 * 128;
        __nv_bfloat16 h, lo; split_bf16(Wl[k * 128 + n], h, lo);
        g_updt_h[i] = h; g_updt_l[i] = lo;
    } else if (idx < 244096) {
        int i = idx - 211328;                 // K=128, N=256
        int n = i / 128, k = i % 128;
        __nv_bfloat16 h, l; split_bf16(fc1W[k * 256 + n], h, l);
        g_fc1t_h[i] = h; g_fc1t_l[i] = l;
    } else if (idx < PACK_TOTAL) {
        int i = idx - 244096;
        __nv_bfloat16 h, l; split_bf16(x[i], h, l);
        g_xh[i] = h; g_xl[i] = l;
    }
}

// ---------------- init: zero deg/gsum, per-graph counts via binary search --------
__global__ void k_init(const int* __restrict__ batch) {
    int i = blockIdx.x * blockDim.x + threadIdx.x;
    if (i < NN) g_deg[i] = 0;
    if (i < NG) {
        g_gsum[i] = 0.f;
        int lo = 0, hi = NN;
        while (lo < hi) { int m = (lo + hi) >> 1; if (batch[m] < i) lo = m + 1; else hi = m; }
        int lo2 = lo, hi2 = NN;
        while (lo2 < hi2) { int m = (lo2 + hi2) >> 1; if (batch[m] < i + 1) lo2 = m + 1; else hi2 = m; }
        g_gcnt[i] = (float)(lo2 - lo);
    }
}

__global__ void k_deg(const int* __restrict__ dst) {
    int e = blockIdx.x * blockDim.x + threadIdx.x;
    if (e < NE) atomicAdd(&g_deg[dst[e]], 1);
}
__global__ void k_scan() {
    __shared__ int ssum[1024];
    const int CH = 40;
    int t = threadIdx.x;
    int base = t * CH;
    int s = 0;
    for (int i = 0; i < CH; i++) { int idx = base + i; if (idx < NN) s += g_deg[idx]; }
    ssum[t] = s;
    __syncthreads();
    for (int off = 1; off < 1024; off <<= 1) {
        int v = 0;
        if (t >= off) v = ssum[t - off];
        __syncthreads();
        ssum[t] += v;
        __syncthreads();
    }
    int run = ssum[t] - s;
    for (int i = 0; i < CH; i++) {
        int idx = base + i;
        if (idx < NN) { g_row[idx] = run; g_cur[idx] = run; run += g_deg[idx]; }
    }
    if (t == 1023) g_row[NN] = ssum[1023];
}
__global__ void k_fill(const int* __restrict__ src, const int* __restrict__ dst) {
    int e = blockIdx.x * blockDim.x + threadIdx.x;
    if (e < NE) {
        int d = dst[e];
        int p = atomicAdd(&g_cur[d], 1);
        g_psrc[p] = src[e];
        g_peid[p] = e;
    }
}

// ================= bf16x3 mma.sync GEMM with ldmatrix + cp.async =================
#define MMA_BF16(d, a, b0, b1) \
    asm volatile("mma.sync.aligned.m16n8k16.row.col.f32.bf16.bf16.f32 " \
        "{%0,%1,%2,%3}, {%4,%5,%6,%7}, {%8,%9}, {%0,%1,%2,%3};" \
        : "+f"(d[0]), "+f"(d[1]), "+f"(d[2]), "+f"(d[3]) \
        : "r"(a[0]), "r"(a[1]), "r"(a[2]), "r"(a[3]), "r"(b0), "r"(b1));

#define LDSM_X4(r, a) \
    asm volatile("ldmatrix.sync.aligned.m8n8.x4.shared.b16 {%0,%1,%2,%3}, [%4];" \
        : "=r"((r)[0]), "=r"((r)[1]), "=r"((r)[2]), "=r"((r)[3]) : "r"(a))

#define CP_ASYNC(sa, ga, sz) \
    asm volatile("cp.async.ca.shared.global [%0], [%1], 16, %2;" :: "r"(sa), "l"(ga), "r"(sz))
#define CP_COMMIT() asm volatile("cp.async.commit_group;" ::: "memory")
#define CP_WAIT(n)  asm volatile("cp.async.wait_group %0;" :: "n"(n) : "memory")

__device__ __forceinline__ uint32_t smem_u32(const void* p) {
    uint32_t a;
    asm("{ .reg .u64 t; cvta.to.shared.u64 t, %1; cvt.u32.u64 %0, t; }" : "=r"(a) : "l"(p));
    return a;
}

#define GEMM_SMEM (2 * 40960)

__global__ void __launch_bounds__(256) k_mgemm(
    const __nv_bfloat16* __restrict__ X1h, const __nv_bfloat16* __restrict__ X1l, int K1,
    const __nv_bfloat16* __restrict__ X2h, const __nv_bfloat16* __restrict__ X2l, int K2,
    const __nv_bfloat16* __restrict__ Wh,  const __nv_bfloat16* __restrict__ Wl,
    const float* __restrict__ bias, float* __restrict__ Y,
    __nv_bfloat16* __restrict__ Yh, __nv_bfloat16* __restrict__ Yl,
    int nrows, int ncols, int act)
{
    extern __shared__ char smem[];
    const uint32_t sb = smem_u32(smem);
    const int tid = threadIdx.x;
    const int wid = tid >> 5, lane = tid & 31;
    const int wm = wid & 1, wn = wid >> 1;
    const int g = lane >> 2, t = lane & 3;
    const int rbase = blockIdx.x * 128, cbase = blockIdx.y * 128;
    const int Ktot = K1 + K2;
    const int nch = Ktot >> 5;

    const int srow = tid >> 1;
    const int sseg = (tid & 1) * 2;

    float acc[4][4][4];
#pragma unroll
    for (int i = 0; i < 4; i++)
#pragma unroll
        for (int j = 0; j < 4; j++)
#pragma unroll
            for (int q = 0; q < 4; q++) acc[i][j][q] = 0.f;

    const int quad = lane >> 3, li = lane & 7;
    const int a_row = (quad & 1) * 8 + li;
    const int a_col = (quad >> 1) * 8;
    const int b_row = (quad >> 1) * 8 + li;
    const int b_col = (quad & 1) * 8;

    auto stage = [&](int ch, int buf) {
        const int kk = ch << 5;
        const uint32_t base = sb + buf * 40960;
        {
            const __nv_bfloat16 *Xh, *Xl; int xs, kx;
            if (kk < K1) { Xh = X1h; Xl = X1l; xs = K1; kx = kk; }
            else         { Xh = X2h; Xl = X2l; xs = K2; kx = kk - K1; }
            int gr = rbase + srow;
            uint32_t sz = (gr < nrows) ? 16u : 0u;
            if (gr >= nrows) gr = nrows - 1;
            const __nv_bfloat16* ph = Xh + (size_t)gr * xs + kx;
            const __nv_bfloat16* pl = Xl + (size_t)gr * xs + kx;
#pragma unroll
            for (int q = 0; q < 2; q++) {
                const int seg = sseg + q;
                const uint32_t so = base + srow * 80 + seg * 16;
                CP_ASYNC(so,         ph + seg * 8, sz);
                CP_ASYNC(so + 10240, pl + seg * 8, sz);
            }
        }
        {
            const int gn = cbase + srow;
            const __nv_bfloat16* ph = Wh + (size_t)gn * Ktot + kk;
            const __nv_bfloat16* pl = Wl + (size_t)gn * Ktot + kk;
#pragma unroll
            for (int q = 0; q < 2; q++) {
                const int seg = sseg + q;
                const uint32_t so = base + 20480 + srow * 80 + seg * 16;
                CP_ASYNC(so,         ph + seg * 8, 16u);
                CP_ASYNC(so + 10240, pl + seg * 8, 16u);
            }
        }
        CP_COMMIT();
    };

    stage(0, 0);
    for (int ch = 0; ch < nch; ch++) {
        const int buf = ch & 1;
        const bool more = (ch + 1 < nch);
        if (more) stage(ch + 1, buf ^ 1);
        if (more) { CP_WAIT(1); } else { CP_WAIT(0); }
        __syncthreads();

        const uint32_t base = sb + buf * 40960;
        const uint32_t aah = base + (wm * 64 + a_row) * 80 + a_col * 2;
        const uint32_t bbh = base + 20480 + (wn * 32 + b_row) * 80 + b_col * 2;
#pragma unroll
        for (int s = 0; s < 2; s++) {
            const uint32_t ks2 = s * 32;
            uint32_t ah[4][4], al[4][4];
#pragma unroll
            for (int mt = 0; mt < 4; mt++) {
                LDSM_X4(ah[mt], aah + mt * 1280 + ks2);
                LDSM_X4(al[mt], aah + 10240 + mt * 1280 + ks2);
            }
            uint32_t bh[4][2], bl[4][2];
#pragma unroll
            for (int pr = 0; pr < 2; pr++) {
                uint32_t tmp[4];
                LDSM_X4(tmp, bbh + pr * 1280 + ks2);
                bh[2 * pr][0] = tmp[0]; bh[2 * pr][1] = tmp[1];
                bh[2 * pr + 1][0] = tmp[2]; bh[2 * pr + 1][1] = tmp[3];
                LDSM_X4(tmp, bbh + 10240 + pr * 1280 + ks2);
                bl[2 * pr][0] = tmp[0]; bl[2 * pr][1] = tmp[1];
                bl[2 * pr + 1][0] = tmp[2]; bl[2 * pr + 1][1] = tmp[3];
            }
#pragma unroll
            for (int nt = 0; nt < 4; nt++)
#pragma unroll
                for (int mt = 0; mt < 4; mt++) {
                    MMA_BF16(acc[mt][nt], ah[mt], bh[nt][0], bh[nt][1]);
                    MMA_BF16(acc[mt][nt], ah[mt], bl[nt][0], bl[nt][1]);
                    MMA_BF16(acc[mt][nt], al[mt], bh[nt][0], bh[nt][1]);
                }
        }
        __syncthreads();
    }

#pragma unroll
    for (int mt = 0; mt < 4; mt++) {
#pragma unroll
        for (int half = 0; half < 2; half++) {
            int row = rbase + wm * 64 + mt * 16 + g + 8 * half;
            if (row >= nrows) continue;
#pragma unroll
            for (int nt = 0; nt < 4; nt++) {
                int col = cbase + wn * 32 + nt * 8 + 2 * t;
                float v0 = acc[mt][nt][2 * half + 0] + bias[col];
                float v1 = acc[mt][nt][2 * half + 1] + bias[col + 1];
                if (act == 1) { v0 = fmaxf(v0, 0.f); v1 = fmaxf(v1, 0.f); }
                if (Y) {
                    float2 v; v.x = v0; v.y = v1;
                    *(float2*)(Y + (size_t)row * ncols + col) = v;
                }
                if (Yh) {
                    __nv_bfloat16 h0, l0, h1, l1;
                    split_bf16(v0, h0, l0);
                    split_bf16(v1, h1, l1);
                    __nv_bfloat162 hp; hp.x = h0; hp.y = h1;
                    __nv_bfloat162 lp; lp.x = l0; lp.y = l1;
                    *(__nv_bfloat162*)(Yh + (size_t)row * ncols + col) = hp;
                    *(__nv_bfloat162*)(Yl + (size_t)row * ncols + col) = lp;
                }
            }
        }
    }
}

// ---------------- fused message + LN + tanh + aggregate (warp per dst node) ----
__global__ void __launch_bounds__(256) k_msg(
    const float* __restrict__ yab, const float* __restrict__ Mw,
    const float* __restrict__ lnw, const float* __restrict__ lnb,
    const float* __restrict__ raw,
    __nv_bfloat16* __restrict__ aggh, __nv_bfloat16* __restrict__ aggl)
{
    int warp = (blockIdx.x * blockDim.x + threadIdx.x) >> 5;
    int lane = threadIdx.x & 31;
    if (warp >= NN) return;

    float Mreg[16][4];
#pragma unroll
    for (int k = 0; k < 16; k++)
#pragma unroll
        for (int j = 0; j < 4; j++) Mreg[k][j] = Mw[k * 128 + lane + 32 * j];

    float bj[4], lw[4], lb[4], accj[4];
#pragma unroll
    for (int j = 0; j < 4; j++) {
        bj[j] = yab[(size_t)warp * 256 + 128 + lane + 32 * j];
        lw[j] = lnw[lane + 32 * j];
        lb[j] = lnb[lane + 32 * j];
        accj[j] = 0.f;
    }

    int p0 = g_row[warp], p1 = g_row[warp + 1];
    for (int p = p0; p < p1; p++) {
        int src = g_psrc[p];
        int eid = g_peid[p];
        const float* ar = yab + (size_t)src * 256;
        const float4* rp = (const float4*)(raw + (size_t)eid * 16);
        float4 r0 = rp[0], r1 = rp[1], r2 = rp[2], r3 = rp[3];
        float rv[16] = {r0.x, r0.y, r0.z, r0.w, r1.x, r1.y, r1.z, r1.w,
                        r2.x, r2.y, r2.z, r2.w, r3.x, r3.y, r3.z, r3.w};
        float pre[4];
#pragma unroll
        for (int j = 0; j < 4; j++) {
            float c = bj[j] + ar[lane + 32 * j];
#pragma unroll
            for (int k = 0; k < 16; k++) c = fmaf(rv[k], Mreg[k][j], c);
            pre[j] = c;
        }
        float s = pre[0] + pre[1] + pre[2] + pre[3];
        float q = pre[0] * pre[0];
        q = fmaf(pre[1], pre[1], q);
        q = fmaf(pre[2], pre[2], q);
        q = fmaf(pre[3], pre[3], q);
#pragma unroll
        for (int off = 16; off > 0; off >>= 1) {
            s += __shfl_xor_sync(0xffffffffu, s, off);
            q += __shfl_xor_sync(0xffffffffu, q, off);
        }
        float mean = s * (1.f / 128.f);
        float var = q * (1.f / 128.f) - mean * mean;
        float rstd = rsqrtf(var + 1e-5f);
#pragma unroll
        for (int j = 0; j < 4; j++) {
            float y = (pre[j] - mean) * rstd * lw[j] + lb[j];
            accj[j] += tanh_fast(y);
        }
    }
#pragma unroll
    for (int j = 0; j < 4; j++) {
        __nv_bfloat16 h, l; split_bf16(accj[j], h, l);
        aggh[(size_t)warp * 128 + lane + 32 * j] = h;
        aggl[(size_t)warp * 128 + lane + 32 * j] = l;
    }
}

// ---------------- per-node LayerNorm + tanh (warp per node), split output -------
__global__ void __launch_bounds__(256) k_lntanh(
    const float* __restrict__ pre, const float* __restrict__ lnw,
    const float* __restrict__ lnb,
    __nv_bfloat16* __restrict__ outh, __nv_bfloat16* __restrict__ outl)
{
    int warp = (blockIdx.x * blockDim.x + threadIdx.x) >> 5;
    int lane = threadIdx.x & 31;
    if (warp >= NN) return;
    float v[4];
#pragma unroll
    for (int j = 0; j < 4; j++) v[j] = pre[(size_t)warp * 128 + lane + 32 * j];
    float s = v[0] + v[1] + v[2] + v[3];
    float q = v[0] * v[0];
    q = fmaf(v[1], v[1], q);
    q = fmaf(v[2], v[2], q);
    q = fmaf(v[3], v[3], q);
#pragma unroll
    for (int off = 16; off > 0; off >>= 1) {
        s += __shfl_xor_sync(0xffffffffu, s, off);
        q += __shfl_xor_sync(0xffffffffu, q, off);
    }
    float mean = s * (1.f / 128.f);
    float var = q * (1.f / 128.f) - mean * mean;
    float rstd = rsqrtf(var + 1e-5f);
#pragma unroll
    for (int j = 0; j < 4; j++) {
        float y = (v[j] - mean) * rstd * lnw[lane + 32 * j] + lnb[lane + 32 * j];
        __nv_bfloat16 h, l; split_bf16(tanh_fast(y), h, l);
        outh[(size_t)warp * 128 + lane + 32 * j] = h;
        outl[(size_t)warp * 128 + lane + 32 * j] = l;
    }
}

// ---------------- fc2 dot + graph pooling ---------------------------------------
__global__ void __launch_bounds__(256) k_fc2pool(
    const float* __restrict__ R, const float* __restrict__ fc2w,
    const float* __restrict__ fc2b, const int* __restrict__ batch)
{
    int warp = (blockIdx.x * blockDim.x + threadIdx.x) >> 5;
    int lane = threadIdx.x & 31;
    if (warp >= NN) return;
    float s = 0.f;
#pragma unroll
    for (int j = 0; j < 8; j++)
        s = fmaf(R[(size_t)warp * 256 + lane + 32 * j], fc2w[lane + 32 * j], s);
#pragma unroll
    for (int off = 16; off > 0; off >>= 1) s += __shfl_xor_sync(0xffffffffu, s, off);
    if (lane == 0) atomicAdd(&g_gsum[batch[warp]], s + fc2b[0]);
}

__global__ void k_final(float* __restrict__ out) {
    int g = blockIdx.x * blockDim.x + threadIdx.x;
    if (g < NG) out[g] = g_gsum[g] / fmaxf(g_gcnt[g], 1.0f);
}

// ---------------- host orchestration --------------------------------------------
extern "C" void kernel_launch(void* const* d_in, const int* in_sizes, int n_in,
                              void* d_out, int out_size)
{
    const float* x      = (const float*)d_in[0];
    const int*   ei     = (const int*)  d_in[1];
    const float* raw    = (const float*)d_in[2];
    const int*   batch  = (const int*)  d_in[3];
    const float* atomsW = (const float*)d_in[4];
    const float* atomsb = (const float*)d_in[5];
    const float* bondsW = (const float*)d_in[6];
    const float* bondsb = (const float*)d_in[7];
    const float* msgW   = (const float*)d_in[8];
    const float* msgb   = (const float*)d_in[9];
    const float* msglnw = (const float*)d_in[10];
    const float* msglnb = (const float*)d_in[11];
    const float* updW   = (const float*)d_in[12];
    const float* updb   = (const float*)d_in[13];
    const float* updlnw = (const float*)d_in[14];
    const float* updlnb = (const float*)d_in[15];
    const float* fc1W   = (const float*)d_in[16];
    const float* fc1b   = (const float*)d_in[17];
    const float* fc2w   = (const float*)d_in[18];
    const float* fc2b   = (const float*)d_in[19];
    float* out = (float*)d_out;

    const int* src = ei;
    const int* dst = ei + NE;

    cudaFuncSetAttribute(k_mgemm, cudaFuncAttributeMaxDynamicSharedMemorySize, GEMM_SMEM);

    float *p_yab, *p_pre, *p_bab, *p_M;
    cudaGetSymbolAddress((void**)&p_yab, g_yab);
    cudaGetSymbolAddress((void**)&p_pre, g_pre);
    cudaGetSymbolAddress((void**)&p_bab, g_bab);
    cudaGetSymbolAddress((void**)&p_M,   g_M);
    __nv_bfloat16 *p_xh, *p_xl, *p_hh, *p_hl, *p_aggh, *p_aggl;
    __nv_bfloat16 *p_wabh, *p_wabl, *p_updh, *p_updl, *p_fc1h, *p_fc1l, *p_atmh, *p_atml;
    cudaGetSymbolAddress((void**)&p_xh,   g_xh);
    cudaGetSymbolAddress((void**)&p_xl,   g_xl);
    cudaGetSymbolAddress((void**)&p_hh,   g_hh);
    cudaGetSymbolAddress((void**)&p_hl,   g_hl);
    cudaGetSymbolAddress((void**)&p_aggh, g_aggh);
    cudaGetSymbolAddress((void**)&p_aggl, g_aggl);
    cudaGetSymbolAddress((void**)&p_wabh, g_wabt_h);
    cudaGetSymbolAddress((void**)&p_wabl, g_wabt_l);
    cudaGetSymbolAddress((void**)&p_updh, g_updt_h);
    cudaGetSymbolAddress((void**)&p_updl, g_updt_l);
    cudaGetSymbolAddress((void**)&p_fc1h, g_fc1t_h);
    cudaGetSymbolAddress((void**)&p_fc1l, g_fc1t_l);
    cudaGetSymbolAddress((void**)&p_atmh, g_atmt_h);
    cudaGetSymbolAddress((void**)&p_atml, g_atmt_l);

    // launches 0-4: packing + CSR build
    k_pack_all<<<(PACK_TOTAL + 255) / 256, 256>>>(msgW, bondsW, bondsb, msgb,
                                                  atomsW, updW, fc1W, x);
    k_init<<<(NN + 255) / 256, 256>>>(batch);
    k_deg<<<(NE + 255) / 256, 256>>>(dst);
    k_scan<<<1, 1024>>>();
    k_fill<<<(NE + 255) / 256, 256>>>(src, dst);

    const int RB = (NN + 127) / 128;
    dim3 g128(RB, 1), g256(RB, 2);

    // launch 5 (ncu profile target): embed GEMM
    k_mgemm<<<g128, 256, GEMM_SMEM>>>(p_xh, p_xl, 64,
                                      (const __nv_bfloat16*)0, (const __nv_bfloat16*)0, 0,
                                      p_atmh, p_atml, atomsb, (float*)0, p_hh, p_hl, NN, 128, 0);

    for (int l = 0; l < 3; l++) {
        k_mgemm<<<g256, 256, GEMM_SMEM>>>(p_hh, p_hl, 128,
                                          (const __nv_bfloat16*)0, (const __nv_bfloat16*)0, 0,
                                          p_wabh + (size_t)l * 256 * 128, p_wabl + (size_t)l * 256 * 128,
                                          p_bab + l * 256, p_yab,
                                          (__nv_bfloat16*)0, (__nv_bfloat16*)0, NN, 256, 0);
        k_msg<<<(NN * 32 + 255) / 256, 256>>>(p_yab, p_M + l * 16 * 128,
                                              msglnw + l * 128, msglnb + l * 128,
                                              raw, p_aggh, p_aggl);
        k_mgemm<<<g128, 256, GEMM_SMEM>>>(p_aggh, p_aggl, 128, p_hh, p_hl, 128,
                                          p_updh + (size_t)l * 128 * 256, p_updl + (size_t)l * 128 * 256,
                                          updb + l * 128, p_pre,
                                          (__nv_bfloat16*)0, (__nv_bfloat16*)0, NN, 128, 0);
        k_lntanh<<<(NN * 32 + 255) / 256, 256>>>(p_pre, updlnw + l * 128, updlnb + l * 128,
                                                 p_hh, p_hl);
    }

    k_mgemm<<<g256, 256, GEMM_SMEM>>>(p_hh, p_hl, 128,
                                      (const __nv_bfloat16*)0, (const __nv_bfloat16*)0, 0,
                                      p_fc1h, p_fc1l, fc1b, p_yab,
                                      (__nv_bfloat16*)0, (__nv_bfloat16*)0, NN, 256, 1);
    k_fc2pool<<<(NN * 32 + 255) / 256, 256>>>(p_yab, fc2w, fc2b, batch);
    k_final<<<(NG + 255) / 256, 256>>>(out);
}

// round 7
// speedup vs baseline: 1.4109x; 1.0643x over previous
#include <cuda_runtime.h>
#include <cuda_bf16.h>
#include <math.h>
#include <stdint.h>

#define NN 40000
#define NE 640000
#define NG 1024

// ---------------- scratch (device globals; no allocations allowed) -------------
__device__ float g_yab [NN * 256];
__device__ float g_bab [3 * 256];
__device__ float g_M   [3 * 16 * 128];

__device__ __nv_bfloat16 g_xh  [NN * 64],  g_xl  [NN * 64];
__device__ __nv_bfloat16 g_hh  [NN * 128], g_hl  [NN * 128];
__device__ __nv_bfloat16 g_aggh[NN * 128], g_aggl[NN * 128];
__device__ __nv_bfloat16 g_wabt_h[3 * 256 * 128], g_wabt_l[3 * 256 * 128];
__device__ __nv_bfloat16 g_updt_h[3 * 128 * 256], g_updt_l[3 * 128 * 256];
__device__ __nv_bfloat16 g_fc1t_h[256 * 128],     g_fc1t_l[256 * 128];
__device__ __nv_bfloat16 g_atmt_h[128 * 64],      g_atmt_l[128 * 64];

__device__ int   g_deg [NN];
__device__ int   g_row [NN + 1];
__device__ int   g_cur [NN];
__device__ int   g_bsum[160];
__device__ int   g_boff[160];
__device__ int   g_psrc[NE];
__device__ int   g_peid[NE];
__device__ float g_gsum[NG];
__device__ float g_gcnt[NG];

// ---------------- helpers --------------------------------------------------------
__device__ __forceinline__ void split_bf16(float v, __nv_bfloat16& h, __nv_bfloat16& l) {
    h = __float2bfloat16(v);
    l = __float2bfloat16(v - __bfloat162float(h));
}
__device__ __forceinline__ float tanh_fast(float x) {
    float y;
    asm("tanh.approx.f32 %0, %1;" : "=f"(y) : "f"(x));
    return y;
}

// ---------------- merged elementwise packing kernel ------------------------------
#define PACK_TOTAL 2804096
__global__ void k_pack_all(const float* __restrict__ msgW, const float* __restrict__ bondsW,
                           const float* __restrict__ bondsb, const float* __restrict__ msgb,
                           const float* __restrict__ atomsW, const float* __restrict__ updW,
                           const float* __restrict__ fc1W, const float* __restrict__ x)
{
    int idx = blockIdx.x * blockDim.x + threadIdx.x;
    if (idx < 98304) {
        int l = idx / 32768, r = idx % 32768;
        int n = r / 128, k = r % 128;
        const float* Wl = msgW + (size_t)l * 384 * 128;
        float v = (n < 128) ? Wl[k * 128 + n] : Wl[(128 + k) * 128 + (n - 128)];
        __nv_bfloat16 h, lo; split_bf16(v, h, lo);
        g_wabt_h[idx] = h; g_wabt_l[idx] = lo;
    } else if (idx < 104832) {
        int i2 = idx - 98304;
        if (i2 < 3 * 16 * 128) {
            int l = i2 / 2048, k = (i2 / 128) & 15, d = i2 & 127;
            const float* W3 = msgW + (size_t)l * 384 * 128 + 256 * 128;
            float s = 0.f;
            for (int j = 0; j < 128; j++) s += bondsW[k * 128 + j] * W3[j * 128 + d];
            g_M[i2] = s;
        } else {
            int i3 = i2 - 3 * 16 * 128;
            int l = i3 / 128, d = i3 & 127;
            const float* W3 = msgW + (size_t)l * 384 * 128 + 256 * 128;
            float s = msgb[l * 128 + d];
            for (int j = 0; j < 128; j++) s += bondsb[j] * W3[j * 128 + d];
            g_bab[l * 256 + d] = s;
            g_bab[l * 256 + 128 + d] = 0.f;
        }
    } else if (idx < 113024) {
        int i = idx - 104832;
        int n = i / 64, k = i % 64;
        __nv_bfloat16 h, l; split_bf16(atomsW[k * 128 + n], h, l);
        g_atmt_h[i] = h; g_atmt_l[i] = l;
    } else if (idx < 211328) {
        int i = idx - 113024;
        int l = i / 32768, r = i % 32768;
        int n = r / 256, k = r % 256;
        const float* Wl = updW + (size_t)l * 256 * 128;
        __nv_bfloat16 h, lo; split_bf16(Wl[k * 128 + n], h, lo);
        g_updt_h[i] = h; g_updt_l[i] = lo;
    } else if (idx < 244096) {
        int i = idx - 211328;
        int n = i / 128, k = i % 128;
        __nv_bfloat16 h, l; split_bf16(fc1W[k * 256 + n], h, l);
        g_fc1t_h[i] = h; g_fc1t_l[i] = l;
    } else if (idx < PACK_TOTAL) {
        int i = idx - 244096;
        __nv_bfloat16 h, l; split_bf16(x[i], h, l);
        g_xh[i] = h; g_xl[i] = l;
    }
}

// ---------------- init: zero deg/gsum, per-graph counts via binary search --------
__global__ void k_init(const int* __restrict__ batch) {
    int i = blockIdx.x * blockDim.x + threadIdx.x;
    if (i < NN) g_deg[i] = 0;
    if (i < NG) {
        g_gsum[i] = 0.f;
        int lo = 0, hi = NN;
        while (lo < hi) { int m = (lo + hi) >> 1; if (batch[m] < i) lo = m + 1; else hi = m; }
        int lo2 = lo, hi2 = NN;
        while (lo2 < hi2) { int m = (lo2 + hi2) >> 1; if (batch[m] < i + 1) lo2 = m + 1; else hi2 = m; }
        g_gcnt[i] = (float)(lo2 - lo);
    }
}

__global__ void k_deg(const int* __restrict__ dst) {
    int e = blockIdx.x * blockDim.x + threadIdx.x;
    if (e < NE) atomicAdd(&g_deg[dst[e]], 1);
}

// ---------------- parallel 3-phase exclusive scan of degrees ---------------------
__global__ void k_scan1() {                       // grid 157, block 256: block sums
    __shared__ int ws[8];
    int t = threadIdx.x, lane = t & 31, w = t >> 5;
    int i = blockIdx.x * 256 + t;
    int d = (i < NN) ? g_deg[i] : 0;
    int s = __reduce_add_sync(0xffffffffu, d);
    if (lane == 0) ws[w] = s;
    __syncthreads();
    if (t == 0) {
        int tot = 0;
        for (int j = 0; j < 8; j++) tot += ws[j];
        g_bsum[blockIdx.x] = tot;
    }
}
__global__ void k_scan2(int nblk) {               // 1 block 256: scan block sums
    __shared__ int wsum[8];
    int t = threadIdx.x, lane = t & 31, w = t >> 5;
    int v = (t < nblk) ? g_bsum[t] : 0;
    int x = v;
#pragma unroll
    for (int off = 1; off < 32; off <<= 1) {
        int y = __shfl_up_sync(0xffffffffu, x, off);
        if (lane >= off) x += y;
    }
    if (lane == 31) wsum[w] = x;
    __syncthreads();
    if (t == 0) {
        int r = 0;
        for (int j = 0; j < 8; j++) { int tmp = wsum[j]; wsum[j] = r; r += tmp; }
        g_row[NN] = NE;
    }
    __syncthreads();
    if (t < nblk) g_boff[t] = x - v + wsum[w];
}
__global__ void k_scan3() {                       // grid 157: final exclusive offsets
    __shared__ int wsum[8];
    int t = threadIdx.x, lane = t & 31, w = t >> 5;
    int i = blockIdx.x * 256 + t;
    int d = (i < NN) ? g_deg[i] : 0;
    int x = d;
#pragma unroll
    for (int off = 1; off < 32; off <<= 1) {
        int y = __shfl_up_sync(0xffffffffu, x, off);
        if (lane >= off) x += y;
    }
    if (lane == 31) wsum[w] = x;
    __syncthreads();
    if (t == 0) {
        int r = 0;
        for (int j = 0; j < 8; j++) { int tmp = wsum[j]; wsum[j] = r; r += tmp; }
    }
    __syncthreads();
    int excl = x - d + wsum[w] + g_boff[blockIdx.x];
    if (i < NN) { g_row[i] = excl; g_cur[i] = excl; }
}

__global__ void k_fill(const int* __restrict__ src, const int* __restrict__ dst) {
    int e = blockIdx.x * blockDim.x + threadIdx.x;
    if (e < NE) {
        int d = dst[e];
        int p = atomicAdd(&g_cur[d], 1);
        g_psrc[p] = src[e];
        g_peid[p] = e;
    }
}

// ================= bf16x3 mma.sync GEMM with ldmatrix + cp.async =================
// act: 0 = none, 1 = relu, 2 = fused LayerNorm+tanh (requires ncols==128, grid.y==1)
#define MMA_BF16(d, a, b0, b1) \
    asm volatile("mma.sync.aligned.m16n8k16.row.col.f32.bf16.bf16.f32 " \
        "{%0,%1,%2,%3}, {%4,%5,%6,%7}, {%8,%9}, {%0,%1,%2,%3};" \
        : "+f"(d[0]), "+f"(d[1]), "+f"(d[2]), "+f"(d[3]) \
        : "r"(a[0]), "r"(a[1]), "r"(a[2]), "r"(a[3]), "r"(b0), "r"(b1));

#define LDSM_X4(r, a) \
    asm volatile("ldmatrix.sync.aligned.m8n8.x4.shared.b16 {%0,%1,%2,%3}, [%4];" \
        : "=r"((r)[0]), "=r"((r)[1]), "=r"((r)[2]), "=r"((r)[3]) : "r"(a))

#define CP_ASYNC(sa, ga, sz) \
    asm volatile("cp.async.ca.shared.global [%0], [%1], 16, %2;" :: "r"(sa), "l"(ga), "r"(sz))
#define CP_COMMIT() asm volatile("cp.async.commit_group;" ::: "memory")
#define CP_WAIT(n)  asm volatile("cp.async.wait_group %0;" :: "n"(n) : "memory")

__device__ __forceinline__ uint32_t smem_u32(const void* p) {
    uint32_t a;
    asm("{ .reg .u64 t; cvta.to.shared.u64 t, %1; cvt.u32.u64 %0, t; }" : "=r"(a) : "l"(p));
    return a;
}

#define GEMM_SMEM (2 * 40960)

__global__ void __launch_bounds__(256) k_mgemm(
    const __nv_bfloat16* __restrict__ X1h, const __nv_bfloat16* __restrict__ X1l, int K1,
    const __nv_bfloat16* __restrict__ X2h, const __nv_bfloat16* __restrict__ X2l, int K2,
    const __nv_bfloat16* __restrict__ Wh,  const __nv_bfloat16* __restrict__ Wl,
    const float* __restrict__ bias, float* __restrict__ Y,
    __nv_bfloat16* __restrict__ Yh, __nv_bfloat16* __restrict__ Yl,
    const float* __restrict__ lnw, const float* __restrict__ lnb,
    int nrows, int ncols, int act)
{
    extern __shared__ char smem[];
    const uint32_t sb = smem_u32(smem);
    const int tid = threadIdx.x;
    const int wid = tid >> 5, lane = tid & 31;
    const int wm = wid & 1, wn = wid >> 1;
    const int g = lane >> 2, t = lane & 3;
    const int rbase = blockIdx.x * 128, cbase = blockIdx.y * 128;
    const int Ktot = K1 + K2;
    const int nch = Ktot >> 5;

    const int srow = tid >> 1;
    const int sseg = (tid & 1) * 2;

    float acc[4][4][4];
#pragma unroll
    for (int i = 0; i < 4; i++)
#pragma unroll
        for (int j = 0; j < 4; j++)
#pragma unroll
            for (int q = 0; q < 4; q++) acc[i][j][q] = 0.f;

    const int quad = lane >> 3, li = lane & 7;
    const int a_row = (quad & 1) * 8 + li;
    const int a_col = (quad >> 1) * 8;
    const int b_row = (quad >> 1) * 8 + li;
    const int b_col = (quad & 1) * 8;

    auto stage = [&](int ch, int buf) {
        const int kk = ch << 5;
        const uint32_t base = sb + buf * 40960;
        {
            const __nv_bfloat16 *Xh, *Xl; int xs, kx;
            if (kk < K1) { Xh = X1h; Xl = X1l; xs = K1; kx = kk; }
            else         { Xh = X2h; Xl = X2l; xs = K2; kx = kk - K1; }
            int gr = rbase + srow;
            uint32_t sz = (gr < nrows) ? 16u : 0u;
            if (gr >= nrows) gr = nrows - 1;
            const __nv_bfloat16* ph = Xh + (size_t)gr * xs + kx;
            const __nv_bfloat16* pl = Xl + (size_t)gr * xs + kx;
#pragma unroll
            for (int q = 0; q < 2; q++) {
                const int seg = sseg + q;
                const uint32_t so = base + srow * 80 + seg * 16;
                CP_ASYNC(so,         ph + seg * 8, sz);
                CP_ASYNC(so + 10240, pl + seg * 8, sz);
            }
        }
        {
            const int gn = cbase + srow;
            const __nv_bfloat16* ph = Wh + (size_t)gn * Ktot + kk;
            const __nv_bfloat16* pl = Wl + (size_t)gn * Ktot + kk;
#pragma unroll
            for (int q = 0; q < 2; q++) {
                const int seg = sseg + q;
                const uint32_t so = base + 20480 + srow * 80 + seg * 16;
                CP_ASYNC(so,         ph + seg * 8, 16u);
                CP_ASYNC(so + 10240, pl + seg * 8, 16u);
            }
        }
        CP_COMMIT();
    };

    stage(0, 0);
    for (int ch = 0; ch < nch; ch++) {
        const int buf = ch & 1;
        const bool more = (ch + 1 < nch);
        if (more) stage(ch + 1, buf ^ 1);
        if (more) { CP_WAIT(1); } else { CP_WAIT(0); }
        __syncthreads();

        const uint32_t base = sb + buf * 40960;
        const uint32_t aah = base + (wm * 64 + a_row) * 80 + a_col * 2;
        const uint32_t bbh = base + 20480 + (wn * 32 + b_row) * 80 + b_col * 2;
#pragma unroll
        for (int s = 0; s < 2; s++) {
            const uint32_t ks2 = s * 32;
            uint32_t ah[4][4], al[4][4];
#pragma unroll
            for (int mt = 0; mt < 4; mt++) {
                LDSM_X4(ah[mt], aah + mt * 1280 + ks2);
                LDSM_X4(al[mt], aah + 10240 + mt * 1280 + ks2);
            }
            uint32_t bh[4][2], bl[4][2];
#pragma unroll
            for (int pr = 0; pr < 2; pr++) {
                uint32_t tmp[4];
                LDSM_X4(tmp, bbh + pr * 1280 + ks2);
                bh[2 * pr][0] = tmp[0]; bh[2 * pr][1] = tmp[1];
                bh[2 * pr + 1][0] = tmp[2]; bh[2 * pr + 1][1] = tmp[3];
                LDSM_X4(tmp, bbh + 10240 + pr * 1280 + ks2);
                bl[2 * pr][0] = tmp[0]; bl[2 * pr][1] = tmp[1];
                bl[2 * pr + 1][0] = tmp[2]; bl[2 * pr + 1][1] = tmp[3];
            }
#pragma unroll
            for (int nt = 0; nt < 4; nt++)
#pragma unroll
                for (int mt = 0; mt < 4; mt++) {
                    MMA_BF16(acc[mt][nt], ah[mt], bh[nt][0], bh[nt][1]);
                    MMA_BF16(acc[mt][nt], ah[mt], bl[nt][0], bl[nt][1]);
                    MMA_BF16(acc[mt][nt], al[mt], bh[nt][0], bh[nt][1]);
                }
        }
        __syncthreads();
    }

    if (act == 2) {
        // ---- fused LayerNorm + tanh + bf16-split epilogue (full 128-wide rows) ----
        float* tb = (float*)smem;                 // 128 x 132 fp32
#pragma unroll
        for (int mt = 0; mt < 4; mt++)
#pragma unroll
            for (int half = 0; half < 2; half++) {
                int row = wm * 64 + mt * 16 + g + 8 * half;
#pragma unroll
                for (int nt = 0; nt < 4; nt++) {
                    int col = wn * 32 + nt * 8 + 2 * t;
                    tb[row * 132 + col]     = acc[mt][nt][2 * half + 0] + bias[col];
                    tb[row * 132 + col + 1] = acc[mt][nt][2 * half + 1] + bias[col + 1];
                }
            }
        __syncthreads();
        float lw[4], lb[4];
#pragma unroll
        for (int j = 0; j < 4; j++) { lw[j] = lnw[lane + 32 * j]; lb[j] = lnb[lane + 32 * j]; }
#pragma unroll 1
        for (int it = 0; it < 16; it++) {
            int row = wid * 16 + it;
            int grow = rbase + row;
            float v[4];
#pragma unroll
            for (int j = 0; j < 4; j++) v[j] = tb[row * 132 + lane + 32 * j];
            float s = v[0] + v[1] + v[2] + v[3];
            float q = v[0] * v[0];
            q = fmaf(v[1], v[1], q);
            q = fmaf(v[2], v[2], q);
            q = fmaf(v[3], v[3], q);
#pragma unroll
            for (int off = 16; off > 0; off >>= 1) {
                s += __shfl_xor_sync(0xffffffffu, s, off);
                q += __shfl_xor_sync(0xffffffffu, q, off);
            }
            float mean = s * (1.f / 128.f);
            float var = q * (1.f / 128.f) - mean * mean;
            float rstd = rsqrtf(var + 1e-5f);
            if (grow < nrows) {
#pragma unroll
                for (int j = 0; j < 4; j++) {
                    float y = (v[j] - mean) * rstd * lw[j] + lb[j];
                    __nv_bfloat16 h, l; split_bf16(tanh_fast(y), h, l);
                    Yh[(size_t)grow * 128 + lane + 32 * j] = h;
                    Yl[(size_t)grow * 128 + lane + 32 * j] = l;
                }
            }
        }
        return;
    }

#pragma unroll
    for (int mt = 0; mt < 4; mt++) {
#pragma unroll
        for (int half = 0; half < 2; half++) {
            int row = rbase + wm * 64 + mt * 16 + g + 8 * half;
            if (row >= nrows) continue;
#pragma unroll
            for (int nt = 0; nt < 4; nt++) {
                int col = cbase + wn * 32 + nt * 8 + 2 * t;
                float v0 = acc[mt][nt][2 * half + 0] + bias[col];
                float v1 = acc[mt][nt][2 * half + 1] + bias[col + 1];
                if (act == 1) { v0 = fmaxf(v0, 0.f); v1 = fmaxf(v1, 0.f); }
                if (Y) {
                    float2 v; v.x = v0; v.y = v1;
                    *(float2*)(Y + (size_t)row * ncols + col) = v;
                }
                if (Yh) {
                    __nv_bfloat16 h0, l0, h1, l1;
                    split_bf16(v0, h0, l0);
                    split_bf16(v1, h1, l1);
                    __nv_bfloat162 hp; hp.x = h0; hp.y = h1;
                    __nv_bfloat162 lp; lp.x = l0; lp.y = l1;
                    *(__nv_bfloat162*)(Yh + (size_t)row * ncols + col) = hp;
                    *(__nv_bfloat162*)(Yl + (size_t)row * ncols + col) = lp;
                }
            }
        }
    }
}

// ---------------- fused message + LN + tanh + aggregate (warp per dst node) ----
__global__ void __launch_bounds__(256) k_msg(
    const float* __restrict__ yab, const float* __restrict__ Mw,
    const float* __restrict__ lnw, const float* __restrict__ lnb,
    const float* __restrict__ raw,
    __nv_bfloat16* __restrict__ aggh, __nv_bfloat16* __restrict__ aggl)
{
    int warp = (blockIdx.x * blockDim.x + threadIdx.x) >> 5;
    int lane = threadIdx.x & 31;
    if (warp >= NN) return;

    float Mreg[16][4];
#pragma unroll
    for (int k = 0; k < 16; k++)
#pragma unroll
        for (int j = 0; j < 4; j++) Mreg[k][j] = Mw[k * 128 + lane + 32 * j];

    float bj[4], lw[4], lb[4], accj[4];
#pragma unroll
    for (int j = 0; j < 4; j++) {
        bj[j] = yab[(size_t)warp * 256 + 128 + lane + 32 * j];
        lw[j] = lnw[lane + 32 * j];
        lb[j] = lnb[lane + 32 * j];
        accj[j] = 0.f;
    }

    int p0 = g_row[warp], p1 = g_row[warp + 1];
    for (int p = p0; p < p1; p++) {
        int src = g_psrc[p];
        int eid = g_peid[p];
        const float* ar = yab + (size_t)src * 256;
        const float4* rp = (const float4*)(raw + (size_t)eid * 16);
        float4 r0 = rp[0], r1 = rp[1], r2 = rp[2], r3 = rp[3];
        float rv[16] = {r0.x, r0.y, r0.z, r0.w, r1.x, r1.y, r1.z, r1.w,
                        r2.x, r2.y, r2.z, r2.w, r3.x, r3.y, r3.z, r3.w};
        float pre[4];
#pragma unroll
        for (int j = 0; j < 4; j++) {
            float c = bj[j] + ar[lane + 32 * j];
#pragma unroll
            for (int k = 0; k < 16; k++) c = fmaf(rv[k], Mreg[k][j], c);
            pre[j] = c;
        }
        float s = pre[0] + pre[1] + pre[2] + pre[3];
        float q = pre[0] * pre[0];
        q = fmaf(pre[1], pre[1], q);
        q = fmaf(pre[2], pre[2], q);
        q = fmaf(pre[3], pre[3], q);
#pragma unroll
        for (int off = 16; off > 0; off >>= 1) {
            s += __shfl_xor_sync(0xffffffffu, s, off);
            q += __shfl_xor_sync(0xffffffffu, q, off);
        }
        float mean = s * (1.f / 128.f);
        float var = q * (1.f / 128.f) - mean * mean;
        float rstd = rsqrtf(var + 1e-5f);
#pragma unroll
        for (int j = 0; j < 4; j++) {
            float y = (pre[j] - mean) * rstd * lw[j] + lb[j];
            accj[j] += tanh_fast(y);
        }
    }
#pragma unroll
    for (int j = 0; j < 4; j++) {
        __nv_bfloat16 h, l; split_bf16(accj[j], h, l);
        aggh[(size_t)warp * 128 + lane + 32 * j] = h;
        aggl[(size_t)warp * 128 + lane + 32 * j] = l;
    }
}

// ---------------- fc2 dot + graph pooling ---------------------------------------
__global__ void __launch_bounds__(256) k_fc2pool(
    const float* __restrict__ R, const float* __restrict__ fc2w,
    const float* __restrict__ fc2b, const int* __restrict__ batch)
{
    int warp = (blockIdx.x * blockDim.x + threadIdx.x) >> 5;
    int lane = threadIdx.x & 31;
    if (warp >= NN) return;
    float s = 0.f;
#pragma unroll
    for (int j = 0; j < 8; j++)
        s = fmaf(R[(size_t)warp * 256 + lane + 32 * j], fc2w[lane + 32 * j], s);
#pragma unroll
    for (int off = 16; off > 0; off >>= 1) s += __shfl_xor_sync(0xffffffffu, s, off);
    if (lane == 0) atomicAdd(&g_gsum[batch[warp]], s + fc2b[0]);
}

__global__ void k_final(float* __restrict__ out) {
    int g = blockIdx.x * blockDim.x + threadIdx.x;
    if (g < NG) out[g] = g_gsum[g] / fmaxf(g_gcnt[g], 1.0f);
}

// ---------------- host orchestration --------------------------------------------
extern "C" void kernel_launch(void* const* d_in, const int* in_sizes, int n_in,
                              void* d_out, int out_size)
{
    const float* x      = (const float*)d_in[0];
    const int*   ei     = (const int*)  d_in[1];
    const float* raw    = (const float*)d_in[2];
    const int*   batch  = (const int*)  d_in[3];
    const float* atomsW = (const float*)d_in[4];
    const float* atomsb = (const float*)d_in[5];
    const float* bondsW = (const float*)d_in[6];
    const float* bondsb = (const float*)d_in[7];
    const float* msgW   = (const float*)d_in[8];
    const float* msgb   = (const float*)d_in[9];
    const float* msglnw = (const float*)d_in[10];
    const float* msglnb = (const float*)d_in[11];
    const float* updW   = (const float*)d_in[12];
    const float* updb   = (const float*)d_in[13];
    const float* updlnw = (const float*)d_in[14];
    const float* updlnb = (const float*)d_in[15];
    const float* fc1W   = (const float*)d_in[16];
    const float* fc1b   = (const float*)d_in[17];
    const float* fc2w   = (const float*)d_in[18];
    const float* fc2b   = (const float*)d_in[19];
    float* out = (float*)d_out;

    const int* src = ei;
    const int* dst = ei + NE;

    cudaFuncSetAttribute(k_mgemm, cudaFuncAttributeMaxDynamicSharedMemorySize, GEMM_SMEM);

    float *p_yab, *p_bab, *p_M;
    cudaGetSymbolAddress((void**)&p_yab, g_yab);
    cudaGetSymbolAddress((void**)&p_bab, g_bab);
    cudaGetSymbolAddress((void**)&p_M,   g_M);
    __nv_bfloat16 *p_xh, *p_xl, *p_hh, *p_hl, *p_aggh, *p_aggl;
    __nv_bfloat16 *p_wabh, *p_wabl, *p_updh, *p_updl, *p_fc1h, *p_fc1l, *p_atmh, *p_atml;
    cudaGetSymbolAddress((void**)&p_xh,   g_xh);
    cudaGetSymbolAddress((void**)&p_xl,   g_xl);
    cudaGetSymbolAddress((void**)&p_hh,   g_hh);
    cudaGetSymbolAddress((void**)&p_hl,   g_hl);
    cudaGetSymbolAddress((void**)&p_aggh, g_aggh);
    cudaGetSymbolAddress((void**)&p_aggl, g_aggl);
    cudaGetSymbolAddress((void**)&p_wabh, g_wabt_h);
    cudaGetSymbolAddress((void**)&p_wabl, g_wabt_l);
    cudaGetSymbolAddress((void**)&p_updh, g_updt_h);
    cudaGetSymbolAddress((void**)&p_updl, g_updt_l);
    cudaGetSymbolAddress((void**)&p_fc1h, g_fc1t_h);
    cudaGetSymbolAddress((void**)&p_fc1l, g_fc1t_l);
    cudaGetSymbolAddress((void**)&p_atmh, g_atmt_h);
    cudaGetSymbolAddress((void**)&p_atml, g_atmt_l);

    const int SCAN_BLK = (NN + 255) / 256;   // 157

    k_pack_all<<<(PACK_TOTAL + 255) / 256, 256>>>(msgW, bondsW, bondsb, msgb,
                                                  atomsW, updW, fc1W, x);
    k_init<<<(NN + 255) / 256, 256>>>(batch);
    k_deg<<<(NE + 255) / 256, 256>>>(dst);
    k_scan1<<<SCAN_BLK, 256>>>();
    k_scan2<<<1, 256>>>(SCAN_BLK);
    k_scan3<<<SCAN_BLK, 256>>>();
    k_fill<<<(NE + 255) / 256, 256>>>(src, dst);

    const int RB = (NN + 127) / 128;
    dim3 g128(RB, 1), g256(RB, 2);

    // embed: h = x @ atoms_W + atoms_b  (split output)
    k_mgemm<<<g128, 256, GEMM_SMEM>>>(p_xh, p_xl, 64,
                                      (const __nv_bfloat16*)0, (const __nv_bfloat16*)0, 0,
                                      p_atmh, p_atml, atomsb, (float*)0, p_hh, p_hl,
                                      (const float*)0, (const float*)0, NN, 128, 0);

    for (int l = 0; l < 3; l++) {
        // A|B = h @ [W1|W2] (+folded bias in A half) -> fp32 yab
        k_mgemm<<<g256, 256, GEMM_SMEM>>>(p_hh, p_hl, 128,
                                          (const __nv_bfloat16*)0, (const __nv_bfloat16*)0, 0,
                                          p_wabh + (size_t)l * 256 * 128, p_wabl + (size_t)l * 256 * 128,
                                          p_bab + l * 256, p_yab,
                                          (__nv_bfloat16*)0, (__nv_bfloat16*)0,
                                          (const float*)0, (const float*)0, NN, 256, 0);
        // message + LN + tanh + aggregate -> agg (split)
        k_msg<<<(NN * 32 + 255) / 256, 256>>>(p_yab, p_M + l * 16 * 128,
                                              msglnw + l * 128, msglnb + l * 128,
                                              raw, p_aggh, p_aggl);
        // update + fused LN + tanh -> h (split)
        k_mgemm<<<g128, 256, GEMM_SMEM>>>(p_aggh, p_aggl, 128, p_hh, p_hl, 128,
                                          p_updh + (size_t)l * 128 * 256, p_updl + (size_t)l * 128 * 256,
                                          updb + l * 128, (float*)0, p_hh, p_hl,
                                          updlnw + l * 128, updlnb + l * 128, NN, 128, 2);
    }

    // readout: R = relu(h @ fc1 + b1) -> fp32 yab
    k_mgemm<<<g256, 256, GEMM_SMEM>>>(p_hh, p_hl, 128,
                                      (const __nv_bfloat16*)0, (const __nv_bfloat16*)0, 0,
                                      p_fc1h, p_fc1l, fc1b, p_yab,
                                      (__nv_bfloat16*)0, (__nv_bfloat16*)0,
                                      (const float*)0, (const float*)0, NN, 256, 1);
    k_fc2pool<<<(NN * 32 + 255) / 256, 256>>>(p_yab, fc2w, fc2b, batch);
    k_final<<<(NG + 255) / 256, 256>>>(out);
}

// round 8
// speedup vs baseline: 1.4199x; 1.0064x over previous
#include <cuda_runtime.h>
#include <cuda_bf16.h>
#include <math.h>
#include <stdint.h>

#define NN 40000
#define NE 640000
#define NG 1024

// ---------------- scratch (device globals; no allocations allowed) -------------
__device__ float g_yab [NN * 256];
__device__ float g_bab [3 * 256];
__device__ float g_M   [3 * 16 * 128];

__device__ __nv_bfloat16 g_xh  [NN * 64],  g_xl  [NN * 64];
__device__ __nv_bfloat16 g_hh  [NN * 128], g_hl  [NN * 128];
__device__ __nv_bfloat16 g_aggh[NN * 128], g_aggl[NN * 128];
__device__ __nv_bfloat16 g_wabt_h[3 * 256 * 128], g_wabt_l[3 * 256 * 128];
__device__ __nv_bfloat16 g_updt_h[3 * 128 * 256], g_updt_l[3 * 128 * 256];
__device__ __nv_bfloat16 g_fc1t_h[256 * 128],     g_fc1t_l[256 * 128];
__device__ __nv_bfloat16 g_atmt_h[128 * 64],      g_atmt_l[128 * 64];

__device__ int   g_deg [NN];
__device__ int   g_row [NN + 1];
__device__ int   g_cur [NN];
__device__ int   g_bsum[160];
__device__ int   g_boff[160];
__device__ int   g_psrc[NE];
__device__ int   g_peid[NE];
__device__ float g_gsum[NG];
__device__ float g_gcnt[NG];

// ---------------- helpers --------------------------------------------------------
__device__ __forceinline__ void split_bf16(float v, __nv_bfloat16& h, __nv_bfloat16& l) {
    h = __float2bfloat16(v);
    l = __float2bfloat16(v - __bfloat162float(h));
}
__device__ __forceinline__ float tanh_fast(float x) {
    float y;
    asm("tanh.approx.f32 %0, %1;" : "=f"(y) : "f"(x));
    return y;
}

// ---------------- merged elementwise packing kernel ------------------------------
#define PACK_TOTAL 2804096
__global__ void k_pack_all(const float* __restrict__ msgW, const float* __restrict__ bondsW,
                           const float* __restrict__ bondsb, const float* __restrict__ msgb,
                           const float* __restrict__ atomsW, const float* __restrict__ updW,
                           const float* __restrict__ fc1W, const float* __restrict__ x)
{
    int idx = blockIdx.x * blockDim.x + threadIdx.x;
    if (idx < 98304) {
        int l = idx / 32768, r = idx % 32768;
        int n = r / 128, k = r % 128;
        const float* Wl = msgW + (size_t)l * 384 * 128;
        float v = (n < 128) ? Wl[k * 128 + n] : Wl[(128 + k) * 128 + (n - 128)];
        __nv_bfloat16 h, lo; split_bf16(v, h, lo);
        g_wabt_h[idx] = h; g_wabt_l[idx] = lo;
    } else if (idx < 104832) {
        int i2 = idx - 98304;
        if (i2 < 3 * 16 * 128) {
            int l = i2 / 2048, k = (i2 / 128) & 15, d = i2 & 127;
            const float* W3 = msgW + (size_t)l * 384 * 128 + 256 * 128;
            float s = 0.f;
            for (int j = 0; j < 128; j++) s += bondsW[k * 128 + j] * W3[j * 128 + d];
            g_M[i2] = s;
        } else {
            int i3 = i2 - 3 * 16 * 128;
            int l = i3 / 128, d = i3 & 127;
            const float* W3 = msgW + (size_t)l * 384 * 128 + 256 * 128;
            float s = msgb[l * 128 + d];
            for (int j = 0; j < 128; j++) s += bondsb[j] * W3[j * 128 + d];
            g_bab[l * 256 + d] = s;
            g_bab[l * 256 + 128 + d] = 0.f;
        }
    } else if (idx < 113024) {
        int i = idx - 104832;
        int n = i / 64, k = i % 64;
        __nv_bfloat16 h, l; split_bf16(atomsW[k * 128 + n], h, l);
        g_atmt_h[i] = h; g_atmt_l[i] = l;
    } else if (idx < 211328) {
        int i = idx - 113024;
        int l = i / 32768, r = i % 32768;
        int n = r / 256, k = r % 256;
        const float* Wl = updW + (size_t)l * 256 * 128;
        __nv_bfloat16 h, lo; split_bf16(Wl[k * 128 + n], h, lo);
        g_updt_h[i] = h; g_updt_l[i] = lo;
    } else if (idx < 244096) {
        int i = idx - 211328;
        int n = i / 128, k = i % 128;
        __nv_bfloat16 h, l; split_bf16(fc1W[k * 256 + n], h, l);
        g_fc1t_h[i] = h; g_fc1t_l[i] = l;
    } else if (idx < PACK_TOTAL) {
        int i = idx - 244096;
        __nv_bfloat16 h, l; split_bf16(x[i], h, l);
        g_xh[i] = h; g_xl[i] = l;
    }
}

// ---------------- init: zero deg/gsum, per-graph counts via binary search --------
__global__ void k_init(const int* __restrict__ batch) {
    int i = blockIdx.x * blockDim.x + threadIdx.x;
    if (i < NN) g_deg[i] = 0;
    if (i < NG) {
        g_gsum[i] = 0.f;
        int lo = 0, hi = NN;
        while (lo < hi) { int m = (lo + hi) >> 1; if (batch[m] < i) lo = m + 1; else hi = m; }
        int lo2 = lo, hi2 = NN;
        while (lo2 < hi2) { int m = (lo2 + hi2) >> 1; if (batch[m] < i + 1) lo2 = m + 1; else hi2 = m; }
        g_gcnt[i] = (float)(lo2 - lo);
    }
}

__global__ void k_deg(const int* __restrict__ dst) {
    int e = blockIdx.x * blockDim.x + threadIdx.x;
    if (e < NE) atomicAdd(&g_deg[dst[e]], 1);
}

// ---------------- parallel 3-phase exclusive scan of degrees ---------------------
__global__ void k_scan1() {
    __shared__ int ws[8];
    int t = threadIdx.x, lane = t & 31, w = t >> 5;
    int i = blockIdx.x * 256 + t;
    int d = (i < NN) ? g_deg[i] : 0;
    int s = __reduce_add_sync(0xffffffffu, d);
    if (lane == 0) ws[w] = s;
    __syncthreads();
    if (t == 0) {
        int tot = 0;
        for (int j = 0; j < 8; j++) tot += ws[j];
        g_bsum[blockIdx.x] = tot;
    }
}
__global__ void k_scan2(int nblk) {
    __shared__ int wsum[8];
    int t = threadIdx.x, lane = t & 31, w = t >> 5;
    int v = (t < nblk) ? g_bsum[t] : 0;
    int x = v;
#pragma unroll
    for (int off = 1; off < 32; off <<= 1) {
        int y = __shfl_up_sync(0xffffffffu, x, off);
        if (lane >= off) x += y;
    }
    if (lane == 31) wsum[w] = x;
    __syncthreads();
    if (t == 0) {
        int r = 0;
        for (int j = 0; j < 8; j++) { int tmp = wsum[j]; wsum[j] = r; r += tmp; }
        g_row[NN] = NE;
    }
    __syncthreads();
    if (t < nblk) g_boff[t] = x - v + wsum[w];
}
__global__ void k_scan3() {
    __shared__ int wsum[8];
    int t = threadIdx.x, lane = t & 31, w = t >> 5;
    int i = blockIdx.x * 256 + t;
    int d = (i < NN) ? g_deg[i] : 0;
    int x = d;
#pragma unroll
    for (int off = 1; off < 32; off <<= 1) {
        int y = __shfl_up_sync(0xffffffffu, x, off);
        if (lane >= off) x += y;
    }
    if (lane == 31) wsum[w] = x;
    __syncthreads();
    if (t == 0) {
        int r = 0;
        for (int j = 0; j < 8; j++) { int tmp = wsum[j]; wsum[j] = r; r += tmp; }
    }
    __syncthreads();
    int excl = x - d + wsum[w] + g_boff[blockIdx.x];
    if (i < NN) { g_row[i] = excl; g_cur[i] = excl; }
}

__global__ void k_fill(const int* __restrict__ src, const int* __restrict__ dst) {
    int e = blockIdx.x * blockDim.x + threadIdx.x;
    if (e < NE) {
        int d = dst[e];
        int p = atomicAdd(&g_cur[d], 1);
        g_psrc[p] = src[e];
        g_peid[p] = e;
    }
}

// ================= bf16x3 mma.sync GEMM with ldmatrix + cp.async =================
// act: 0 = none, 1 = relu, 2 = fused LN+tanh (ncols==128, grid.y==1),
//      3 = fused relu + fc2-dot + graph pooling (writes g_gsum via atomics)
#define MMA_BF16(d, a, b0, b1) \
    asm volatile("mma.sync.aligned.m16n8k16.row.col.f32.bf16.bf16.f32 " \
        "{%0,%1,%2,%3}, {%4,%5,%6,%7}, {%8,%9}, {%0,%1,%2,%3};" \
        : "+f"(d[0]), "+f"(d[1]), "+f"(d[2]), "+f"(d[3]) \
        : "r"(a[0]), "r"(a[1]), "r"(a[2]), "r"(a[3]), "r"(b0), "r"(b1));

#define LDSM_X4(r, a) \
    asm volatile("ldmatrix.sync.aligned.m8n8.x4.shared.b16 {%0,%1,%2,%3}, [%4];" \
        : "=r"((r)[0]), "=r"((r)[1]), "=r"((r)[2]), "=r"((r)[3]) : "r"(a))

#define CP_ASYNC(sa, ga, sz) \
    asm volatile("cp.async.ca.shared.global [%0], [%1], 16, %2;" :: "r"(sa), "l"(ga), "r"(sz))
#define CP_COMMIT() asm volatile("cp.async.commit_group;" ::: "memory")
#define CP_WAIT(n)  asm volatile("cp.async.wait_group %0;" :: "n"(n) : "memory")

__device__ __forceinline__ uint32_t smem_u32(const void* p) {
    uint32_t a;
    asm("{ .reg .u64 t; cvta.to.shared.u64 t, %1; cvt.u32.u64 %0, t; }" : "=r"(a) : "l"(p));
    return a;
}

#define GEMM_SMEM (2 * 40960)

__global__ void __launch_bounds__(256) k_mgemm(
    const __nv_bfloat16* __restrict__ X1h, const __nv_bfloat16* __restrict__ X1l, int K1,
    const __nv_bfloat16* __restrict__ X2h, const __nv_bfloat16* __restrict__ X2l, int K2,
    const __nv_bfloat16* __restrict__ Wh,  const __nv_bfloat16* __restrict__ Wl,
    const float* __restrict__ bias, float* __restrict__ Y,
    __nv_bfloat16* __restrict__ Yh, __nv_bfloat16* __restrict__ Yl,
    const float* __restrict__ lnw, const float* __restrict__ lnb,
    const int* __restrict__ batch,
    int nrows, int ncols, int act)
{
    extern __shared__ char smem[];
    const uint32_t sb = smem_u32(smem);
    const int tid = threadIdx.x;
    const int wid = tid >> 5, lane = tid & 31;
    const int wm = wid & 1, wn = wid >> 1;
    const int g = lane >> 2, t = lane & 3;
    const int rbase = blockIdx.x * 128, cbase = blockIdx.y * 128;
    const int Ktot = K1 + K2;
    const int nch = Ktot >> 5;

    const int srow = tid >> 1;
    const int sseg = (tid & 1) * 2;

    float acc[4][4][4];
#pragma unroll
    for (int i = 0; i < 4; i++)
#pragma unroll
        for (int j = 0; j < 4; j++)
#pragma unroll
            for (int q = 0; q < 4; q++) acc[i][j][q] = 0.f;

    const int quad = lane >> 3, li = lane & 7;
    const int a_row = (quad & 1) * 8 + li;
    const int a_col = (quad >> 1) * 8;
    const int b_row = (quad >> 1) * 8 + li;
    const int b_col = (quad & 1) * 8;

    auto stage = [&](int ch, int buf) {
        const int kk = ch << 5;
        const uint32_t base = sb + buf * 40960;
        {
            const __nv_bfloat16 *Xh, *Xl; int xs, kx;
            if (kk < K1) { Xh = X1h; Xl = X1l; xs = K1; kx = kk; }
            else         { Xh = X2h; Xl = X2l; xs = K2; kx = kk - K1; }
            int gr = rbase + srow;
            uint32_t sz = (gr < nrows) ? 16u : 0u;
            if (gr >= nrows) gr = nrows - 1;
            const __nv_bfloat16* ph = Xh + (size_t)gr * xs + kx;
            const __nv_bfloat16* pl = Xl + (size_t)gr * xs + kx;
#pragma unroll
            for (int q = 0; q < 2; q++) {
                const int seg = sseg + q;
                const uint32_t so = base + srow * 80 + seg * 16;
                CP_ASYNC(so,         ph + seg * 8, sz);
                CP_ASYNC(so + 10240, pl + seg * 8, sz);
            }
        }
        {
            const int gn = cbase + srow;
            const __nv_bfloat16* ph = Wh + (size_t)gn * Ktot + kk;
            const __nv_bfloat16* pl = Wl + (size_t)gn * Ktot + kk;
#pragma unroll
            for (int q = 0; q < 2; q++) {
                const int seg = sseg + q;
                const uint32_t so = base + 20480 + srow * 80 + seg * 16;
                CP_ASYNC(so,         ph + seg * 8, 16u);
                CP_ASYNC(so + 10240, pl + seg * 8, 16u);
            }
        }
        CP_COMMIT();
    };

    stage(0, 0);
    for (int ch = 0; ch < nch; ch++) {
        const int buf = ch & 1;
        const bool more = (ch + 1 < nch);
        if (more) stage(ch + 1, buf ^ 1);
        if (more) { CP_WAIT(1); } else { CP_WAIT(0); }
        __syncthreads();

        const uint32_t base = sb + buf * 40960;
        const uint32_t aah = base + (wm * 64 + a_row) * 80 + a_col * 2;
        const uint32_t bbh = base + 20480 + (wn * 32 + b_row) * 80 + b_col * 2;
#pragma unroll
        for (int s = 0; s < 2; s++) {
            const uint32_t ks2 = s * 32;
            uint32_t ah[4][4], al[4][4];
#pragma unroll
            for (int mt = 0; mt < 4; mt++) {
                LDSM_X4(ah[mt], aah + mt * 1280 + ks2);
                LDSM_X4(al[mt], aah + 10240 + mt * 1280 + ks2);
            }
            uint32_t bh[4][2], bl[4][2];
#pragma unroll
            for (int pr = 0; pr < 2; pr++) {
                uint32_t tmp[4];
                LDSM_X4(tmp, bbh + pr * 1280 + ks2);
                bh[2 * pr][0] = tmp[0]; bh[2 * pr][1] = tmp[1];
                bh[2 * pr + 1][0] = tmp[2]; bh[2 * pr + 1][1] = tmp[3];
                LDSM_X4(tmp, bbh + 10240 + pr * 1280 + ks2);
                bl[2 * pr][0] = tmp[0]; bl[2 * pr][1] = tmp[1];
                bl[2 * pr + 1][0] = tmp[2]; bl[2 * pr + 1][1] = tmp[3];
            }
#pragma unroll
            for (int nt = 0; nt < 4; nt++)
#pragma unroll
                for (int mt = 0; mt < 4; mt++) {
                    MMA_BF16(acc[mt][nt], ah[mt], bh[nt][0], bh[nt][1]);
                    MMA_BF16(acc[mt][nt], ah[mt], bl[nt][0], bl[nt][1]);
                    MMA_BF16(acc[mt][nt], al[mt], bh[nt][0], bh[nt][1]);
                }
        }
        __syncthreads();
    }

    if (act == 2) {
        // ---- fused LayerNorm + tanh + bf16-split epilogue ----
        float* tb = (float*)smem;                 // 128 x 132 fp32
#pragma unroll
        for (int mt = 0; mt < 4; mt++)
#pragma unroll
            for (int half = 0; half < 2; half++) {
                int row = wm * 64 + mt * 16 + g + 8 * half;
#pragma unroll
                for (int nt = 0; nt < 4; nt++) {
                    int col = wn * 32 + nt * 8 + 2 * t;
                    tb[row * 132 + col]     = acc[mt][nt][2 * half + 0] + bias[col];
                    tb[row * 132 + col + 1] = acc[mt][nt][2 * half + 1] + bias[col + 1];
                }
            }
        __syncthreads();
        float lw[4], lb[4];
#pragma unroll
        for (int j = 0; j < 4; j++) { lw[j] = lnw[lane + 32 * j]; lb[j] = lnb[lane + 32 * j]; }
#pragma unroll 1
        for (int it = 0; it < 16; it++) {
            int row = wid * 16 + it;
            int grow = rbase + row;
            float v[4];
#pragma unroll
            for (int j = 0; j < 4; j++) v[j] = tb[row * 132 + lane + 32 * j];
            float s = v[0] + v[1] + v[2] + v[3];
            float q = v[0] * v[0];
            q = fmaf(v[1], v[1], q);
            q = fmaf(v[2], v[2], q);
            q = fmaf(v[3], v[3], q);
#pragma unroll
            for (int off = 16; off > 0; off >>= 1) {
                s += __shfl_xor_sync(0xffffffffu, s, off);
                q += __shfl_xor_sync(0xffffffffu, q, off);
            }
            float mean = s * (1.f / 128.f);
            float var = q * (1.f / 128.f) - mean * mean;
            float rstd = rsqrtf(var + 1e-5f);
            if (grow < nrows) {
#pragma unroll
                for (int j = 0; j < 4; j++) {
                    float y = (v[j] - mean) * rstd * lw[j] + lb[j];
                    __nv_bfloat16 h, l; split_bf16(tanh_fast(y), h, l);
                    Yh[(size_t)grow * 128 + lane + 32 * j] = h;
                    Yl[(size_t)grow * 128 + lane + 32 * j] = l;
                }
            }
        }
        return;
    }

    if (act == 3) {
        // ---- fused relu + fc2 dot + graph pooling (lnw = fc2w, lnb = &fc2b) ----
        float* rs = (float*)smem;                 // 128 rowsums
        if (tid < 128) rs[tid] = 0.f;
        __syncthreads();
#pragma unroll
        for (int mt = 0; mt < 4; mt++)
#pragma unroll
            for (int half = 0; half < 2; half++) {
                float p = 0.f;
#pragma unroll
                for (int nt = 0; nt < 4; nt++) {
                    int col = cbase + wn * 32 + nt * 8 + 2 * t;
                    float v0 = fmaxf(acc[mt][nt][2 * half + 0] + bias[col], 0.f);
                    float v1 = fmaxf(acc[mt][nt][2 * half + 1] + bias[col + 1], 0.f);
                    p = fmaf(v0, lnw[col], p);
                    p = fmaf(v1, lnw[col + 1], p);
                }
                p += __shfl_xor_sync(0xffffffffu, p, 1);
                p += __shfl_xor_sync(0xffffffffu, p, 2);
                if (t == 0) atomicAdd(&rs[wm * 64 + mt * 16 + g + 8 * half], p);
            }
        __syncthreads();
        if (tid < 128) {
            int grow = rbase + tid;
            if (grow < nrows) {
                float v = rs[tid];
                if (cbase == 0) v += lnb[0];
                atomicAdd(&g_gsum[batch[grow]], v);
            }
        }
        return;
    }

#pragma unroll
    for (int mt = 0; mt < 4; mt++) {
#pragma unroll
        for (int half = 0; half < 2; half++) {
            int row = rbase + wm * 64 + mt * 16 + g + 8 * half;
            if (row >= nrows) continue;
#pragma unroll
            for (int nt = 0; nt < 4; nt++) {
                int col = cbase + wn * 32 + nt * 8 + 2 * t;
                float v0 = acc[mt][nt][2 * half + 0] + bias[col];
                float v1 = acc[mt][nt][2 * half + 1] + bias[col + 1];
                if (act == 1) { v0 = fmaxf(v0, 0.f); v1 = fmaxf(v1, 0.f); }
                if (Y) {
                    float2 v; v.x = v0; v.y = v1;
                    *(float2*)(Y + (size_t)row * ncols + col) = v;
                }
                if (Yh) {
                    __nv_bfloat16 h0, l0, h1, l1;
                    split_bf16(v0, h0, l0);
                    split_bf16(v1, h1, l1);
                    __nv_bfloat162 hp; hp.x = h0; hp.y = h1;
                    __nv_bfloat162 lp; lp.x = l0; lp.y = l1;
                    *(__nv_bfloat162*)(Yh + (size_t)row * ncols + col) = hp;
                    *(__nv_bfloat162*)(Yl + (size_t)row * ncols + col) = lp;
                }
            }
        }
    }
}

// ---------------- fused message + LN + tanh + aggregate (warp per dst node) ----
__global__ void __launch_bounds__(256) k_msg(
    const float* __restrict__ yab, const float* __restrict__ Mw,
    const float* __restrict__ lnw, const float* __restrict__ lnb,
    const float* __restrict__ raw,
    __nv_bfloat16* __restrict__ aggh, __nv_bfloat16* __restrict__ aggl)
{
    int warp = (blockIdx.x * blockDim.x + threadIdx.x) >> 5;
    int lane = threadIdx.x & 31;
    if (warp >= NN) return;

    float Mreg[16][4];
#pragma unroll
    for (int k = 0; k < 16; k++)
#pragma unroll
        for (int j = 0; j < 4; j++) Mreg[k][j] = Mw[k * 128 + lane + 32 * j];

    float bj[4], lw[4], lb[4], accj[4];
#pragma unroll
    for (int j = 0; j < 4; j++) {
        bj[j] = yab[(size_t)warp * 256 + 128 + lane + 32 * j];
        lw[j] = lnw[lane + 32 * j];
        lb[j] = lnb[lane + 32 * j];
        accj[j] = 0.f;
    }

    int p0 = g_row[warp], p1 = g_row[warp + 1];
    if (p0 < p1) {
        // prefetch edge p0
        int eid_n = g_peid[p0];
        int src_n = g_psrc[p0];
        float an[4];
        {
            const float* arn = yab + (size_t)src_n * 256;
#pragma unroll
            for (int j = 0; j < 4; j++) an[j] = arn[lane + 32 * j];
        }
        for (int p = p0; p < p1; p++) {
            const int eid = eid_n;
            float a0 = an[0], a1 = an[1], a2 = an[2], a3 = an[3];
            const float4* rp = (const float4*)(raw + (size_t)eid * 16);
            float4 r0 = rp[0], r1 = rp[1], r2 = rp[2], r3 = rp[3];
            // prefetch next edge's indices + A-gather
            if (p + 1 < p1) {
                src_n = g_psrc[p + 1];
                eid_n = g_peid[p + 1];
                const float* arn = yab + (size_t)src_n * 256;
#pragma unroll
                for (int j = 0; j < 4; j++) an[j] = arn[lane + 32 * j];
            }
            float rv[16] = {r0.x, r0.y, r0.z, r0.w, r1.x, r1.y, r1.z, r1.w,
                            r2.x, r2.y, r2.z, r2.w, r3.x, r3.y, r3.z, r3.w};
            float pre[4];
            float ca[4] = {a0, a1, a2, a3};
#pragma unroll
            for (int j = 0; j < 4; j++) {
                float c = bj[j] + ca[j];
#pragma unroll
                for (int k = 0; k < 16; k++) c = fmaf(rv[k], Mreg[k][j], c);
                pre[j] = c;
            }
            float s = pre[0] + pre[1] + pre[2] + pre[3];
            float q = pre[0] * pre[0];
            q = fmaf(pre[1], pre[1], q);
            q = fmaf(pre[2], pre[2], q);
            q = fmaf(pre[3], pre[3], q);
#pragma unroll
            for (int off = 16; off > 0; off >>= 1) {
                s += __shfl_xor_sync(0xffffffffu, s, off);
                q += __shfl_xor_sync(0xffffffffu, q, off);
            }
            float mean = s * (1.f / 128.f);
            float var = q * (1.f / 128.f) - mean * mean;
            float rstd = rsqrtf(var + 1e-5f);
#pragma unroll
            for (int j = 0; j < 4; j++) {
                float y = (pre[j] - mean) * rstd * lw[j] + lb[j];
                accj[j] += tanh_fast(y);
            }
        }
    }
#pragma unroll
    for (int j = 0; j < 4; j++) {
        __nv_bfloat16 h, l; split_bf16(accj[j], h, l);
        aggh[(size_t)warp * 128 + lane + 32 * j] = h;
        aggl[(size_t)warp * 128 + lane + 32 * j] = l;
    }
}

__global__ void k_final(float* __restrict__ out) {
    int g = blockIdx.x * blockDim.x + threadIdx.x;
    if (g < NG) out[g] = g_gsum[g] / fmaxf(g_gcnt[g], 1.0f);
}

// ---------------- host orchestration --------------------------------------------
extern "C" void kernel_launch(void* const* d_in, const int* in_sizes, int n_in,
                              void* d_out, int out_size)
{
    const float* x      = (const float*)d_in[0];
    const int*   ei     = (const int*)  d_in[1];
    const float* raw    = (const float*)d_in[2];
    const int*   batch  = (const int*)  d_in[3];
    const float* atomsW = (const float*)d_in[4];
    const float* atomsb = (const float*)d_in[5];
    const float* bondsW = (const float*)d_in[6];
    const float* bondsb = (const float*)d_in[7];
    const float* msgW   = (const float*)d_in[8];
    const float* msgb   = (const float*)d_in[9];
    const float* msglnw = (const float*)d_in[10];
    const float* msglnb = (const float*)d_in[11];
    const float* updW   = (const float*)d_in[12];
    const float* updb   = (const float*)d_in[13];
    const float* updlnw = (const float*)d_in[14];
    const float* updlnb = (const float*)d_in[15];
    const float* fc1W   = (const float*)d_in[16];
    const float* fc1b   = (const float*)d_in[17];
    const float* fc2w   = (const float*)d_in[18];
    const float* fc2b   = (const float*)d_in[19];
    float* out = (float*)d_out;

    const int* src = ei;
    const int* dst = ei + NE;

    cudaFuncSetAttribute(k_mgemm, cudaFuncAttributeMaxDynamicSharedMemorySize, GEMM_SMEM);

    float *p_yab, *p_bab, *p_M;
    cudaGetSymbolAddress((void**)&p_yab, g_yab);
    cudaGetSymbolAddress((void**)&p_bab, g_bab);
    cudaGetSymbolAddress((void**)&p_M,   g_M);
    __nv_bfloat16 *p_xh, *p_xl, *p_hh, *p_hl, *p_aggh, *p_aggl;
    __nv_bfloat16 *p_wabh, *p_wabl, *p_updh, *p_updl, *p_fc1h, *p_fc1l, *p_atmh, *p_atml;
    cudaGetSymbolAddress((void**)&p_xh,   g_xh);
    cudaGetSymbolAddress((void**)&p_xl,   g_xl);
    cudaGetSymbolAddress((void**)&p_hh,   g_hh);
    cudaGetSymbolAddress((void**)&p_hl,   g_hl);
    cudaGetSymbolAddress((void**)&p_aggh, g_aggh);
    cudaGetSymbolAddress((void**)&p_aggl, g_aggl);
    cudaGetSymbolAddress((void**)&p_wabh, g_wabt_h);
    cudaGetSymbolAddress((void**)&p_wabl, g_wabt_l);
    cudaGetSymbolAddress((void**)&p_updh, g_updt_h);
    cudaGetSymbolAddress((void**)&p_updl, g_updt_l);
    cudaGetSymbolAddress((void**)&p_fc1h, g_fc1t_h);
    cudaGetSymbolAddress((void**)&p_fc1l, g_fc1t_l);
    cudaGetSymbolAddress((void**)&p_atmh, g_atmt_h);
    cudaGetSymbolAddress((void**)&p_atml, g_atmt_l);

    const int SCAN_BLK = (NN + 255) / 256;   // 157
    const int RB = (NN + 127) / 128;
    dim3 g128(RB, 1), g256(RB, 2);

    // launch 0-2
    k_pack_all<<<(PACK_TOTAL + 255) / 256, 256>>>(msgW, bondsW, bondsb, msgb,
                                                  atomsW, updW, fc1W, x);
    k_init<<<(NN + 255) / 256, 256>>>(batch);
    k_deg<<<(NE + 255) / 256, 256>>>(dst);

    // launch 3 == ncu capture target: embed GEMM (depends only on pack)
    k_mgemm<<<g128, 256, GEMM_SMEM>>>(p_xh, p_xl, 64,
                                      (const __nv_bfloat16*)0, (const __nv_bfloat16*)0, 0,
                                      p_atmh, p_atml, atomsb, (float*)0, p_hh, p_hl,
                                      (const float*)0, (const float*)0, (const int*)0,
                                      NN, 128, 0);

    // CSR build continues
    k_scan1<<<SCAN_BLK, 256>>>();
    k_scan2<<<1, 256>>>(SCAN_BLK);
    k_scan3<<<SCAN_BLK, 256>>>();
    k_fill<<<(NE + 255) / 256, 256>>>(src, dst);

    for (int l = 0; l < 3; l++) {
        k_mgemm<<<g256, 256, GEMM_SMEM>>>(p_hh, p_hl, 128,
                                          (const __nv_bfloat16*)0, (const __nv_bfloat16*)0, 0,
                                          p_wabh + (size_t)l * 256 * 128, p_wabl + (size_t)l * 256 * 128,
                                          p_bab + l * 256, p_yab,
                                          (__nv_bfloat16*)0, (__nv_bfloat16*)0,
                                          (const float*)0, (const float*)0, (const int*)0,
                                          NN, 256, 0);
        k_msg<<<(NN * 32 + 255) / 256, 256>>>(p_yab, p_M + l * 16 * 128,
                                              msglnw + l * 128, msglnb + l * 128,
                                              raw, p_aggh, p_aggl);
        k_mgemm<<<g128, 256, GEMM_SMEM>>>(p_aggh, p_aggl, 128, p_hh, p_hl, 128,
                                          p_updh + (size_t)l * 128 * 256, p_updl + (size_t)l * 128 * 256,
                                          updb + l * 128, (float*)0, p_hh, p_hl,
                                          updlnw + l * 128, updlnb + l * 128, (const int*)0,
                                          NN, 128, 2);
    }

    // readout: fused fc1 + relu + fc2 dot + pooling
    k_mgemm<<<g256, 256, GEMM_SMEM>>>(p_hh, p_hl, 128,
                                      (const __nv_bfloat16*)0, (const __nv_bfloat16*)0, 0,
                                      p_fc1h, p_fc1l, fc1b, (float*)0,
                                      (__nv_bfloat16*)0, (__nv_bfloat16*)0,
                                      fc2w, fc2b, batch,
                                      NN, 256, 3);
    k_final<<<(NG + 255) / 256, 256>>>(out);
}

// round 11
// speedup vs baseline: 1.4269x; 1.0050x over previous
#include <cuda_runtime.h>
#include <cuda_bf16.h>
#include <math.h>
#include <stdint.h>

#define NN 40000
#define NE 640000
#define NG 1024

// ---------------- scratch (device globals; no allocations allowed) -------------
__device__ float g_yab [NN * 256];
__device__ float g_bab [3 * 256];
__device__ float g_M   [3 * 16 * 128];
__device__ float g_ub0 [128];

__device__ __nv_bfloat16 g_xh  [NN * 64],  g_xl  [NN * 64];
__device__ __nv_bfloat16 g_hh  [NN * 128], g_hl  [NN * 128];
__device__ __nv_bfloat16 g_aggh[NN * 128], g_aggl[NN * 128];
__device__ __nv_bfloat16 g_wabt_h[3 * 256 * 128], g_wabt_l[3 * 256 * 128];
__device__ __nv_bfloat16 g_updt_h[3 * 128 * 256], g_updt_l[3 * 128 * 256];
__device__ __nv_bfloat16 g_fc1t_h[256 * 128],     g_fc1t_l[256 * 128];
__device__ __nv_bfloat16 g_w0t_h[256 * 64],       g_w0t_l[256 * 64];
__device__ __nv_bfloat16 g_u0t_h[128 * 192],      g_u0t_l[128 * 192];

__device__ int   g_deg [NN];
__device__ int   g_row [NN + 1];
__device__ int   g_cur [NN];
__device__ int   g_bsum[160];
__device__ int   g_boff[160];
__device__ int   g_psrc[NE];
__device__ int   g_peid[NE];
__device__ float g_gsum[NG];
__device__ float g_gcnt[NG];

// ---------------- helpers --------------------------------------------------------
__device__ __forceinline__ void split_bf16(float v, __nv_bfloat16& h, __nv_bfloat16& l) {
    h = __float2bfloat16(v);
    l = __float2bfloat16(v - __bfloat162float(h));
}
__device__ __forceinline__ float tanh_fast(float x) {
    float y;
    asm("tanh.approx.f32 %0, %1;" : "=f"(y) : "f"(x));
    return y;
}

// ---------------- merged packing + weight folding + init kernel ------------------
// r0 [0,98304)        : [W1|W2]^T split (3 layers)
// r1 [98304,104832)   : M = bondsW@W3 (6144) ; folded biases -> g_bab (384)
// r2 [104832,203136)  : updW^T split (3 layers, Ktot=256 layout)
// r3 [203136,235904)  : fc1W^T split
// r4 [235904,2795904) : x split
// r5 [2795904,2812288): wab0 fold  W0[n][m] = sum_j Wa[m][j]*Wab[j][n]   (256x64)
// r6 [2812288,2828672): upd0 copy  U0[n][k] = updW0[k][n], k<128         (128x128)
// r7 [2828672,2836864): upd0 fold  U0[n][128+m] = sum_j Wa[m][j]*U2[j][n](128x64)
// r8 [2836864,2836992): ub0[n] = updb0[n] + sum_j atomsb[j]*U2[j][n]
// r9 [2836992,2876992): g_deg = 0
// r10[2876992,2878016): g_gsum=0, g_gcnt via binary search on sorted batch
#define PACK_TOTAL 2878016
__global__ void k_pack_all(const float* __restrict__ msgW, const float* __restrict__ bondsW,
                           const float* __restrict__ bondsb, const float* __restrict__ msgb,
                           const float* __restrict__ atomsW, const float* __restrict__ atomsb,
                           const float* __restrict__ updW, const float* __restrict__ updb,
                           const float* __restrict__ fc1W, const float* __restrict__ x,
                           const int* __restrict__ batch)
{
    int idx = blockIdx.x * blockDim.x + threadIdx.x;
    if (idx < 98304) {
        int l = idx / 32768, r = idx % 32768;
        int n = r / 128, k = r % 128;
        const float* Wl = msgW + (size_t)l * 384 * 128;
        float v = (n < 128) ? Wl[k * 128 + n] : Wl[(128 + k) * 128 + (n - 128)];
        __nv_bfloat16 h, lo; split_bf16(v, h, lo);
        g_wabt_h[idx] = h; g_wabt_l[idx] = lo;
    } else if (idx < 104832) {
        int i2 = idx - 98304;
        if (i2 < 3 * 16 * 128) {
            int l = i2 / 2048, k = (i2 / 128) & 15, d = i2 & 127;
            const float* W3 = msgW + (size_t)l * 384 * 128 + 256 * 128;
            float s = 0.f;
            for (int j = 0; j < 128; j++) s += bondsW[k * 128 + j] * W3[j * 128 + d];
            g_M[i2] = s;
        } else {
            int i3 = i2 - 3 * 16 * 128;
            int l = i3 / 128, d = i3 & 127;
            const float* W3 = msgW + (size_t)l * 384 * 128 + 256 * 128;
            float s = msgb[l * 128 + d];
            for (int j = 0; j < 128; j++) s += bondsb[j] * W3[j * 128 + d];
            float sB = 0.f;
            if (l == 0) {
                const float* W0 = msgW;
                float sA = 0.f;
                for (int j = 0; j < 128; j++) {
                    sA += atomsb[j] * W0[j * 128 + d];
                    sB += atomsb[j] * W0[(128 + j) * 128 + d];
                }
                s += sA;
            }
            g_bab[l * 256 + d] = s;
            g_bab[l * 256 + 128 + d] = sB;
        }
    } else if (idx < 203136) {
        int i = idx - 104832;
        int l = i / 32768, r = i % 32768;
        int n = r / 256, k = r % 256;
        const float* Wl = updW + (size_t)l * 256 * 128;
        __nv_bfloat16 h, lo; split_bf16(Wl[k * 128 + n], h, lo);
        g_updt_h[i] = h; g_updt_l[i] = lo;
    } else if (idx < 235904) {
        int i = idx - 203136;
        int n = i / 128, k = i % 128;
        __nv_bfloat16 h, l; split_bf16(fc1W[k * 256 + n], h, l);
        g_fc1t_h[i] = h; g_fc1t_l[i] = l;
    } else if (idx < 2795904) {
        int i = idx - 235904;
        __nv_bfloat16 h, l; split_bf16(x[i], h, l);
        g_xh[i] = h; g_xl[i] = l;
    } else if (idx < 2812288) {
        int i = idx - 2795904;               // wab0 fold: n in [0,256), m in [0,64)
        int n = i / 64, m = i % 64;
        const float* W0 = msgW;
        float s = 0.f;
        if (n < 128) {
            for (int j = 0; j < 128; j++) s += atomsW[m * 128 + j] * W0[j * 128 + n];
        } else {
            for (int j = 0; j < 128; j++) s += atomsW[m * 128 + j] * W0[(128 + j) * 128 + (n - 128)];
        }
        __nv_bfloat16 h, lo; split_bf16(s, h, lo);
        g_w0t_h[i] = h; g_w0t_l[i] = lo;
    } else if (idx < 2828672) {
        int i = idx - 2812288;               // upd0 copy: n in [0,128), k in [0,128)
        int n = i / 128, k = i % 128;
        __nv_bfloat16 h, lo; split_bf16(updW[k * 128 + n], h, lo);
        g_u0t_h[n * 192 + k] = h; g_u0t_l[n * 192 + k] = lo;
    } else if (idx < 2836864) {
        int i = idx - 2828672;               // upd0 fold: n in [0,128), m in [0,64)
        int n = i / 64, m = i % 64;
        float s = 0.f;
        for (int j = 0; j < 128; j++) s += atomsW[m * 128 + j] * updW[(128 + j) * 128 + n];
        __nv_bfloat16 h, lo; split_bf16(s, h, lo);
        g_u0t_h[n * 192 + 128 + m] = h; g_u0t_l[n * 192 + 128 + m] = lo;
    } else if (idx < 2836992) {
        int n = idx - 2836864;
        float s = updb[n];
        for (int j = 0; j < 128; j++) s += atomsb[j] * updW[(128 + j) * 128 + n];
        g_ub0[n] = s;
    } else if (idx < 2876992) {
        g_deg[idx - 2836992] = 0;
    } else if (idx < PACK_TOTAL) {
        int i = idx - 2876992;
        g_gsum[i] = 0.f;
        int lo = 0, hi = NN;
        while (lo < hi) { int m = (lo + hi) >> 1; if (batch[m] < i) lo = m + 1; else hi = m; }
        int lo2 = lo, hi2 = NN;
        while (lo2 < hi2) { int m = (lo2 + hi2) >> 1; if (batch[m] < i + 1) lo2 = m + 1; else hi2 = m; }
        g_gcnt[i] = (float)(lo2 - lo);
    }
}

__global__ void k_deg(const int* __restrict__ dst) {
    int e = blockIdx.x * blockDim.x + threadIdx.x;
    if (e < NE) atomicAdd(&g_deg[dst[e]], 1);
}

// ---------------- parallel 3-phase exclusive scan of degrees ---------------------
__global__ void k_scan1() {
    __shared__ int ws[8];
    int t = threadIdx.x, lane = t & 31, w = t >> 5;
    int i = blockIdx.x * 256 + t;
    int d = (i < NN) ? g_deg[i] : 0;
    int s = __reduce_add_sync(0xffffffffu, d);
    if (lane == 0) ws[w] = s;
    __syncthreads();
    if (t == 0) {
        int tot = 0;
        for (int j = 0; j < 8; j++) tot += ws[j];
        g_bsum[blockIdx.x] = tot;
    }
}
__global__ void k_scan2(int nblk) {
    __shared__ int wsum[8];
    int t = threadIdx.x, lane = t & 31, w = t >> 5;
    int v = (t < nblk) ? g_bsum[t] : 0;
    int x = v;
#pragma unroll
    for (int off = 1; off < 32; off <<= 1) {
        int y = __shfl_up_sync(0xffffffffu, x, off);
        if (lane >= off) x += y;
    }
    if (lane == 31) wsum[w] = x;
    __syncthreads();
    if (t == 0) {
        int r = 0;
        for (int j = 0; j < 8; j++) { int tmp = wsum[j]; wsum[j] = r; r += tmp; }
        g_row[NN] = NE;
    }
    __syncthreads();
    if (t < nblk) g_boff[t] = x - v + wsum[w];
}
__global__ void k_scan3() {
    __shared__ int wsum[8];
    int t = threadIdx.x, lane = t & 31, w = t >> 5;
    int i = blockIdx.x * 256 + t;
    int d = (i < NN) ? g_deg[i] : 0;
    int x = d;
#pragma unroll
    for (int off = 1; off < 32; off <<= 1) {
        int y = __shfl_up_sync(0xffffffffu, x, off);
        if (lane >= off) x += y;
    }
    if (lane == 31) wsum[w] = x;
    __syncthreads();
    if (t == 0) {
        int r = 0;
        for (int j = 0; j < 8; j++) { int tmp = wsum[j]; wsum[j] = r; r += tmp; }
    }
    __syncthreads();
    int excl = x - d + wsum[w] + g_boff[blockIdx.x];
    if (i < NN) { g_row[i] = excl; g_cur[i] = excl; }
}

__global__ void k_fill(const int* __restrict__ src, const int* __restrict__ dst) {
    int e = blockIdx.x * blockDim.x + threadIdx.x;
    if (e < NE) {
        int d = dst[e];
        int p = atomicAdd(&g_cur[d], 1);
        g_psrc[p] = src[e];
        g_peid[p] = e;
    }
}

// ================= bf16x3 mma.sync GEMM with ldmatrix + cp.async =================
// act: 0 = none (Y and/or Yh/Yl), 1 = relu, 2 = fused LN+tanh (ncols==128, grid.y==1),
//      3 = fused relu + fc2-dot + graph pooling
#define MMA_BF16(d, a, b0, b1) \
    asm volatile("mma.sync.aligned.m16n8k16.row.col.f32.bf16.bf16.f32 " \
        "{%0,%1,%2,%3}, {%4,%5,%6,%7}, {%8,%9}, {%0,%1,%2,%3};" \
        : "+f"(d[0]), "+f"(d[1]), "+f"(d[2]), "+f"(d[3]) \
        : "r"(a[0]), "r"(a[1]), "r"(a[2]), "r"(a[3]), "r"(b0), "r"(b1));

#define LDSM_X4(r, a) \
    asm volatile("ldmatrix.sync.aligned.m8n8.x4.shared.b16 {%0,%1,%2,%3}, [%4];" \
        : "=r"((r)[0]), "=r"((r)[1]), "=r"((r)[2]), "=r"((r)[3]) : "r"(a))

#define CP_ASYNC(sa, ga, sz) \
    asm volatile("cp.async.ca.shared.global [%0], [%1], 16, %2;" :: "r"(sa), "l"(ga), "r"(sz))
#define CP_COMMIT() asm volatile("cp.async.commit_group;" ::: "memory")
#define CP_WAIT(n)  asm volatile("cp.async.wait_group %0;" :: "n"(n) : "memory")

__device__ __forceinline__ uint32_t smem_u32(const void* p) {
    uint32_t a;
    asm("{ .reg .u64 t; cvta.to.shared.u64 t, %1; cvt.u32.u64 %0, t; }" : "=r"(a) : "l"(p));
    return a;
}

#define GEMM_SMEM (2 * 40960)

__global__ void __launch_bounds__(256) k_mgemm(
    const __nv_bfloat16* __restrict__ X1h, const __nv_bfloat16* __restrict__ X1l, int K1,
    const __nv_bfloat16* __restrict__ X2h, const __nv_bfloat16* __restrict__ X2l, int K2,
    const __nv_bfloat16* __restrict__ Wh,  const __nv_bfloat16* __restrict__ Wl,
    const float* __restrict__ bias, float* __restrict__ Y,
    __nv_bfloat16* __restrict__ Yh, __nv_bfloat16* __restrict__ Yl,
    const float* __restrict__ lnw, const float* __restrict__ lnb,
    const int* __restrict__ batch,
    int nrows, int ncols, int act)
{
    extern __shared__ char smem[];
    const uint32_t sb = smem_u32(smem);
    const int tid = threadIdx.x;
    const int wid = tid >> 5, lane = tid & 31;
    const int wm = wid & 1, wn = wid >> 1;
    const int g = lane >> 2, t = lane & 3;
    const int rbase = blockIdx.x * 128, cbase = blockIdx.y * 128;
    const int Ktot = K1 + K2;
    const int nch = Ktot >> 5;

    const int srow = tid >> 1;
    const int sseg = (tid & 1) * 2;

    float acc[4][4][4];
#pragma unroll
    for (int i = 0; i < 4; i++)
#pragma unroll
        for (int j = 0; j < 4; j++)
#pragma unroll
            for (int q = 0; q < 4; q++) acc[i][j][q] = 0.f;

    const int quad = lane >> 3, li = lane & 7;
    const int a_row = (quad & 1) * 8 + li;
    const int a_col = (quad >> 1) * 8;
    const int b_row = (quad >> 1) * 8 + li;
    const int b_col = (quad & 1) * 8;

    auto stage = [&](int ch, int buf) {
        const int kk = ch << 5;
        const uint32_t base = sb + buf * 40960;
        {
            const __nv_bfloat16 *Xh, *Xl; int xs, kx;
            if (kk < K1) { Xh = X1h; Xl = X1l; xs = K1; kx = kk; }
            else         { Xh = X2h; Xl = X2l; xs = K2; kx = kk - K1; }
            int gr = rbase + srow;
            uint32_t sz = (gr < nrows) ? 16u : 0u;
            if (gr >= nrows) gr = nrows - 1;
            const __nv_bfloat16* ph = Xh + (size_t)gr * xs + kx;
            const __nv_bfloat16* pl = Xl + (size_t)gr * xs + kx;
#pragma unroll
            for (int q = 0; q < 2; q++) {
                const int seg = sseg + q;
                const uint32_t so = base + srow * 80 + seg * 16;
                CP_ASYNC(so,         ph + seg * 8, sz);
                CP_ASYNC(so + 10240, pl + seg * 8, sz);
            }
        }
        {
            const int gn = cbase + srow;
            const __nv_bfloat16* ph = Wh + (size_t)gn * Ktot + kk;
            const __nv_bfloat16* pl = Wl + (size_t)gn * Ktot + kk;
#pragma unroll
            for (int q = 0; q < 2; q++) {
                const int seg = sseg + q;
                const uint32_t so = base + 20480 + srow * 80 + seg * 16;
                CP_ASYNC(so,         ph + seg * 8, 16u);
                CP_ASYNC(so + 10240, pl + seg * 8, 16u);
            }
        }
        CP_COMMIT();
    };

    stage(0, 0);
    for (int ch = 0; ch < nch; ch++) {
        const int buf = ch & 1;
        const bool more = (ch + 1 < nch);
        if (more) stage(ch + 1, buf ^ 1);
        if (more) { CP_WAIT(1); } else { CP_WAIT(0); }
        __syncthreads();

        const uint32_t base = sb + buf * 40960;
        const uint32_t aah = base + (wm * 64 + a_row) * 80 + a_col * 2;
        const uint32_t bbh = base + 20480 + (wn * 32 + b_row) * 80 + b_col * 2;
#pragma unroll
        for (int s = 0; s < 2; s++) {
            const uint32_t ks2 = s * 32;
            uint32_t ah[4][4], al[4][4];
#pragma unroll
            for (int mt = 0; mt < 4; mt++) {
                LDSM_X4(ah[mt], aah + mt * 1280 + ks2);
                LDSM_X4(al[mt], aah + 10240 + mt * 1280 + ks2);
            }
            uint32_t bh[4][2], bl[4][2];
#pragma unroll
            for (int pr = 0; pr < 2; pr++) {
                uint32_t tmp[4];
                LDSM_X4(tmp, bbh + pr * 1280 + ks2);
                bh[2 * pr][0] = tmp[0]; bh[2 * pr][1] = tmp[1];
                bh[2 * pr + 1][0] = tmp[2]; bh[2 * pr + 1][1] = tmp[3];
                LDSM_X4(tmp, bbh + 10240 + pr * 1280 + ks2);
                bl[2 * pr][0] = tmp[0]; bl[2 * pr][1] = tmp[1];
                bl[2 * pr + 1][0] = tmp[2]; bl[2 * pr + 1][1] = tmp[3];
            }
#pragma unroll
            for (int nt = 0; nt < 4; nt++)
#pragma unroll
                for (int mt = 0; mt < 4; mt++) {
                    MMA_BF16(acc[mt][nt], ah[mt], bh[nt][0], bh[nt][1]);
                    MMA_BF16(acc[mt][nt], ah[mt], bl[nt][0], bl[nt][1]);
                    MMA_BF16(acc[mt][nt], al[mt], bh[nt][0], bh[nt][1]);
                }
        }
        __syncthreads();
    }

    if (act == 2) {
        float* tb = (float*)smem;
#pragma unroll
        for (int mt = 0; mt < 4; mt++)
#pragma unroll
            for (int half = 0; half < 2; half++) {
                int row = wm * 64 + mt * 16 + g + 8 * half;
#pragma unroll
                for (int nt = 0; nt < 4; nt++) {
                    int col = wn * 32 + nt * 8 + 2 * t;
                    tb[row * 132 + col]     = acc[mt][nt][2 * half + 0] + bias[col];
                    tb[row * 132 + col + 1] = acc[mt][nt][2 * half + 1] + bias[col + 1];
                }
            }
        __syncthreads();
        float lw[4], lb[4];
#pragma unroll
        for (int j = 0; j < 4; j++) { lw[j] = lnw[lane + 32 * j]; lb[j] = lnb[lane + 32 * j]; }
#pragma unroll 1
        for (int it = 0; it < 16; it++) {
            int row = wid * 16 + it;
            int grow = rbase + row;
            float v[4];
#pragma unroll
            for (int j = 0; j < 4; j++) v[j] = tb[row * 132 + lane + 32 * j];
            float s = v[0] + v[1] + v[2] + v[3];
            float q = v[0] * v[0];
            q = fmaf(v[1], v[1], q);
            q = fmaf(v[2], v[2], q);
            q = fmaf(v[3], v[3], q);
#pragma unroll
            for (int off = 16; off > 0; off >>= 1) {
                s += __shfl_xor_sync(0xffffffffu, s, off);
                q += __shfl_xor_sync(0xffffffffu, q, off);
            }
            float mean = s * (1.f / 128.f);
            float var = q * (1.f / 128.f) - mean * mean;
            float rstd = rsqrtf(var + 1e-5f);
            if (grow < nrows) {
#pragma unroll
                for (int j = 0; j < 4; j++) {
                    float y = (v[j] - mean) * rstd * lw[j] + lb[j];
                    __nv_bfloat16 h, l; split_bf16(tanh_fast(y), h, l);
                    Yh[(size_t)grow * 128 + lane + 32 * j] = h;
                    Yl[(size_t)grow * 128 + lane + 32 * j] = l;
                }
            }
        }
        return;
    }

    if (act == 3) {
        float* rs = (float*)smem;
        if (tid < 128) rs[tid] = 0.f;
        __syncthreads();
#pragma unroll
        for (int mt = 0; mt < 4; mt++)
#pragma unroll
            for (int half = 0; half < 2; half++) {
                float p = 0.f;
#pragma unroll
                for (int nt = 0; nt < 4; nt++) {
                    int col = cbase + wn * 32 + nt * 8 + 2 * t;
                    float v0 = fmaxf(acc[mt][nt][2 * half + 0] + bias[col], 0.f);
                    float v1 = fmaxf(acc[mt][nt][2 * half + 1] + bias[col + 1], 0.f);
                    p = fmaf(v0, lnw[col], p);
                    p = fmaf(v1, lnw[col + 1], p);
                }
                p += __shfl_xor_sync(0xffffffffu, p, 1);
                p += __shfl_xor_sync(0xffffffffu, p, 2);
                if (t == 0) atomicAdd(&rs[wm * 64 + mt * 16 + g + 8 * half], p);
            }
        __syncthreads();
        if (tid < 128) {
            int grow = rbase + tid;
            if (grow < nrows) {
                float v = rs[tid];
                if (cbase == 0) v += lnb[0];
                atomicAdd(&g_gsum[batch[grow]], v);
            }
        }
        return;
    }

#pragma unroll
    for (int mt = 0; mt < 4; mt++) {
#pragma unroll
        for (int half = 0; half < 2; half++) {
            int row = rbase + wm * 64 + mt * 16 + g + 8 * half;
            if (row >= nrows) continue;
#pragma unroll
            for (int nt = 0; nt < 4; nt++) {
                int col = cbase + wn * 32 + nt * 8 + 2 * t;
                float v0 = acc[mt][nt][2 * half + 0] + bias[col];
                float v1 = acc[mt][nt][2 * half + 1] + bias[col + 1];
                if (act == 1) { v0 = fmaxf(v0, 0.f); v1 = fmaxf(v1, 0.f); }
                if (Y) {
                    float2 v; v.x = v0; v.y = v1;
                    *(float2*)(Y + (size_t)row * ncols + col) = v;
                }
                if (Yh) {
                    __nv_bfloat16 h0, l0, h1, l1;
                    split_bf16(v0, h0, l0);
                    split_bf16(v1, h1, l1);
                    __nv_bfloat162 hp; hp.x = h0; hp.y = h1;
                    __nv_bfloat162 lp; lp.x = l0; lp.y = l1;
                    *(__nv_bfloat162*)(Yh + (size_t)row * ncols + col) = hp;
                    *(__nv_bfloat162*)(Yl + (size_t)row * ncols + col) = lp;
                }
            }
        }
    }
}

// ---------------- fused message + LN + tanh + aggregate (warp per dst node) ----
__global__ void __launch_bounds__(256) k_msg(
    const float* __restrict__ yab, const float* __restrict__ Mw,
    const float* __restrict__ lnw, const float* __restrict__ lnb,
    const float* __restrict__ raw,
    __nv_bfloat16* __restrict__ aggh, __nv_bfloat16* __restrict__ aggl)
{
    int warp = (blockIdx.x * blockDim.x + threadIdx.x) >> 5;
    int lane = threadIdx.x & 31;
    if (warp >= NN) return;

    float Mreg[16][4];
#pragma unroll
    for (int k = 0; k < 16; k++)
#pragma unroll
        for (int j = 0; j < 4; j++) Mreg[k][j] = Mw[k * 128 + lane + 32 * j];

    float bj[4], lw[4], lb[4], accj[4];
#pragma unroll
    for (int j = 0; j < 4; j++) {
        bj[j] = yab[(size_t)warp * 256 + 128 + lane + 32 * j];
        lw[j] = lnw[lane + 32 * j];
        lb[j] = lnb[lane + 32 * j];
        accj[j] = 0.f;
    }

    int p0 = g_row[warp], p1 = g_row[warp + 1];
    if (p0 < p1) {
        int eid_n = g_peid[p0];
        int src_n = g_psrc[p0];
        float an[4];
        {
            const float* arn = yab + (size_t)src_n * 256;
#pragma unroll
            for (int j = 0; j < 4; j++) an[j] = arn[lane + 32 * j];
        }
        for (int p = p0; p < p1; p++) {
            const int eid = eid_n;
            float ca[4] = {an[0], an[1], an[2], an[3]};
            const float4* rp = (const float4*)(raw + (size_t)eid * 16);
            float4 r0 = rp[0], r1 = rp[1], r2 = rp[2], r3 = rp[3];
            if (p + 1 < p1) {
                src_n = g_psrc[p + 1];
                eid_n = g_peid[p + 1];
                const float* arn = yab + (size_t)src_n * 256;
#pragma unroll
                for (int j = 0; j < 4; j++) an[j] = arn[lane + 32 * j];
            }
            float rv[16] = {r0.x, r0.y, r0.z, r0.w, r1.x, r1.y, r1.z, r1.w,
                            r2.x, r2.y, r2.z, r2.w, r3.x, r3.y, r3.z, r3.w};
            float pre[4];
#pragma unroll
            for (int j = 0; j < 4; j++) {
                float c = bj[j] + ca[j];
#pragma unroll
                for (int k = 0; k < 16; k++) c = fmaf(rv[k], Mreg[k][j], c);
                pre[j] = c;
            }
            float s = pre[0] + pre[1] + pre[2] + pre[3];
            float q = pre[0] * pre[0];
            q = fmaf(pre[1], pre[1], q);
            q = fmaf(pre[2], pre[2], q);
            q = fmaf(pre[3], pre[3], q);
#pragma unroll
            for (int off = 16; off > 0; off >>= 1) {
                s += __shfl_xor_sync(0xffffffffu, s, off);
                q += __shfl_xor_sync(0xffffffffu, q, off);
            }
            float mean = s * (1.f / 128.f);
            float var = q * (1.f / 128.f) - mean * mean;
            float rstd = rsqrtf(var + 1e-5f);
#pragma unroll
            for (int j = 0; j < 4; j++) {
                float y = (pre[j] - mean) * rstd * lw[j] + lb[j];
                accj[j] += tanh_fast(y);
            }
        }
    }
#pragma unroll
    for (int j = 0; j < 4; j++) {
        __nv_bfloat16 h, l; split_bf16(accj[j], h, l);
        aggh[(size_t)warp * 128 + lane + 32 * j] = h;
        aggl[(size_t)warp * 128 + lane + 32 * j] = l;
    }
}

__global__ void k_final(float* __restrict__ out) {
    int g = blockIdx.x * blockDim.x + threadIdx.x;
    if (g < NG) out[g] = g_gsum[g] / fmaxf(g_gcnt[g], 1.0f);
}

// ---------------- host orchestration --------------------------------------------
extern "C" void kernel_launch(void* const* d_in, const int* in_sizes, int n_in,
                              void* d_out, int out_size)
{
    const float* x      = (const float*)d_in[0];
    const int*   ei     = (const int*)  d_in[1];
    const float* raw    = (const float*)d_in[2];
    const int*   batch  = (const int*)  d_in[3];
    const float* atomsW = (const float*)d_in[4];
    const float* atomsb = (const float*)d_in[5];
    const float* bondsW = (const float*)d_in[6];
    const float* bondsb = (const float*)d_in[7];
    const float* msgW   = (const float*)d_in[8];
    const float* msgb   = (const float*)d_in[9];
    const float* msglnw = (const float*)d_in[10];
    const float* msglnb = (const float*)d_in[11];
    const float* updW   = (const float*)d_in[12];
    const float* updb   = (const float*)d_in[13];
    const float* updlnw = (const float*)d_in[14];
    const float* updlnb = (const float*)d_in[15];
    const float* fc1W   = (const float*)d_in[16];
    const float* fc1b   = (const float*)d_in[17];
    const float* fc2w   = (const float*)d_in[18];
    const float* fc2b   = (const float*)d_in[19];
    float* out = (float*)d_out;

    const int* src = ei;
    const int* dst = ei + NE;

    cudaFuncSetAttribute(k_mgemm, cudaFuncAttributeMaxDynamicSharedMemorySize, GEMM_SMEM);

    float *p_yab, *p_bab, *p_M, *p_ub0;
    cudaGetSymbolAddress((void**)&p_yab, g_yab);
    cudaGetSymbolAddress((void**)&p_bab, g_bab);
    cudaGetSymbolAddress((void**)&p_M,   g_M);
    cudaGetSymbolAddress((void**)&p_ub0, g_ub0);
    __nv_bfloat16 *p_xh, *p_xl, *p_hh, *p_hl, *p_aggh, *p_aggl;
    __nv_bfloat16 *p_wabh, *p_wabl, *p_updh, *p_updl, *p_fc1h, *p_fc1l;
    __nv_bfloat16 *p_w0h, *p_w0l, *p_u0h, *p_u0l;
    cudaGetSymbolAddress((void**)&p_xh,   g_xh);
    cudaGetSymbolAddress((void**)&p_xl,   g_xl);
    cudaGetSymbolAddress((void**)&p_hh,   g_hh);
    cudaGetSymbolAddress((void**)&p_hl,   g_hl);
    cudaGetSymbolAddress((void**)&p_aggh, g_aggh);
    cudaGetSymbolAddress((void**)&p_aggl, g_aggl);
    cudaGetSymbolAddress((void**)&p_wabh, g_wabt_h);
    cudaGetSymbolAddress((void**)&p_wabl, g_wabt_l);
    cudaGetSymbolAddress((void**)&p_updh, g_updt_h);
    cudaGetSymbolAddress((void**)&p_updl, g_updt_l);
    cudaGetSymbolAddress((void**)&p_fc1h, g_fc1t_h);
    cudaGetSymbolAddress((void**)&p_fc1l, g_fc1t_l);
    cudaGetSymbolAddress((void**)&p_w0h,  g_w0t_h);
    cudaGetSymbolAddress((void**)&p_w0l,  g_w0t_l);
    cudaGetSymbolAddress((void**)&p_u0h,  g_u0t_h);
    cudaGetSymbolAddress((void**)&p_u0l,  g_u0t_l);

    const int SCAN_BLK = (NN + 255) / 256;   // 157
    const int RB = (NN + 127) / 128;
    dim3 g128(RB, 1), g256(RB, 2);

    // 0: packing + folding + init (embed folded into layer-0 weights)
    k_pack_all<<<(PACK_TOTAL + 255) / 256, 256>>>(msgW, bondsW, bondsb, msgb,
                                                  atomsW, atomsb, updW, updb, fc1W, x, batch);
    // 1-2: CSR degree + scan phase 1
    k_deg<<<(NE + 255) / 256, 256>>>(dst);
    k_scan1<<<SCAN_BLK, 256>>>();

    // 3 (ncu capture target): wab0 GEMM  A|B = x @ W0ab (K=64)
    k_mgemm<<<g256, 256, GEMM_SMEM>>>(p_xh, p_xl, 64,
                                      (const __nv_bfloat16*)0, (const __nv_bfloat16*)0, 0,
                                      p_w0h, p_w0l, p_bab, p_yab,
                                      (__nv_bfloat16*)0, (__nv_bfloat16*)0,
                                      (const float*)0, (const float*)0, (const int*)0,
                                      NN, 256, 0);

    // 4-6: finish CSR
    k_scan2<<<1, 256>>>(SCAN_BLK);
    k_scan3<<<SCAN_BLK, 256>>>();
    k_fill<<<(NE + 255) / 256, 256>>>(src, dst);

    // 7: msg0, 8: upd0 (K=192: agg | x-folded)
    k_msg<<<(NN * 32 + 255) / 256, 256>>>(p_yab, p_M, msglnw, msglnb, raw, p_aggh, p_aggl);
    k_mgemm<<<g128, 256, GEMM_SMEM>>>(p_aggh, p_aggl, 128, p_xh, p_xl, 64,
                                      p_u0h, p_u0l, p_ub0, (float*)0, p_hh, p_hl,
                                      updlnw, updlnb, (const int*)0, NN, 128, 2);

    for (int l = 1; l < 3; l++) {
        k_mgemm<<<g256, 256, GEMM_SMEM>>>(p_hh, p_hl, 128,
                                          (const __nv_bfloat16*)0, (const __nv_bfloat16*)0, 0,
                                          p_wabh + (size_t)l * 256 * 128, p_wabl + (size_t)l * 256 * 128,
                                          p_bab + l * 256, p_yab,
                                          (__nv_bfloat16*)0, (__nv_bfloat16*)0,
                                          (const float*)0, (const float*)0, (const int*)0,
                                          NN, 256, 0);
        k_msg<<<(NN * 32 + 255) / 256, 256>>>(p_yab, p_M + l * 16 * 128,
                                              msglnw + l * 128, msglnb + l * 128,
                                              raw, p_aggh, p_aggl);
        k_mgemm<<<g128, 256, GEMM_SMEM>>>(p_aggh, p_aggl, 128, p_hh, p_hl, 128,
                                          p_updh + (size_t)l * 128 * 256, p_updl + (size_t)l * 128 * 256,
                                          updb + l * 128, (float*)0, p_hh, p_hl,
                                          updlnw + l * 128, updlnb + l * 128, (const int*)0,
                                          NN, 128, 2);
    }

    // readout: fused fc1 + relu + fc2 dot + pooling
    k_mgemm<<<g256, 256, GEMM_SMEM>>>(p_hh, p_hl, 128,
                                      (const __nv_bfloat16*)0, (const __nv_bfloat16*)0, 0,
                                      p_fc1h, p_fc1l, fc1b, (float*)0,
                                      (__nv_bfloat16*)0, (__nv_bfloat16*)0,
                                      fc2w, fc2b, batch,
                                      NN, 256, 3);
    k_final<<<(NG + 255) / 256, 256>>>(out);
}

// round 12
// speedup vs baseline: 1.4992x; 1.0506x over previous
#include <cuda_runtime.h>
#include <cuda_bf16.h>
#include <math.h>
#include <stdint.h>

#define NN 40000
#define NE 640000
#define NG 1024

// ---------------- scratch (device globals; no allocations allowed) -------------
__device__ float g_yab [NN * 256];
__device__ float g_bab [3 * 256];
__device__ float g_M   [3 * 16 * 128];
__device__ float g_ub0 [128];

__device__ __nv_bfloat16 g_xh  [NN * 64],  g_xl  [NN * 64];
__device__ __nv_bfloat16 g_hh  [NN * 128], g_hl  [NN * 128];
__device__ __nv_bfloat16 g_aggh[NN * 128], g_aggl[NN * 128];
__device__ __nv_bfloat16 g_wabt_h[3 * 256 * 128], g_wabt_l[3 * 256 * 128];
__device__ __nv_bfloat16 g_updt_h[3 * 128 * 256], g_updt_l[3 * 128 * 256];
__device__ __nv_bfloat16 g_fc1t_h[256 * 128],     g_fc1t_l[256 * 128];
__device__ __nv_bfloat16 g_w0t_h[256 * 64],       g_w0t_l[256 * 64];
__device__ __nv_bfloat16 g_u0t_h[128 * 192],      g_u0t_l[128 * 192];

__device__ int   g_deg [NN];
__device__ int   g_row [NN + 1];
__device__ int   g_cur [NN];
__device__ int   g_bsum[160];
__device__ int   g_boff[160];
__device__ int   g_psrc[NE];
__device__ int   g_peid[NE];
__device__ float g_gsum[NG];
__device__ float g_gcnt[NG];

// ---------------- helpers --------------------------------------------------------
__device__ __forceinline__ void split_bf16(float v, __nv_bfloat16& h, __nv_bfloat16& l) {
    h = __float2bfloat16(v);
    l = __float2bfloat16(v - __bfloat162float(h));
}
__device__ __forceinline__ float tanh_fast(float x) {
    float y;
    asm("tanh.approx.f32 %0, %1;" : "=f"(y) : "f"(x));
    return y;
}

// ---------------- merged packing + weight folding + init kernel ------------------
#define PACK_TOTAL 2878016
__global__ void k_pack_all(const float* __restrict__ msgW, const float* __restrict__ bondsW,
                           const float* __restrict__ bondsb, const float* __restrict__ msgb,
                           const float* __restrict__ atomsW, const float* __restrict__ atomsb,
                           const float* __restrict__ updW, const float* __restrict__ updb,
                           const float* __restrict__ fc1W, const float* __restrict__ x,
                           const int* __restrict__ batch)
{
    int idx = blockIdx.x * blockDim.x + threadIdx.x;
    if (idx < 98304) {
        int l = idx / 32768, r = idx % 32768;
        int n = r / 128, k = r % 128;
        const float* Wl = msgW + (size_t)l * 384 * 128;
        float v = (n < 128) ? Wl[k * 128 + n] : Wl[(128 + k) * 128 + (n - 128)];
        __nv_bfloat16 h, lo; split_bf16(v, h, lo);
        g_wabt_h[idx] = h; g_wabt_l[idx] = lo;
    } else if (idx < 104832) {
        int i2 = idx - 98304;
        if (i2 < 3 * 16 * 128) {
            int l = i2 / 2048, k = (i2 / 128) & 15, d = i2 & 127;
            const float* W3 = msgW + (size_t)l * 384 * 128 + 256 * 128;
            float s = 0.f;
            for (int j = 0; j < 128; j++) s += bondsW[k * 128 + j] * W3[j * 128 + d];
            g_M[i2] = s;
        } else {
            int i3 = i2 - 3 * 16 * 128;
            int l = i3 / 128, d = i3 & 127;
            const float* W3 = msgW + (size_t)l * 384 * 128 + 256 * 128;
            float s = msgb[l * 128 + d];
            for (int j = 0; j < 128; j++) s += bondsb[j] * W3[j * 128 + d];
            float sB = 0.f;
            if (l == 0) {
                const float* W0 = msgW;
                float sA = 0.f;
                for (int j = 0; j < 128; j++) {
                    sA += atomsb[j] * W0[j * 128 + d];
                    sB += atomsb[j] * W0[(128 + j) * 128 + d];
                }
                s += sA;
            }
            g_bab[l * 256 + d] = s;
            g_bab[l * 256 + 128 + d] = sB;
        }
    } else if (idx < 203136) {
        int i = idx - 104832;
        int l = i / 32768, r = i % 32768;
        int n = r / 256, k = r % 256;
        const float* Wl = updW + (size_t)l * 256 * 128;
        __nv_bfloat16 h, lo; split_bf16(Wl[k * 128 + n], h, lo);
        g_updt_h[i] = h; g_updt_l[i] = lo;
    } else if (idx < 235904) {
        int i = idx - 203136;
        int n = i / 128, k = i % 128;
        __nv_bfloat16 h, l; split_bf16(fc1W[k * 256 + n], h, l);
        g_fc1t_h[i] = h; g_fc1t_l[i] = l;
    } else if (idx < 2795904) {
        int i = idx - 235904;
        __nv_bfloat16 h, l; split_bf16(x[i], h, l);
        g_xh[i] = h; g_xl[i] = l;
    } else if (idx < 2812288) {
        int i = idx - 2795904;               // wab0 fold
        int n = i / 64, m = i % 64;
        const float* W0 = msgW;
        float s = 0.f;
        if (n < 128) {
            for (int j = 0; j < 128; j++) s += atomsW[m * 128 + j] * W0[j * 128 + n];
        } else {
            for (int j = 0; j < 128; j++) s += atomsW[m * 128 + j] * W0[(128 + j) * 128 + (n - 128)];
        }
        __nv_bfloat16 h, lo; split_bf16(s, h, lo);
        g_w0t_h[i] = h; g_w0t_l[i] = lo;
    } else if (idx < 2828672) {
        int i = idx - 2812288;               // upd0 copy
        int n = i / 128, k = i % 128;
        __nv_bfloat16 h, lo; split_bf16(updW[k * 128 + n], h, lo);
        g_u0t_h[n * 192 + k] = h; g_u0t_l[n * 192 + k] = lo;
    } else if (idx < 2836864) {
        int i = idx - 2828672;               // upd0 fold
        int n = i / 64, m = i % 64;
        float s = 0.f;
        for (int j = 0; j < 128; j++) s += atomsW[m * 128 + j] * updW[(128 + j) * 128 + n];
        __nv_bfloat16 h, lo; split_bf16(s, h, lo);
        g_u0t_h[n * 192 + 128 + m] = h; g_u0t_l[n * 192 + 128 + m] = lo;
    } else if (idx < 2836992) {
        int n = idx - 2836864;
        float s = updb[n];
        for (int j = 0; j < 128; j++) s += atomsb[j] * updW[(128 + j) * 128 + n];
        g_ub0[n] = s;
    } else if (idx < 2876992) {
        g_deg[idx - 2836992] = 0;
    } else if (idx < PACK_TOTAL) {
        int i = idx - 2876992;
        g_gsum[i] = 0.f;
        int lo = 0, hi = NN;
        while (lo < hi) { int m = (lo + hi) >> 1; if (batch[m] < i) lo = m + 1; else hi = m; }
        int lo2 = lo, hi2 = NN;
        while (lo2 < hi2) { int m = (lo2 + hi2) >> 1; if (batch[m] < i + 1) lo2 = m + 1; else hi2 = m; }
        g_gcnt[i] = (float)(lo2 - lo);
    }
}

__global__ void k_deg(const int* __restrict__ dst) {
    int e = blockIdx.x * blockDim.x + threadIdx.x;
    if (e < NE) atomicAdd(&g_deg[dst[e]], 1);
}

// ---------------- parallel 3-phase exclusive scan of degrees ---------------------
__global__ void k_scan1() {
    __shared__ int ws[8];
    int t = threadIdx.x, lane = t & 31, w = t >> 5;
    int i = blockIdx.x * 256 + t;
    int d = (i < NN) ? g_deg[i] : 0;
    int s = __reduce_add_sync(0xffffffffu, d);
    if (lane == 0) ws[w] = s;
    __syncthreads();
    if (t == 0) {
        int tot = 0;
        for (int j = 0; j < 8; j++) tot += ws[j];
        g_bsum[blockIdx.x] = tot;
    }
}
__global__ void k_scan2(int nblk) {
    __shared__ int wsum[8];
    int t = threadIdx.x, lane = t & 31, w = t >> 5;
    int v = (t < nblk) ? g_bsum[t] : 0;
    int x = v;
#pragma unroll
    for (int off = 1; off < 32; off <<= 1) {
        int y = __shfl_up_sync(0xffffffffu, x, off);
        if (lane >= off) x += y;
    }
    if (lane == 31) wsum[w] = x;
    __syncthreads();
    if (t == 0) {
        int r = 0;
        for (int j = 0; j < 8; j++) { int tmp = wsum[j]; wsum[j] = r; r += tmp; }
        g_row[NN] = NE;
    }
    __syncthreads();
    if (t < nblk) g_boff[t] = x - v + wsum[w];
}
__global__ void k_scan3() {
    __shared__ int wsum[8];
    int t = threadIdx.x, lane = t & 31, w = t >> 5;
    int i = blockIdx.x * 256 + t;
    int d = (i < NN) ? g_deg[i] : 0;
    int x = d;
#pragma unroll
    for (int off = 1; off < 32; off <<= 1) {
        int y = __shfl_up_sync(0xffffffffu, x, off);
        if (lane >= off) x += y;
    }
    if (lane == 31) wsum[w] = x;
    __syncthreads();
    if (t == 0) {
        int r = 0;
        for (int j = 0; j < 8; j++) { int tmp = wsum[j]; wsum[j] = r; r += tmp; }
    }
    __syncthreads();
    int excl = x - d + wsum[w] + g_boff[blockIdx.x];
    if (i < NN) { g_row[i] = excl; g_cur[i] = excl; }
}

__global__ void k_fill(const int* __restrict__ src, const int* __restrict__ dst) {
    int e = blockIdx.x * blockDim.x + threadIdx.x;
    if (e < NE) {
        int d = dst[e];
        int p = atomicAdd(&g_cur[d], 1);
        g_psrc[p] = src[e];
        g_peid[p] = e;
    }
}

// ================= bf16x3 mma.sync GEMM with ldmatrix + cp.async =================
// act: 0 = none, 1 = relu, 2 = fused LN+tanh (ncols==128, grid.y==1),
//      3 = fused relu + fc2-dot + graph pooling
#define MMA_BF16(d, a, b0, b1) \
    asm volatile("mma.sync.aligned.m16n8k16.row.col.f32.bf16.bf16.f32 " \
        "{%0,%1,%2,%3}, {%4,%5,%6,%7}, {%8,%9}, {%0,%1,%2,%3};" \
        : "+f"(d[0]), "+f"(d[1]), "+f"(d[2]), "+f"(d[3]) \
        : "r"(a[0]), "r"(a[1]), "r"(a[2]), "r"(a[3]), "r"(b0), "r"(b1));

#define LDSM_X4(r, a) \
    asm volatile("ldmatrix.sync.aligned.m8n8.x4.shared.b16 {%0,%1,%2,%3}, [%4];" \
        : "=r"((r)[0]), "=r"((r)[1]), "=r"((r)[2]), "=r"((r)[3]) : "r"(a))

#define CP_ASYNC(sa, ga, sz) \
    asm volatile("cp.async.ca.shared.global [%0], [%1], 16, %2;" :: "r"(sa), "l"(ga), "r"(sz))
#define CP_COMMIT() asm volatile("cp.async.commit_group;" ::: "memory")
#define CP_WAIT(n)  asm volatile("cp.async.wait_group %0;" :: "n"(n) : "memory")

#define FMA_F32X2(d, a, b) \
    asm("fma.rn.f32x2 %0, %1, %2, %0;" : "+l"(d) : "l"(a), "l"(b))
#define UNPACK_F32X2(lo, hi, v) \
    asm("mov.b64 {%0, %1}, %2;" : "=f"(lo), "=f"(hi) : "l"(v))
#define PACK_F32X2(d, lo, hi) \
    asm("mov.b64 %0, {%1, %2};" : "=l"(d) : "f"(lo), "f"(hi))

__device__ __forceinline__ uint32_t smem_u32(const void* p) {
    uint32_t a;
    asm("{ .reg .u64 t; cvta.to.shared.u64 t, %1; cvt.u32.u64 %0, t; }" : "=r"(a) : "l"(p));
    return a;
}

#define GEMM_SMEM (2 * 40960)

__global__ void __launch_bounds__(256) k_mgemm(
    const __nv_bfloat16* __restrict__ X1h, const __nv_bfloat16* __restrict__ X1l, int K1,
    const __nv_bfloat16* __restrict__ X2h, const __nv_bfloat16* __restrict__ X2l, int K2,
    const __nv_bfloat16* __restrict__ Wh,  const __nv_bfloat16* __restrict__ Wl,
    const float* __restrict__ bias, float* __restrict__ Y,
    __nv_bfloat16* __restrict__ Yh, __nv_bfloat16* __restrict__ Yl,
    const float* __restrict__ lnw, const float* __restrict__ lnb,
    const int* __restrict__ batch,
    int nrows, int ncols, int act)
{
    extern __shared__ char smem[];
    const uint32_t sb = smem_u32(smem);
    const int tid = threadIdx.x;
    const int wid = tid >> 5, lane = tid & 31;
    const int wm = wid & 1, wn = wid >> 1;
    const int g = lane >> 2, t = lane & 3;
    const int rbase = blockIdx.x * 128, cbase = blockIdx.y * 128;
    const int Ktot = K1 + K2;
    const int nch = Ktot >> 5;

    const int srow = tid >> 1;
    const int sseg = (tid & 1) * 2;

    float acc[4][4][4];
#pragma unroll
    for (int i = 0; i < 4; i++)
#pragma unroll
        for (int j = 0; j < 4; j++)
#pragma unroll
            for (int q = 0; q < 4; q++) acc[i][j][q] = 0.f;

    const int quad = lane >> 3, li = lane & 7;
    const int a_row = (quad & 1) * 8 + li;
    const int a_col = (quad >> 1) * 8;
    const int b_row = (quad >> 1) * 8 + li;
    const int b_col = (quad & 1) * 8;

    auto stage = [&](int ch, int buf) {
        const int kk = ch << 5;
        const uint32_t base = sb + buf * 40960;
        {
            const __nv_bfloat16 *Xh, *Xl; int xs, kx;
            if (kk < K1) { Xh = X1h; Xl = X1l; xs = K1; kx = kk; }
            else         { Xh = X2h; Xl = X2l; xs = K2; kx = kk - K1; }
            int gr = rbase + srow;
            uint32_t sz = (gr < nrows) ? 16u : 0u;
            if (gr >= nrows) gr = nrows - 1;
            const __nv_bfloat16* ph = Xh + (size_t)gr * xs + kx;
            const __nv_bfloat16* pl = Xl + (size_t)gr * xs + kx;
#pragma unroll
            for (int q = 0; q < 2; q++) {
                const int seg = sseg + q;
                const uint32_t so = base + srow * 80 + seg * 16;
                CP_ASYNC(so,         ph + seg * 8, sz);
                CP_ASYNC(so + 10240, pl + seg * 8, sz);
            }
        }
        {
            const int gn = cbase + srow;
            const __nv_bfloat16* ph = Wh + (size_t)gn * Ktot + kk;
            const __nv_bfloat16* pl = Wl + (size_t)gn * Ktot + kk;
#pragma unroll
            for (int q = 0; q < 2; q++) {
                const int seg = sseg + q;
                const uint32_t so = base + 20480 + srow * 80 + seg * 16;
                CP_ASYNC(so,         ph + seg * 8, 16u);
                CP_ASYNC(so + 10240, pl + seg * 8, 16u);
            }
        }
        CP_COMMIT();
    };

    stage(0, 0);
    for (int ch = 0; ch < nch; ch++) {
        const int buf = ch & 1;
        const bool more = (ch + 1 < nch);
        if (more) stage(ch + 1, buf ^ 1);
        if (more) { CP_WAIT(1); } else { CP_WAIT(0); }
        __syncthreads();

        const uint32_t base = sb + buf * 40960;
        const uint32_t aah = base + (wm * 64 + a_row) * 80 + a_col * 2;
        const uint32_t bbh = base + 20480 + (wn * 32 + b_row) * 80 + b_col * 2;
#pragma unroll
        for (int s = 0; s < 2; s++) {
            const uint32_t ks2 = s * 32;
            uint32_t ah[4][4], al[4][4];
#pragma unroll
            for (int mt = 0; mt < 4; mt++) {
                LDSM_X4(ah[mt], aah + mt * 1280 + ks2);
                LDSM_X4(al[mt], aah + 10240 + mt * 1280 + ks2);
            }
            uint32_t bh[4][2], bl[4][2];
#pragma unroll
            for (int pr = 0; pr < 2; pr++) {
                uint32_t tmp[4];
                LDSM_X4(tmp, bbh + pr * 1280 + ks2);
                bh[2 * pr][0] = tmp[0]; bh[2 * pr][1] = tmp[1];
                bh[2 * pr + 1][0] = tmp[2]; bh[2 * pr + 1][1] = tmp[3];
                LDSM_X4(tmp, bbh + 10240 + pr * 1280 + ks2);
                bl[2 * pr][0] = tmp[0]; bl[2 * pr][1] = tmp[1];
                bl[2 * pr + 1][0] = tmp[2]; bl[2 * pr + 1][1] = tmp[3];
            }
#pragma unroll
            for (int nt = 0; nt < 4; nt++)
#pragma unroll
                for (int mt = 0; mt < 4; mt++) {
                    MMA_BF16(acc[mt][nt], ah[mt], bh[nt][0], bh[nt][1]);
                    MMA_BF16(acc[mt][nt], ah[mt], bl[nt][0], bl[nt][1]);
                    MMA_BF16(acc[mt][nt], al[mt], bh[nt][0], bh[nt][1]);
                }
        }
        __syncthreads();
    }

    if (act == 2) {
        float* tb = (float*)smem;
#pragma unroll
        for (int mt = 0; mt < 4; mt++)
#pragma unroll
            for (int half = 0; half < 2; half++) {
                int row = wm * 64 + mt * 16 + g + 8 * half;
#pragma unroll
                for (int nt = 0; nt < 4; nt++) {
                    int col = wn * 32 + nt * 8 + 2 * t;
                    tb[row * 132 + col]     = acc[mt][nt][2 * half + 0] + bias[col];
                    tb[row * 132 + col + 1] = acc[mt][nt][2 * half + 1] + bias[col + 1];
                }
            }
        __syncthreads();
        float lw[4], lb[4];
#pragma unroll
        for (int j = 0; j < 4; j++) { lw[j] = lnw[lane + 32 * j]; lb[j] = lnb[lane + 32 * j]; }
#pragma unroll 1
        for (int it = 0; it < 16; it++) {
            int row = wid * 16 + it;
            int grow = rbase + row;
            float v[4];
#pragma unroll
            for (int j = 0; j < 4; j++) v[j] = tb[row * 132 + lane + 32 * j];
            float s = v[0] + v[1] + v[2] + v[3];
            float q = v[0] * v[0];
            q = fmaf(v[1], v[1], q);
            q = fmaf(v[2], v[2], q);
            q = fmaf(v[3], v[3], q);
#pragma unroll
            for (int off = 16; off > 0; off >>= 1) {
                s += __shfl_xor_sync(0xffffffffu, s, off);
                q += __shfl_xor_sync(0xffffffffu, q, off);
            }
            float mean = s * (1.f / 128.f);
            float var = q * (1.f / 128.f) - mean * mean;
            float rstd = rsqrtf(var + 1e-5f);
            if (grow < nrows) {
#pragma unroll
                for (int j = 0; j < 4; j++) {
                    float y = (v[j] - mean) * rstd * lw[j] + lb[j];
                    __nv_bfloat16 h, l; split_bf16(tanh_fast(y), h, l);
                    Yh[(size_t)grow * 128 + lane + 32 * j] = h;
                    Yl[(size_t)grow * 128 + lane + 32 * j] = l;
                }
            }
        }
        return;
    }

    if (act == 3) {
        float* rs = (float*)smem;
        if (tid < 128) rs[tid] = 0.f;
        __syncthreads();
#pragma unroll
        for (int mt = 0; mt < 4; mt++)
#pragma unroll
            for (int half = 0; half < 2; half++) {
                float p = 0.f;
#pragma unroll
                for (int nt = 0; nt < 4; nt++) {
                    int col = cbase + wn * 32 + nt * 8 + 2 * t;
                    float v0 = fmaxf(acc[mt][nt][2 * half + 0] + bias[col], 0.f);
                    float v1 = fmaxf(acc[mt][nt][2 * half + 1] + bias[col + 1], 0.f);
                    p = fmaf(v0, lnw[col], p);
                    p = fmaf(v1, lnw[col + 1], p);
                }
                p += __shfl_xor_sync(0xffffffffu, p, 1);
                p += __shfl_xor_sync(0xffffffffu, p, 2);
                if (t == 0) atomicAdd(&rs[wm * 64 + mt * 16 + g + 8 * half], p);
            }
        __syncthreads();
        if (tid < 128) {
            int grow = rbase + tid;
            if (grow < nrows) {
                float v = rs[tid];
                if (cbase == 0) v += lnb[0];
                atomicAdd(&g_gsum[batch[grow]], v);
            }
        }
        return;
    }

#pragma unroll
    for (int mt = 0; mt < 4; mt++) {
#pragma unroll
        for (int half = 0; half < 2; half++) {
            int row = rbase + wm * 64 + mt * 16 + g + 8 * half;
            if (row >= nrows) continue;
#pragma unroll
            for (int nt = 0; nt < 4; nt++) {
                int col = cbase + wn * 32 + nt * 8 + 2 * t;
                float v0 = acc[mt][nt][2 * half + 0] + bias[col];
                float v1 = acc[mt][nt][2 * half + 1] + bias[col + 1];
                if (act == 1) { v0 = fmaxf(v0, 0.f); v1 = fmaxf(v1, 0.f); }
                if (Y) {
                    float2 v; v.x = v0; v.y = v1;
                    *(float2*)(Y + (size_t)row * ncols + col) = v;
                }
                if (Yh) {
                    __nv_bfloat16 h0, l0, h1, l1;
                    split_bf16(v0, h0, l0);
                    split_bf16(v1, h1, l1);
                    __nv_bfloat162 hp; hp.x = h0; hp.y = h1;
                    __nv_bfloat162 lp; lp.x = l0; lp.y = l1;
                    *(__nv_bfloat162*)(Yh + (size_t)row * ncols + col) = hp;
                    *(__nv_bfloat162*)(Yl + (size_t)row * ncols + col) = lp;
                }
            }
        }
    }
}

// ---------------- fused message + LN + tanh + aggregate (warp per dst node) ----
// Inner product raw[16] @ M uses packed fma.rn.f32x2: raw pairs load pre-packed
// from memory (adjacent floats), M pre-packed k-pairwise into 64 regs.
__global__ void __launch_bounds__(256) k_msg(
    const float* __restrict__ yab, const float* __restrict__ Mw,
    const float* __restrict__ lnw, const float* __restrict__ lnb,
    const float* __restrict__ raw,
    __nv_bfloat16* __restrict__ aggh, __nv_bfloat16* __restrict__ aggl)
{
    int warp = (blockIdx.x * blockDim.x + threadIdx.x) >> 5;
    int lane = threadIdx.x & 31;
    if (warp >= NN) return;

    // M packed: Mp[k2][j] = (M[2k2][ch], M[2k2+1][ch]), ch = lane + 32j
    unsigned long long Mp[8][4];
#pragma unroll
    for (int k2 = 0; k2 < 8; k2++)
#pragma unroll
        for (int j = 0; j < 4; j++) {
            float m0 = Mw[(2 * k2) * 128 + lane + 32 * j];
            float m1 = Mw[(2 * k2 + 1) * 128 + lane + 32 * j];
            PACK_F32X2(Mp[k2][j], m0, m1);
        }

    float bj[4], lw[4], lb[4], accj[4];
#pragma unroll
    for (int j = 0; j < 4; j++) {
        bj[j] = yab[(size_t)warp * 256 + 128 + lane + 32 * j];
        lw[j] = lnw[lane + 32 * j];
        lb[j] = lnb[lane + 32 * j];
        accj[j] = 0.f;
    }

    int p0 = g_row[warp], p1 = g_row[warp + 1];
    if (p0 < p1) {
        int eid_n = g_peid[p0];
        int src_n = g_psrc[p0];
        float an[4];
        {
            const float* arn = yab + (size_t)src_n * 256;
#pragma unroll
            for (int j = 0; j < 4; j++) an[j] = arn[lane + 32 * j];
        }
        for (int p = p0; p < p1; p++) {
            const int eid = eid_n;
            float ca[4] = {an[0], an[1], an[2], an[3]};
            // raw pairs arrive pre-packed as f32x2 (adjacent floats)
            const ulonglong2* rp = (const ulonglong2*)(raw + (size_t)eid * 16);
            ulonglong2 u0 = rp[0], u1 = rp[1], u2 = rp[2], u3 = rp[3];
            if (p + 1 < p1) {
                src_n = g_psrc[p + 1];
                eid_n = g_peid[p + 1];
                const float* arn = yab + (size_t)src_n * 256;
#pragma unroll
                for (int j = 0; j < 4; j++) an[j] = arn[lane + 32 * j];
            }
            unsigned long long rvp[8] = {u0.x, u0.y, u1.x, u1.y, u2.x, u2.y, u3.x, u3.y};
            unsigned long long accp[4] = {0ull, 0ull, 0ull, 0ull};
#pragma unroll
            for (int k2 = 0; k2 < 8; k2++)
#pragma unroll
                for (int j = 0; j < 4; j++)
                    FMA_F32X2(accp[j], rvp[k2], Mp[k2][j]);
            float pre[4];
#pragma unroll
            for (int j = 0; j < 4; j++) {
                float e, o;
                UNPACK_F32X2(e, o, accp[j]);
                pre[j] = (bj[j] + ca[j]) + (e + o);
            }
            float s = pre[0] + pre[1] + pre[2] + pre[3];
            float q = pre[0] * pre[0];
            q = fmaf(pre[1], pre[1], q);
            q = fmaf(pre[2], pre[2], q);
            q = fmaf(pre[3], pre[3], q);
#pragma unroll
            for (int off = 16; off > 0; off >>= 1) {
                s += __shfl_xor_sync(0xffffffffu, s, off);
                q += __shfl_xor_sync(0xffffffffu, q, off);
            }
            float mean = s * (1.f / 128.f);
            float var = q * (1.f / 128.f) - mean * mean;
            float rstd = rsqrtf(var + 1e-5f);
#pragma unroll
            for (int j = 0; j < 4; j++) {
                float y = (pre[j] - mean) * rstd * lw[j] + lb[j];
                accj[j] += tanh_fast(y);
            }
        }
    }
#pragma unroll
    for (int j = 0; j < 4; j++) {
        __nv_bfloat16 h, l; split_bf16(accj[j], h, l);
        aggh[(size_t)warp * 128 + lane + 32 * j] = h;
        aggl[(size_t)warp * 128 + lane + 32 * j] = l;
    }
}

__global__ void k_final(float* __restrict__ out) {
    int g = blockIdx.x * blockDim.x + threadIdx.x;
    if (g < NG) out[g] = g_gsum[g] / fmaxf(g_gcnt[g], 1.0f);
}

// ---------------- host orchestration --------------------------------------------
extern "C" void kernel_launch(void* const* d_in, const int* in_sizes, int n_in,
                              void* d_out, int out_size)
{
    const float* x      = (const float*)d_in[0];
    const int*   ei     = (const int*)  d_in[1];
    const float* raw    = (const float*)d_in[2];
    const int*   batch  = (const int*)  d_in[3];
    const float* atomsW = (const float*)d_in[4];
    const float* atomsb = (const float*)d_in[5];
    const float* bondsW = (const float*)d_in[6];
    const float* bondsb = (const float*)d_in[7];
    const float* msgW   = (const float*)d_in[8];
    const float* msgb   = (const float*)d_in[9];
    const float* msglnw = (const float*)d_in[10];
    const float* msglnb = (const float*)d_in[11];
    const float* updW   = (const float*)d_in[12];
    const float* updb   = (const float*)d_in[13];
    const float* updlnw = (const float*)d_in[14];
    const float* updlnb = (const float*)d_in[15];
    const float* fc1W   = (const float*)d_in[16];
    const float* fc1b   = (const float*)d_in[17];
    const float* fc2w   = (const float*)d_in[18];
    const float* fc2b   = (const float*)d_in[19];
    float* out = (float*)d_out;

    const int* src = ei;
    const int* dst = ei + NE;

    cudaFuncSetAttribute(k_mgemm, cudaFuncAttributeMaxDynamicSharedMemorySize, GEMM_SMEM);

    float *p_yab, *p_bab, *p_M, *p_ub0;
    cudaGetSymbolAddress((void**)&p_yab, g_yab);
    cudaGetSymbolAddress((void**)&p_bab, g_bab);
    cudaGetSymbolAddress((void**)&p_M,   g_M);
    cudaGetSymbolAddress((void**)&p_ub0, g_ub0);
    __nv_bfloat16 *p_xh, *p_xl, *p_hh, *p_hl, *p_aggh, *p_aggl;
    __nv_bfloat16 *p_wabh, *p_wabl, *p_updh, *p_updl, *p_fc1h, *p_fc1l;
    __nv_bfloat16 *p_w0h, *p_w0l, *p_u0h, *p_u0l;
    cudaGetSymbolAddress((void**)&p_xh,   g_xh);
    cudaGetSymbolAddress((void**)&p_xl,   g_xl);
    cudaGetSymbolAddress((void**)&p_hh,   g_hh);
    cudaGetSymbolAddress((void**)&p_hl,   g_hl);
    cudaGetSymbolAddress((void**)&p_aggh, g_aggh);
    cudaGetSymbolAddress((void**)&p_aggl, g_aggl);
    cudaGetSymbolAddress((void**)&p_wabh, g_wabt_h);
    cudaGetSymbolAddress((void**)&p_wabl, g_wabt_l);
    cudaGetSymbolAddress((void**)&p_updh, g_updt_h);
    cudaGetSymbolAddress((void**)&p_updl, g_updt_l);
    cudaGetSymbolAddress((void**)&p_fc1h, g_fc1t_h);
    cudaGetSymbolAddress((void**)&p_fc1l, g_fc1t_l);
    cudaGetSymbolAddress((void**)&p_w0h,  g_w0t_h);
    cudaGetSymbolAddress((void**)&p_w0l,  g_w0t_l);
    cudaGetSymbolAddress((void**)&p_u0h,  g_u0t_h);
    cudaGetSymbolAddress((void**)&p_u0l,  g_u0t_l);

    const int SCAN_BLK = (NN + 255) / 256;   // 157
    const int RB = (NN + 127) / 128;
    dim3 g128(RB, 1), g256(RB, 2);

    // 0: packing + folding + init
    k_pack_all<<<(PACK_TOTAL + 255) / 256, 256>>>(msgW, bondsW, bondsb, msgb,
                                                  atomsW, atomsb, updW, updb, fc1W, x, batch);
    // 1-2: CSR degree + scan phase 1
    k_deg<<<(NE + 255) / 256, 256>>>(dst);
    k_scan1<<<SCAN_BLK, 256>>>();

    // 3 (ncu capture target): wab0 GEMM  A|B = x @ W0ab (K=64)
    k_mgemm<<<g256, 256, GEMM_SMEM>>>(p_xh, p_xl, 64,
                                      (const __nv_bfloat16*)0, (const __nv_bfloat16*)0, 0,
                                      p_w0h, p_w0l, p_bab, p_yab,
                                      (__nv_bfloat16*)0, (__nv_bfloat16*)0,
                                      (const float*)0, (const float*)0, (const int*)0,
                                      NN, 256, 0);

    // 4-6: finish CSR
    k_scan2<<<1, 256>>>(SCAN_BLK);
    k_scan3<<<SCAN_BLK, 256>>>();
    k_fill<<<(NE + 255) / 256, 256>>>(src, dst);

    // 7: msg0, 8: upd0 (K=192: agg | x-folded)
    k_msg<<<(NN * 32 + 255) / 256, 256>>>(p_yab, p_M, msglnw, msglnb, raw, p_aggh, p_aggl);
    k_mgemm<<<g128, 256, GEMM_SMEM>>>(p_aggh, p_aggl, 128, p_xh, p_xl, 64,
                                      p_u0h, p_u0l, p_ub0, (float*)0, p_hh, p_hl,
                                      updlnw, updlnb, (const int*)0, NN, 128, 2);

    for (int l = 1; l < 3; l++) {
        k_mgemm<<<g256, 256, GEMM_SMEM>>>(p_hh, p_hl, 128,
                                          (const __nv_bfloat16*)0, (const __nv_bfloat16*)0, 0,
                                          p_wabh + (size_t)l * 256 * 128, p_wabl + (size_t)l * 256 * 128,
                                          p_bab + l * 256, p_yab,
                                          (__nv_bfloat16*)0, (__nv_bfloat16*)0,
                                          (const float*)0, (const float*)0, (const int*)0,
                                          NN, 256, 0);
        k_msg<<<(NN * 32 + 255) / 256, 256>>>(p_yab, p_M + l * 16 * 128,
                                              msglnw + l * 128, msglnb + l * 128,
                                              raw, p_aggh, p_aggl);
        k_mgemm<<<g128, 256, GEMM_SMEM>>>(p_aggh, p_aggl, 128, p_hh, p_hl, 128,
                                          p_updh + (size_t)l * 128 * 256, p_updl + (size_t)l * 128 * 256,
                                          updb + l * 128, (float*)0, p_hh, p_hl,
                                          updlnw + l * 128, updlnb + l * 128, (const int*)0,
                                          NN, 128, 2);
    }

    // readout: fused fc1 + relu + fc2 dot + pooling
    k_mgemm<<<g256, 256, GEMM_SMEM>>>(p_hh, p_hl, 128,
                                      (const __nv_bfloat16*)0, (const __nv_bfloat16*)0, 0,
                                      p_fc1h, p_fc1l, fc1b, (float*)0,
                                      (__nv_bfloat16*)0, (__nv_bfloat16*)0,
                                      fc2w, fc2b, batch,
                                      NN, 256, 3);
    k_final<<<(NG + 255) / 256, 256>>>(out);
}

// round 13
// speedup vs baseline: 1.5158x; 1.0111x over previous
#include <cuda_runtime.h>
#include <cuda_bf16.h>
#include <math.h>
#include <stdint.h>

#define NN 40000
#define NE 640000
#define NG 1024

// ---------------- scratch (device globals; no allocations allowed) -------------
__device__ float g_yab [NN * 256];
__device__ float g_bab [3 * 256];
__device__ float g_M   [3 * 16 * 128];
__device__ float g_ub0 [128];

__device__ __nv_bfloat16 g_xh  [NN * 64],  g_xl  [NN * 64];
__device__ __nv_bfloat16 g_hh  [NN * 128], g_hl  [NN * 128];
__device__ __nv_bfloat16 g_aggh[NN * 128], g_aggl[NN * 128];
__device__ __nv_bfloat16 g_wabt_h[3 * 256 * 128], g_wabt_l[3 * 256 * 128];
__device__ __nv_bfloat16 g_updt_h[3 * 128 * 256], g_updt_l[3 * 128 * 256];
__device__ __nv_bfloat16 g_fc1t_h[256 * 128],     g_fc1t_l[256 * 128];
__device__ __nv_bfloat16 g_w0t_h[256 * 64],       g_w0t_l[256 * 64];
__device__ __nv_bfloat16 g_u0t_h[128 * 192],      g_u0t_l[128 * 192];

__device__ int   g_deg [NN];
__device__ int   g_row [NN + 1];
__device__ int   g_cur [NN];
__device__ int   g_bsum[160];
__device__ int   g_boff[160];
__device__ int   g_psrc[NE];
__device__ int   g_peid[NE];
__device__ float g_gsum[NG];
__device__ float g_gcnt[NG];

// ---------------- helpers --------------------------------------------------------
__device__ __forceinline__ void split_bf16(float v, __nv_bfloat16& h, __nv_bfloat16& l) {
    h = __float2bfloat16(v);
    l = __float2bfloat16(v - __bfloat162float(h));
}
__device__ __forceinline__ float tanh_fast(float x) {
    float y;
    asm("tanh.approx.f32 %0, %1;" : "=f"(y) : "f"(x));
    return y;
}
__device__ __forceinline__ void prefetch_l1(const void* p) {
    asm volatile("prefetch.global.L1 [%0];" :: "l"(p));
}

// ---------------- merged packing + weight folding + init kernel ------------------
#define PACK_TOTAL 2878016
__global__ void k_pack_all(const float* __restrict__ msgW, const float* __restrict__ bondsW,
                           const float* __restrict__ bondsb, const float* __restrict__ msgb,
                           const float* __restrict__ atomsW, const float* __restrict__ atomsb,
                           const float* __restrict__ updW, const float* __restrict__ updb,
                           const float* __restrict__ fc1W, const float* __restrict__ x,
                           const int* __restrict__ batch)
{
    int idx = blockIdx.x * blockDim.x + threadIdx.x;
    if (idx < 98304) {
        int l = idx / 32768, r = idx % 32768;
        int n = r / 128, k = r % 128;
        const float* Wl = msgW + (size_t)l * 384 * 128;
        float v = (n < 128) ? Wl[k * 128 + n] : Wl[(128 + k) * 128 + (n - 128)];
        __nv_bfloat16 h, lo; split_bf16(v, h, lo);
        g_wabt_h[idx] = h; g_wabt_l[idx] = lo;
    } else if (idx < 104832) {
        int i2 = idx - 98304;
        if (i2 < 3 * 16 * 128) {
            int l = i2 / 2048, k = (i2 / 128) & 15, d = i2 & 127;
            const float* W3 = msgW + (size_t)l * 384 * 128 + 256 * 128;
            float s = 0.f;
            for (int j = 0; j < 128; j++) s += bondsW[k * 128 + j] * W3[j * 128 + d];
            g_M[i2] = s;
        } else {
            int i3 = i2 - 3 * 16 * 128;
            int l = i3 / 128, d = i3 & 127;
            const float* W3 = msgW + (size_t)l * 384 * 128 + 256 * 128;
            float s = msgb[l * 128 + d];
            for (int j = 0; j < 128; j++) s += bondsb[j] * W3[j * 128 + d];
            float sB = 0.f;
            if (l == 0) {
                const float* W0 = msgW;
                float sA = 0.f;
                for (int j = 0; j < 128; j++) {
                    sA += atomsb[j] * W0[j * 128 + d];
                    sB += atomsb[j] * W0[(128 + j) * 128 + d];
                }
                s += sA;
            }
            g_bab[l * 256 + d] = s;
            g_bab[l * 256 + 128 + d] = sB;
        }
    } else if (idx < 203136) {
        int i = idx - 104832;
        int l = i / 32768, r = i % 32768;
        int n = r / 256, k = r % 256;
        const float* Wl = updW + (size_t)l * 256 * 128;
        __nv_bfloat16 h, lo; split_bf16(Wl[k * 128 + n], h, lo);
        g_updt_h[i] = h; g_updt_l[i] = lo;
    } else if (idx < 235904) {
        int i = idx - 203136;
        int n = i / 128, k = i % 128;
        __nv_bfloat16 h, l; split_bf16(fc1W[k * 256 + n], h, l);
        g_fc1t_h[i] = h; g_fc1t_l[i] = l;
    } else if (idx < 2795904) {
        int i = idx - 235904;
        __nv_bfloat16 h, l; split_bf16(x[i], h, l);
        g_xh[i] = h; g_xl[i] = l;
    } else if (idx < 2812288) {
        int i = idx - 2795904;               // wab0 fold
        int n = i / 64, m = i % 64;
        const float* W0 = msgW;
        float s = 0.f;
        if (n < 128) {
            for (int j = 0; j < 128; j++) s += atomsW[m * 128 + j] * W0[j * 128 + n];
        } else {
            for (int j = 0; j < 128; j++) s += atomsW[m * 128 + j] * W0[(128 + j) * 128 + (n - 128)];
        }
        __nv_bfloat16 h, lo; split_bf16(s, h, lo);
        g_w0t_h[i] = h; g_w0t_l[i] = lo;
    } else if (idx < 2828672) {
        int i = idx - 2812288;               // upd0 copy
        int n = i / 128, k = i % 128;
        __nv_bfloat16 h, lo; split_bf16(updW[k * 128 + n], h, lo);
        g_u0t_h[n * 192 + k] = h; g_u0t_l[n * 192 + k] = lo;
    } else if (idx < 2836864) {
        int i = idx - 2828672;               // upd0 fold
        int n = i / 64, m = i % 64;
        float s = 0.f;
        for (int j = 0; j < 128; j++) s += atomsW[m * 128 + j] * updW[(128 + j) * 128 + n];
        __nv_bfloat16 h, lo; split_bf16(s, h, lo);
        g_u0t_h[n * 192 + 128 + m] = h; g_u0t_l[n * 192 + 128 + m] = lo;
    } else if (idx < 2836992) {
        int n = idx - 2836864;
        float s = updb[n];
        for (int j = 0; j < 128; j++) s += atomsb[j] * updW[(128 + j) * 128 + n];
        g_ub0[n] = s;
    } else if (idx < 2876992) {
        g_deg[idx - 2836992] = 0;
    } else if (idx < PACK_TOTAL) {
        int i = idx - 2876992;
        g_gsum[i] = 0.f;
        int lo = 0, hi = NN;
        while (lo < hi) { int m = (lo + hi) >> 1; if (batch[m] < i) lo = m + 1; else hi = m; }
        int lo2 = lo, hi2 = NN;
        while (lo2 < hi2) { int m = (lo2 + hi2) >> 1; if (batch[m] < i + 1) lo2 = m + 1; else hi2 = m; }
        g_gcnt[i] = (float)(lo2 - lo);
    }
}

__global__ void k_deg(const int* __restrict__ dst) {
    int e = blockIdx.x * blockDim.x + threadIdx.x;
    if (e < NE) atomicAdd(&g_deg[dst[e]], 1);
}

// ---------------- parallel 3-phase exclusive scan of degrees ---------------------
__global__ void k_scan1() {
    __shared__ int ws[8];
    int t = threadIdx.x, lane = t & 31, w = t >> 5;
    int i = blockIdx.x * 256 + t;
    int d = (i < NN) ? g_deg[i] : 0;
    int s = __reduce_add_sync(0xffffffffu, d);
    if (lane == 0) ws[w] = s;
    __syncthreads();
    if (t == 0) {
        int tot = 0;
        for (int j = 0; j < 8; j++) tot += ws[j];
        g_bsum[blockIdx.x] = tot;
    }
}
__global__ void k_scan2(int nblk) {
    __shared__ int wsum[8];
    int t = threadIdx.x, lane = t & 31, w = t >> 5;
    int v = (t < nblk) ? g_bsum[t] : 0;
    int x = v;
#pragma unroll
    for (int off = 1; off < 32; off <<= 1) {
        int y = __shfl_up_sync(0xffffffffu, x, off);
        if (lane >= off) x += y;
    }
    if (lane == 31) wsum[w] = x;
    __syncthreads();
    if (t == 0) {
        int r = 0;
        for (int j = 0; j < 8; j++) { int tmp = wsum[j]; wsum[j] = r; r += tmp; }
        g_row[NN] = NE;
    }
    __syncthreads();
    if (t < nblk) g_boff[t] = x - v + wsum[w];
}
__global__ void k_scan3() {
    __shared__ int wsum[8];
    int t = threadIdx.x, lane = t & 31, w = t >> 5;
    int i = blockIdx.x * 256 + t;
    int d = (i < NN) ? g_deg[i] : 0;
    int x = d;
#pragma unroll
    for (int off = 1; off < 32; off <<= 1) {
        int y = __shfl_up_sync(0xffffffffu, x, off);
        if (lane >= off) x += y;
    }
    if (lane == 31) wsum[w] = x;
    __syncthreads();
    if (t == 0) {
        int r = 0;
        for (int j = 0; j < 8; j++) { int tmp = wsum[j]; wsum[j] = r; r += tmp; }
    }
    __syncthreads();
    int excl = x - d + wsum[w] + g_boff[blockIdx.x];
    if (i < NN) { g_row[i] = excl; g_cur[i] = excl; }
}

__global__ void k_fill(const int* __restrict__ src, const int* __restrict__ dst) {
    int e = blockIdx.x * blockDim.x + threadIdx.x;
    if (e < NE) {
        int d = dst[e];
        int p = atomicAdd(&g_cur[d], 1);
        g_psrc[p] = src[e];
        g_peid[p] = e;
    }
}

// ================= bf16x3 mma.sync GEMM with ldmatrix + cp.async =================
#define MMA_BF16(d, a, b0, b1) \
    asm volatile("mma.sync.aligned.m16n8k16.row.col.f32.bf16.bf16.f32 " \
        "{%0,%1,%2,%3}, {%4,%5,%6,%7}, {%8,%9}, {%0,%1,%2,%3};" \
        : "+f"(d[0]), "+f"(d[1]), "+f"(d[2]), "+f"(d[3]) \
        : "r"(a[0]), "r"(a[1]), "r"(a[2]), "r"(a[3]), "r"(b0), "r"(b1));

#define LDSM_X4(r, a) \
    asm volatile("ldmatrix.sync.aligned.m8n8.x4.shared.b16 {%0,%1,%2,%3}, [%4];" \
        : "=r"((r)[0]), "=r"((r)[1]), "=r"((r)[2]), "=r"((r)[3]) : "r"(a))

#define CP_ASYNC(sa, ga, sz) \
    asm volatile("cp.async.ca.shared.global [%0], [%1], 16, %2;" :: "r"(sa), "l"(ga), "r"(sz))
#define CP_COMMIT() asm volatile("cp.async.commit_group;" ::: "memory")
#define CP_WAIT(n)  asm volatile("cp.async.wait_group %0;" :: "n"(n) : "memory")

#define FMA_F32X2(d, a, b) \
    asm("fma.rn.f32x2 %0, %1, %2, %0;" : "+l"(d) : "l"(a), "l"(b))
#define UNPACK_F32X2(lo, hi, v) \
    asm("mov.b64 {%0, %1}, %2;" : "=f"(lo), "=f"(hi) : "l"(v))
#define PACK_F32X2(d, lo, hi) \
    asm("mov.b64 %0, {%1, %2};" : "=l"(d) : "f"(lo), "f"(hi))

__device__ __forceinline__ uint32_t smem_u32(const void* p) {
    uint32_t a;
    asm("{ .reg .u64 t; cvta.to.shared.u64 t, %1; cvt.u32.u64 %0, t; }" : "=r"(a) : "l"(p));
    return a;
}

#define GEMM_SMEM (2 * 40960)

__global__ void __launch_bounds__(256) k_mgemm(
    const __nv_bfloat16* __restrict__ X1h, const __nv_bfloat16* __restrict__ X1l, int K1,
    const __nv_bfloat16* __restrict__ X2h, const __nv_bfloat16* __restrict__ X2l, int K2,
    const __nv_bfloat16* __restrict__ Wh,  const __nv_bfloat16* __restrict__ Wl,
    const float* __restrict__ bias, float* __restrict__ Y,
    __nv_bfloat16* __restrict__ Yh, __nv_bfloat16* __restrict__ Yl,
    const float* __restrict__ lnw, const float* __restrict__ lnb,
    const int* __restrict__ batch,
    int nrows, int ncols, int act)
{
    extern __shared__ char smem[];
    const uint32_t sb = smem_u32(smem);
    const int tid = threadIdx.x;
    const int wid = tid >> 5, lane = tid & 31;
    const int wm = wid & 1, wn = wid >> 1;
    const int g = lane >> 2, t = lane & 3;
    const int rbase = blockIdx.x * 128, cbase = blockIdx.y * 128;
    const int Ktot = K1 + K2;
    const int nch = Ktot >> 5;

    const int srow = tid >> 1;
    const int sseg = (tid & 1) * 2;

    float acc[4][4][4];
#pragma unroll
    for (int i = 0; i < 4; i++)
#pragma unroll
        for (int j = 0; j < 4; j++)
#pragma unroll
            for (int q = 0; q < 4; q++) acc[i][j][q] = 0.f;

    const int quad = lane >> 3, li = lane & 7;
    const int a_row = (quad & 1) * 8 + li;
    const int a_col = (quad >> 1) * 8;
    const int b_row = (quad >> 1) * 8 + li;
    const int b_col = (quad & 1) * 8;

    auto stage = [&](int ch, int buf) {
        const int kk = ch << 5;
        const uint32_t base = sb + buf * 40960;
        {
            const __nv_bfloat16 *Xh, *Xl; int xs, kx;
            if (kk < K1) { Xh = X1h; Xl = X1l; xs = K1; kx = kk; }
            else         { Xh = X2h; Xl = X2l; xs = K2; kx = kk - K1; }
            int gr = rbase + srow;
            uint32_t sz = (gr < nrows) ? 16u : 0u;
            if (gr >= nrows) gr = nrows - 1;
            const __nv_bfloat16* ph = Xh + (size_t)gr * xs + kx;
            const __nv_bfloat16* pl = Xl + (size_t)gr * xs + kx;
#pragma unroll
            for (int q = 0; q < 2; q++) {
                const int seg = sseg + q;
                const uint32_t so = base + srow * 80 + seg * 16;
                CP_ASYNC(so,         ph + seg * 8, sz);
                CP_ASYNC(so + 10240, pl + seg * 8, sz);
            }
        }
        {
            const int gn = cbase + srow;
            const __nv_bfloat16* ph = Wh + (size_t)gn * Ktot + kk;
            const __nv_bfloat16* pl = Wl + (size_t)gn * Ktot + kk;
#pragma unroll
            for (int q = 0; q < 2; q++) {
                const int seg = sseg + q;
                const uint32_t so = base + 20480 + srow * 80 + seg * 16;
                CP_ASYNC(so,         ph + seg * 8, 16u);
                CP_ASYNC(so + 10240, pl + seg * 8, 16u);
            }
        }
        CP_COMMIT();
    };

    stage(0, 0);
    for (int ch = 0; ch < nch; ch++) {
        const int buf = ch & 1;
        const bool more = (ch + 1 < nch);
        if (more) stage(ch + 1, buf ^ 1);
        if (more) { CP_WAIT(1); } else { CP_WAIT(0); }
        __syncthreads();

        const uint32_t base = sb + buf * 40960;
        const uint32_t aah = base + (wm * 64 + a_row) * 80 + a_col * 2;
        const uint32_t bbh = base + 20480 + (wn * 32 + b_row) * 80 + b_col * 2;
#pragma unroll
        for (int s = 0; s < 2; s++) {
            const uint32_t ks2 = s * 32;
            uint32_t ah[4][4], al[4][4];
#pragma unroll
            for (int mt = 0; mt < 4; mt++) {
                LDSM_X4(ah[mt], aah + mt * 1280 + ks2);
                LDSM_X4(al[mt], aah + 10240 + mt * 1280 + ks2);
            }
            uint32_t bh[4][2], bl[4][2];
#pragma unroll
            for (int pr = 0; pr < 2; pr++) {
                uint32_t tmp[4];
                LDSM_X4(tmp, bbh + pr * 1280 + ks2);
                bh[2 * pr][0] = tmp[0]; bh[2 * pr][1] = tmp[1];
                bh[2 * pr + 1][0] = tmp[2]; bh[2 * pr + 1][1] = tmp[3];
                LDSM_X4(tmp, bbh + 10240 + pr * 1280 + ks2);
                bl[2 * pr][0] = tmp[0]; bl[2 * pr][1] = tmp[1];
                bl[2 * pr + 1][0] = tmp[2]; bl[2 * pr + 1][1] = tmp[3];
            }
#pragma unroll
            for (int nt = 0; nt < 4; nt++)
#pragma unroll
                for (int mt = 0; mt < 4; mt++) {
                    MMA_BF16(acc[mt][nt], ah[mt], bh[nt][0], bh[nt][1]);
                    MMA_BF16(acc[mt][nt], ah[mt], bl[nt][0], bl[nt][1]);
                    MMA_BF16(acc[mt][nt], al[mt], bh[nt][0], bh[nt][1]);
                }
        }
        __syncthreads();
    }

    if (act == 2) {
        float* tb = (float*)smem;
#pragma unroll
        for (int mt = 0; mt < 4; mt++)
#pragma unroll
            for (int half = 0; half < 2; half++) {
                int row = wm * 64 + mt * 16 + g + 8 * half;
#pragma unroll
                for (int nt = 0; nt < 4; nt++) {
                    int col = wn * 32 + nt * 8 + 2 * t;
                    tb[row * 132 + col]     = acc[mt][nt][2 * half + 0] + bias[col];
                    tb[row * 132 + col + 1] = acc[mt][nt][2 * half + 1] + bias[col + 1];
                }
            }
        __syncthreads();
        float lw[4], lb[4];
#pragma unroll
        for (int j = 0; j < 4; j++) { lw[j] = lnw[lane + 32 * j]; lb[j] = lnb[lane + 32 * j]; }
#pragma unroll 1
        for (int it = 0; it < 16; it++) {
            int row = wid * 16 + it;
            int grow = rbase + row;
            float v[4];
#pragma unroll
            for (int j = 0; j < 4; j++) v[j] = tb[row * 132 + lane + 32 * j];
            float s = v[0] + v[1] + v[2] + v[3];
            float q = v[0] * v[0];
            q = fmaf(v[1], v[1], q);
            q = fmaf(v[2], v[2], q);
            q = fmaf(v[3], v[3], q);
#pragma unroll
            for (int off = 16; off > 0; off >>= 1) {
                s += __shfl_xor_sync(0xffffffffu, s, off);
                q += __shfl_xor_sync(0xffffffffu, q, off);
            }
            float mean = s * (1.f / 128.f);
            float var = q * (1.f / 128.f) - mean * mean;
            float rstd = rsqrtf(var + 1e-5f);
            if (grow < nrows) {
#pragma unroll
                for (int j = 0; j < 4; j++) {
                    float y = (v[j] - mean) * rstd * lw[j] + lb[j];
                    __nv_bfloat16 h, l; split_bf16(tanh_fast(y), h, l);
                    Yh[(size_t)grow * 128 + lane + 32 * j] = h;
                    Yl[(size_t)grow * 128 + lane + 32 * j] = l;
                }
            }
        }
        return;
    }

    if (act == 3) {
        float* rs = (float*)smem;
        if (tid < 128) rs[tid] = 0.f;
        __syncthreads();
#pragma unroll
        for (int mt = 0; mt < 4; mt++)
#pragma unroll
            for (int half = 0; half < 2; half++) {
                float p = 0.f;
#pragma unroll
                for (int nt = 0; nt < 4; nt++) {
                    int col = cbase + wn * 32 + nt * 8 + 2 * t;
                    float v0 = fmaxf(acc[mt][nt][2 * half + 0] + bias[col], 0.f);
                    float v1 = fmaxf(acc[mt][nt][2 * half + 1] + bias[col + 1], 0.f);
                    p = fmaf(v0, lnw[col], p);
                    p = fmaf(v1, lnw[col + 1], p);
                }
                p += __shfl_xor_sync(0xffffffffu, p, 1);
                p += __shfl_xor_sync(0xffffffffu, p, 2);
                if (t == 0) atomicAdd(&rs[wm * 64 + mt * 16 + g + 8 * half], p);
            }
        __syncthreads();
        if (tid < 128) {
            int grow = rbase + tid;
            if (grow < nrows) {
                float v = rs[tid];
                if (cbase == 0) v += lnb[0];
                atomicAdd(&g_gsum[batch[grow]], v);
            }
        }
        return;
    }

#pragma unroll
    for (int mt = 0; mt < 4; mt++) {
#pragma unroll
        for (int half = 0; half < 2; half++) {
            int row = rbase + wm * 64 + mt * 16 + g + 8 * half;
            if (row >= nrows) continue;
#pragma unroll
            for (int nt = 0; nt < 4; nt++) {
                int col = cbase + wn * 32 + nt * 8 + 2 * t;
                float v0 = acc[mt][nt][2 * half + 0] + bias[col];
                float v1 = acc[mt][nt][2 * half + 1] + bias[col + 1];
                if (act == 1) { v0 = fmaxf(v0, 0.f); v1 = fmaxf(v1, 0.f); }
                if (Y) {
                    float2 v; v.x = v0; v.y = v1;
                    *(float2*)(Y + (size_t)row * ncols + col) = v;
                }
                if (Yh) {
                    __nv_bfloat16 h0, l0, h1, l1;
                    split_bf16(v0, h0, l0);
                    split_bf16(v1, h1, l1);
                    __nv_bfloat162 hp; hp.x = h0; hp.y = h1;
                    __nv_bfloat162 lp; lp.x = l0; lp.y = l1;
                    *(__nv_bfloat162*)(Yh + (size_t)row * ncols + col) = hp;
                    *(__nv_bfloat162*)(Yl + (size_t)row * ncols + col) = lp;
                }
            }
        }
    }
}

// ---------------- fused message + LN + tanh + aggregate (warp per dst node) ----
// f32x2 packed inner product; next edge's raw row prefetched to L1 (zero regs).
__global__ void __launch_bounds__(256) k_msg(
    const float* __restrict__ yab, const float* __restrict__ Mw,
    const float* __restrict__ lnw, const float* __restrict__ lnb,
    const float* __restrict__ raw,
    __nv_bfloat16* __restrict__ aggh, __nv_bfloat16* __restrict__ aggl)
{
    int warp = (blockIdx.x * blockDim.x + threadIdx.x) >> 5;
    int lane = threadIdx.x & 31;
    if (warp >= NN) return;

    unsigned long long Mp[8][4];
#pragma unroll
    for (int k2 = 0; k2 < 8; k2++)
#pragma unroll
        for (int j = 0; j < 4; j++) {
            float m0 = Mw[(2 * k2) * 128 + lane + 32 * j];
            float m1 = Mw[(2 * k2 + 1) * 128 + lane + 32 * j];
            PACK_F32X2(Mp[k2][j], m0, m1);
        }

    float bj[4], lw[4], lb[4], accj[4];
#pragma unroll
    for (int j = 0; j < 4; j++) {
        bj[j] = yab[(size_t)warp * 256 + 128 + lane + 32 * j];
        lw[j] = lnw[lane + 32 * j];
        lb[j] = lnb[lane + 32 * j];
        accj[j] = 0.f;
    }

    int p0 = g_row[warp], p1 = g_row[warp + 1];
    if (p0 < p1) {
        int eid_n = g_peid[p0];
        int src_n = g_psrc[p0];
        // prefetch first edge's raw row (64B) into L1
        if (lane == 0) prefetch_l1(raw + (size_t)eid_n * 16);
        float an[4];
        {
            const float* arn = yab + (size_t)src_n * 256;
#pragma unroll
            for (int j = 0; j < 4; j++) an[j] = arn[lane + 32 * j];
        }
        for (int p = p0; p < p1; p++) {
            const int eid = eid_n;
            float ca[4] = {an[0], an[1], an[2], an[3]};
            if (p + 1 < p1) {
                src_n = g_psrc[p + 1];
                eid_n = g_peid[p + 1];
                // prefetch NEXT raw row before touching this one
                if (lane == 0) prefetch_l1(raw + (size_t)eid_n * 16);
                const float* arn = yab + (size_t)src_n * 256;
#pragma unroll
                for (int j = 0; j < 4; j++) an[j] = arn[lane + 32 * j];
            }
            const ulonglong2* rp = (const ulonglong2*)(raw + (size_t)eid * 16);
            ulonglong2 u0 = rp[0], u1 = rp[1], u2 = rp[2], u3 = rp[3];
            unsigned long long rvp[8] = {u0.x, u0.y, u1.x, u1.y, u2.x, u2.y, u3.x, u3.y};
            unsigned long long accp[4] = {0ull, 0ull, 0ull, 0ull};
#pragma unroll
            for (int k2 = 0; k2 < 8; k2++)
#pragma unroll
                for (int j = 0; j < 4; j++)
                    FMA_F32X2(accp[j], rvp[k2], Mp[k2][j]);
            float pre[4];
#pragma unroll
            for (int j = 0; j < 4; j++) {
                float e, o;
                UNPACK_F32X2(e, o, accp[j]);
                pre[j] = (bj[j] + ca[j]) + (e + o);
            }
            float s = pre[0] + pre[1] + pre[2] + pre[3];
            float q = pre[0] * pre[0];
            q = fmaf(pre[1], pre[1], q);
            q = fmaf(pre[2], pre[2], q);
            q = fmaf(pre[3], pre[3], q);
#pragma unroll
            for (int off = 16; off > 0; off >>= 1) {
                s += __shfl_xor_sync(0xffffffffu, s, off);
                q += __shfl_xor_sync(0xffffffffu, q, off);
            }
            float mean = s * (1.f / 128.f);
            float var = q * (1.f / 128.f) - mean * mean;
            float rstd = rsqrtf(var + 1e-5f);
#pragma unroll
            for (int j = 0; j < 4; j++) {
                float y = (pre[j] - mean) * rstd * lw[j] + lb[j];
                accj[j] += tanh_fast(y);
            }
        }
    }
#pragma unroll
    for (int j = 0; j < 4; j++) {
        __nv_bfloat16 h, l; split_bf16(accj[j], h, l);
        aggh[(size_t)warp * 128 + lane + 32 * j] = h;
        aggl[(size_t)warp * 128 + lane + 32 * j] = l;
    }
}

__global__ void k_final(float* __restrict__ out) {
    int g = blockIdx.x * blockDim.x + threadIdx.x;
    if (g < NG) out[g] = g_gsum[g] / fmaxf(g_gcnt[g], 1.0f);
}

// ---------------- host orchestration --------------------------------------------
extern "C" void kernel_launch(void* const* d_in, const int* in_sizes, int n_in,
                              void* d_out, int out_size)
{
    const float* x      = (const float*)d_in[0];
    const int*   ei     = (const int*)  d_in[1];
    const float* raw    = (const float*)d_in[2];
    const int*   batch  = (const int*)  d_in[3];
    const float* atomsW = (const float*)d_in[4];
    const float* atomsb = (const float*)d_in[5];
    const float* bondsW = (const float*)d_in[6];
    const float* bondsb = (const float*)d_in[7];
    const float* msgW   = (const float*)d_in[8];
    const float* msgb   = (const float*)d_in[9];
    const float* msglnw = (const float*)d_in[10];
    const float* msglnb = (const float*)d_in[11];
    const float* updW   = (const float*)d_in[12];
    const float* updb   = (const float*)d_in[13];
    const float* updlnw = (const float*)d_in[14];
    const float* updlnb = (const float*)d_in[15];
    const float* fc1W   = (const float*)d_in[16];
    const float* fc1b   = (const float*)d_in[17];
    const float* fc2w   = (const float*)d_in[18];
    const float* fc2b   = (const float*)d_in[19];
    float* out = (float*)d_out;

    const int* src = ei;
    const int* dst = ei + NE;

    cudaFuncSetAttribute(k_mgemm, cudaFuncAttributeMaxDynamicSharedMemorySize, GEMM_SMEM);

    float *p_yab, *p_bab, *p_M, *p_ub0;
    cudaGetSymbolAddress((void**)&p_yab, g_yab);
    cudaGetSymbolAddress((void**)&p_bab, g_bab);
    cudaGetSymbolAddress((void**)&p_M,   g_M);
    cudaGetSymbolAddress((void**)&p_ub0, g_ub0);
    __nv_bfloat16 *p_xh, *p_xl, *p_hh, *p_hl, *p_aggh, *p_aggl;
    __nv_bfloat16 *p_wabh, *p_wabl, *p_updh, *p_updl, *p_fc1h, *p_fc1l;
    __nv_bfloat16 *p_w0h, *p_w0l, *p_u0h, *p_u0l;
    cudaGetSymbolAddress((void**)&p_xh,   g_xh);
    cudaGetSymbolAddress((void**)&p_xl,   g_xl);
    cudaGetSymbolAddress((void**)&p_hh,   g_hh);
    cudaGetSymbolAddress((void**)&p_hl,   g_hl);
    cudaGetSymbolAddress((void**)&p_aggh, g_aggh);
    cudaGetSymbolAddress((void**)&p_aggl, g_aggl);
    cudaGetSymbolAddress((void**)&p_wabh, g_wabt_h);
    cudaGetSymbolAddress((void**)&p_wabl, g_wabt_l);
    cudaGetSymbolAddress((void**)&p_updh, g_updt_h);
    cudaGetSymbolAddress((void**)&p_updl, g_updt_l);
    cudaGetSymbolAddress((void**)&p_fc1h, g_fc1t_h);
    cudaGetSymbolAddress((void**)&p_fc1l, g_fc1t_l);
    cudaGetSymbolAddress((void**)&p_w0h,  g_w0t_h);
    cudaGetSymbolAddress((void**)&p_w0l,  g_w0t_l);
    cudaGetSymbolAddress((void**)&p_u0h,  g_u0t_h);
    cudaGetSymbolAddress((void**)&p_u0l,  g_u0t_l);

    const int SCAN_BLK = (NN + 255) / 256;   // 157
    const int RB = (NN + 127) / 128;
    dim3 g128(RB, 1), g256(RB, 2);

    // 0: packing + folding + init
    k_pack_all<<<(PACK_TOTAL + 255) / 256, 256>>>(msgW, bondsW, bondsb, msgb,
                                                  atomsW, atomsb, updW, updb, fc1W, x, batch);
    // 1-2: CSR degree + scan phase 1
    k_deg<<<(NE + 255) / 256, 256>>>(dst);
    k_scan1<<<SCAN_BLK, 256>>>();

    // 3 (ncu capture target): wab0 GEMM  A|B = x @ W0ab (K=64)
    k_mgemm<<<g256, 256, GEMM_SMEM>>>(p_xh, p_xl, 64,
                                      (const __nv_bfloat16*)0, (const __nv_bfloat16*)0, 0,
                                      p_w0h, p_w0l, p_bab, p_yab,
                                      (__nv_bfloat16*)0, (__nv_bfloat16*)0,
                                      (const float*)0, (const float*)0, (const int*)0,
                                      NN, 256, 0);

    // 4-6: finish CSR
    k_scan2<<<1, 256>>>(SCAN_BLK);
    k_scan3<<<SCAN_BLK, 256>>>();
    k_fill<<<(NE + 255) / 256, 256>>>(src, dst);

    // 7: msg0, 8: upd0 (K=192: agg | x-folded)
    k_msg<<<(NN * 32 + 255) / 256, 256>>>(p_yab, p_M, msglnw, msglnb, raw, p_aggh, p_aggl);
    k_mgemm<<<g128, 256, GEMM_SMEM>>>(p_aggh, p_aggl, 128, p_xh, p_xl, 64,
                                      p_u0h, p_u0l, p_ub0, (float*)0, p_hh, p_hl,
                                      updlnw, updlnb, (const int*)0, NN, 128, 2);

    for (int l = 1; l < 3; l++) {
        k_mgemm<<<g256, 256, GEMM_SMEM>>>(p_hh, p_hl, 128,
                                          (const __nv_bfloat16*)0, (const __nv_bfloat16*)0, 0,
                                          p_wabh + (size_t)l * 256 * 128, p_wabl + (size_t)l * 256 * 128,
                                          p_bab + l * 256, p_yab,
                                          (__nv_bfloat16*)0, (__nv_bfloat16*)0,
                                          (const float*)0, (const float*)0, (const int*)0,
                                          NN, 256, 0);
        k_msg<<<(NN * 32 + 255) / 256, 256>>>(p_yab, p_M + l * 16 * 128,
                                              msglnw + l * 128, msglnb + l * 128,
                                              raw, p_aggh, p_aggl);
        k_mgemm<<<g128, 256, GEMM_SMEM>>>(p_aggh, p_aggl, 128, p_hh, p_hl, 128,
                                          p_updh + (size_t)l * 128 * 256, p_updl + (size_t)l * 128 * 256,
                                          updb + l * 128, (float*)0, p_hh, p_hl,
                                          updlnw + l * 128, updlnb + l * 128, (const int*)0,
                                          NN, 128, 2);
    }

    // readout: fused fc1 + relu + fc2 dot + pooling
    k_mgemm<<<g256, 256, GEMM_SMEM>>>(p_hh, p_hl, 128,
                                      (const __nv_bfloat16*)0, (const __nv_bfloat16*)0, 0,
                                      p_fc1h, p_fc1l, fc1b, (float*)0,
                                      (__nv_bfloat16*)0, (__nv_bfloat16*)0,
                                      fc2w, fc2b, batch,
                                      NN, 256, 3);
    k_final<<<(NG + 255) / 256, 256>>>(out);
}

// round 16
// speedup vs baseline: 1.5339x; 1.0120x over previous
#include <cuda_runtime.h>
#include <cuda_bf16.h>
#include <math.h>
#include <stdint.h>

#define NN 40000
#define NE 640000
#define NG 1024

// ---------------- scratch (device globals; no allocations allowed) -------------
__device__ float g_yab [NN * 256];
__device__ float g_bab [3 * 256];
__device__ float g_M   [3 * 16 * 128];
__device__ float g_ub0 [128];

__device__ __nv_bfloat16 g_xh  [NN * 64],  g_xl  [NN * 64];
__device__ __nv_bfloat16 g_hh  [NN * 128], g_hl  [NN * 128];
__device__ __nv_bfloat16 g_aggh[NN * 128], g_aggl[NN * 128];
__device__ __nv_bfloat16 g_wabt_h[3 * 256 * 128], g_wabt_l[3 * 256 * 128];
__device__ __nv_bfloat16 g_updt_h[3 * 128 * 256], g_updt_l[3 * 128 * 256];
__device__ __nv_bfloat16 g_fc1t_h[256 * 128],     g_fc1t_l[256 * 128];
__device__ __nv_bfloat16 g_w0t_h[256 * 64],       g_w0t_l[256 * 64];
__device__ __nv_bfloat16 g_u0t_h[128 * 192],      g_u0t_l[128 * 192];

__device__ int   g_deg [NN];
__device__ int   g_row [NN + 1];
__device__ int   g_cur [NN];
__device__ int   g_bsum[160];
__device__ int   g_boff[160];
__device__ int   g_psrc[NE];
__device__ int   g_peid[NE];
__device__ float g_gsum[NG];
__device__ float g_gcnt[NG];

// ---------------- helpers --------------------------------------------------------
__device__ __forceinline__ void split_bf16(float v, __nv_bfloat16& h, __nv_bfloat16& l) {
    h = __float2bfloat16(v);
    l = __float2bfloat16(v - __bfloat162float(h));
}
__device__ __forceinline__ float tanh_fast(float x) {
    float y;
    asm("tanh.approx.f32 %0, %1;" : "=f"(y) : "f"(x));
    return y;
}
__device__ __forceinline__ void prefetch_l1(const void* p) {
    asm volatile("prefetch.global.L1 [%0];" :: "l"(p));
}

// ---------------- merged packing + weight folding + init kernel ------------------
#define PACK_TOTAL 2878016
__global__ void k_pack_all(const float* __restrict__ msgW, const float* __restrict__ bondsW,
                           const float* __restrict__ bondsb, const float* __restrict__ msgb,
                           const float* __restrict__ atomsW, const float* __restrict__ atomsb,
                           const float* __restrict__ updW, const float* __restrict__ updb,
                           const float* __restrict__ fc1W, const float* __restrict__ x,
                           const int* __restrict__ batch)
{
    int idx = blockIdx.x * blockDim.x + threadIdx.x;
    if (idx < 98304) {
        int l = idx / 32768, r = idx % 32768;
        int n = r / 128, k = r % 128;
        const float* Wl = msgW + (size_t)l * 384 * 128;
        float v = (n < 128) ? Wl[k * 128 + n] : Wl[(128 + k) * 128 + (n - 128)];
        __nv_bfloat16 h, lo; split_bf16(v, h, lo);
        g_wabt_h[idx] = h; g_wabt_l[idx] = lo;
    } else if (idx < 104832) {
        int i2 = idx - 98304;
        if (i2 < 3 * 16 * 128) {
            int l = i2 / 2048, k = (i2 / 128) & 15, d = i2 & 127;
            const float* W3 = msgW + (size_t)l * 384 * 128 + 256 * 128;
            float s = 0.f;
            for (int j = 0; j < 128; j++) s += bondsW[k * 128 + j] * W3[j * 128 + d];
            g_M[i2] = s;
        } else {
            int i3 = i2 - 3 * 16 * 128;
            int l = i3 / 128, d = i3 & 127;
            const float* W3 = msgW + (size_t)l * 384 * 128 + 256 * 128;
            float s = msgb[l * 128 + d];
            for (int j = 0; j < 128; j++) s += bondsb[j] * W3[j * 128 + d];
            float sB = 0.f;
            if (l == 0) {
                const float* W0 = msgW;
                float sA = 0.f;
                for (int j = 0; j < 128; j++) {
                    sA += atomsb[j] * W0[j * 128 + d];
                    sB += atomsb[j] * W0[(128 + j) * 128 + d];
                }
                s += sA;
            }
            g_bab[l * 256 + d] = s;
            g_bab[l * 256 + 128 + d] = sB;
        }
    } else if (idx < 203136) {
        int i = idx - 104832;
        int l = i / 32768, r = i % 32768;
        int n = r / 256, k = r % 256;
        const float* Wl = updW + (size_t)l * 256 * 128;
        __nv_bfloat16 h, lo; split_bf16(Wl[k * 128 + n], h, lo);
        g_updt_h[i] = h; g_updt_l[i] = lo;
    } else if (idx < 235904) {
        int i = idx - 203136;
        int n = i / 128, k = i % 128;
        __nv_bfloat16 h, l; split_bf16(fc1W[k * 256 + n], h, l);
        g_fc1t_h[i] = h; g_fc1t_l[i] = l;
    } else if (idx < 2795904) {
        int i = idx - 235904;
        __nv_bfloat16 h, l; split_bf16(x[i], h, l);
        g_xh[i] = h; g_xl[i] = l;
    } else if (idx < 2812288) {
        int i = idx - 2795904;               // wab0 fold
        int n = i / 64, m = i % 64;
        const float* W0 = msgW;
        float s = 0.f;
        if (n < 128) {
            for (int j = 0; j < 128; j++) s += atomsW[m * 128 + j] * W0[j * 128 + n];
        } else {
            for (int j = 0; j < 128; j++) s += atomsW[m * 128 + j] * W0[(128 + j) * 128 + (n - 128)];
        }
        __nv_bfloat16 h, lo; split_bf16(s, h, lo);
        g_w0t_h[i] = h; g_w0t_l[i] = lo;
    } else if (idx < 2828672) {
        int i = idx - 2812288;               // upd0 copy
        int n = i / 128, k = i % 128;
        __nv_bfloat16 h, lo; split_bf16(updW[k * 128 + n], h, lo);
        g_u0t_h[n * 192 + k] = h; g_u0t_l[n * 192 + k] = lo;
    } else if (idx < 2836864) {
        int i = idx - 2828672;               // upd0 fold
        int n = i / 64, m = i % 64;
        float s = 0.f;
        for (int j = 0; j < 128; j++) s += atomsW[m * 128 + j] * updW[(128 + j) * 128 + n];
        __nv_bfloat16 h, lo; split_bf16(s, h, lo);
        g_u0t_h[n * 192 + 128 + m] = h; g_u0t_l[n * 192 + 128 + m] = lo;
    } else if (idx < 2836992) {
        int n = idx - 2836864;
        float s = updb[n];
        for (int j = 0; j < 128; j++) s += atomsb[j] * updW[(128 + j) * 128 + n];
        g_ub0[n] = s;
    } else if (idx < 2876992) {
        g_deg[idx - 2836992] = 0;
    } else if (idx < PACK_TOTAL) {
        int i = idx - 2876992;
        g_gsum[i] = 0.f;
        int lo = 0, hi = NN;
        while (lo < hi) { int m = (lo + hi) >> 1; if (batch[m] < i) lo = m + 1; else hi = m; }
        int lo2 = lo, hi2 = NN;
        while (lo2 < hi2) { int m = (lo2 + hi2) >> 1; if (batch[m] < i + 1) lo2 = m + 1; else hi2 = m; }
        g_gcnt[i] = (float)(lo2 - lo);
    }
}

__global__ void k_deg(const int* __restrict__ dst) {
    int e = blockIdx.x * blockDim.x + threadIdx.x;
    if (e < NE) atomicAdd(&g_deg[dst[e]], 1);
}

// ---------------- parallel 3-phase exclusive scan of degrees ---------------------
__global__ void k_scan1() {
    __shared__ int ws[8];
    int t = threadIdx.x, lane = t & 31, w = t >> 5;
    int i = blockIdx.x * 256 + t;
    int d = (i < NN) ? g_deg[i] : 0;
    int s = __reduce_add_sync(0xffffffffu, d);
    if (lane == 0) ws[w] = s;
    __syncthreads();
    if (t == 0) {
        int tot = 0;
        for (int j = 0; j < 8; j++) tot += ws[j];
        g_bsum[blockIdx.x] = tot;
    }
}
__global__ void k_scan2(int nblk) {
    __shared__ int wsum[8];
    int t = threadIdx.x, lane = t & 31, w = t >> 5;
    int v = (t < nblk) ? g_bsum[t] : 0;
    int x = v;
#pragma unroll
    for (int off = 1; off < 32; off <<= 1) {
        int y = __shfl_up_sync(0xffffffffu, x, off);
        if (lane >= off) x += y;
    }
    if (lane == 31) wsum[w] = x;
    __syncthreads();
    if (t == 0) {
        int r = 0;
        for (int j = 0; j < 8; j++) { int tmp = wsum[j]; wsum[j] = r; r += tmp; }
        g_row[NN] = NE;
    }
    __syncthreads();
    if (t < nblk) g_boff[t] = x - v + wsum[w];
}
__global__ void k_scan3() {
    __shared__ int wsum[8];
    int t = threadIdx.x, lane = t & 31, w = t >> 5;
    int i = blockIdx.x * 256 + t;
    int d = (i < NN) ? g_deg[i] : 0;
    int x = d;
#pragma unroll
    for (int off = 1; off < 32; off <<= 1) {
        int y = __shfl_up_sync(0xffffffffu, x, off);
        if (lane >= off) x += y;
    }
    if (lane == 31) wsum[w] = x;
    __syncthreads();
    if (t == 0) {
        int r = 0;
        for (int j = 0; j < 8; j++) { int tmp = wsum[j]; wsum[j] = r; r += tmp; }
    }
    __syncthreads();
    int excl = x - d + wsum[w] + g_boff[blockIdx.x];
    if (i < NN) { g_row[i] = excl; g_cur[i] = excl; }
}

__global__ void k_fill(const int* __restrict__ src, const int* __restrict__ dst) {
    int e = blockIdx.x * blockDim.x + threadIdx.x;
    if (e < NE) {
        int d = dst[e];
        int p = atomicAdd(&g_cur[d], 1);
        g_psrc[p] = src[e];
        g_peid[p] = e;
    }
}

// ================= bf16x3 mma.sync GEMM with ldmatrix + cp.async =================
#define MMA_BF16(d, a, b0, b1) \
    asm volatile("mma.sync.aligned.m16n8k16.row.col.f32.bf16.bf16.f32 " \
        "{%0,%1,%2,%3}, {%4,%5,%6,%7}, {%8,%9}, {%0,%1,%2,%3};" \
        : "+f"(d[0]), "+f"(d[1]), "+f"(d[2]), "+f"(d[3]) \
        : "r"(a[0]), "r"(a[1]), "r"(a[2]), "r"(a[3]), "r"(b0), "r"(b1));

#define LDSM_X4(r, a) \
    asm volatile("ldmatrix.sync.aligned.m8n8.x4.shared.b16 {%0,%1,%2,%3}, [%4];" \
        : "=r"((r)[0]), "=r"((r)[1]), "=r"((r)[2]), "=r"((r)[3]) : "r"(a))

#define CP_ASYNC(sa, ga, sz) \
    asm volatile("cp.async.ca.shared.global [%0], [%1], 16, %2;" :: "r"(sa), "l"(ga), "r"(sz))
#define CP_COMMIT() asm volatile("cp.async.commit_group;" ::: "memory")
#define CP_WAIT(n)  asm volatile("cp.async.wait_group %0;" :: "n"(n) : "memory")

#define FMA_F32X2(d, a, b) \
    asm("fma.rn.f32x2 %0, %1, %2, %0;" : "+l"(d) : "l"(a), "l"(b))
#define UNPACK_F32X2(lo, hi, v) \
    asm("mov.b64 {%0, %1}, %2;" : "=f"(lo), "=f"(hi) : "l"(v))
#define PACK_F32X2(d, lo, hi) \
    asm("mov.b64 %0, {%1, %2};" : "=l"(d) : "f"(lo), "f"(hi))

__device__ __forceinline__ uint32_t smem_u32(const void* p) {
    uint32_t a;
    asm("{ .reg .u64 t; cvta.to.shared.u64 t, %1; cvt.u32.u64 %0, t; }" : "=r"(a) : "l"(p));
    return a;
}

#define GEMM_SMEM (2 * 40960)

__global__ void __launch_bounds__(256) k_mgemm(
    const __nv_bfloat16* __restrict__ X1h, const __nv_bfloat16* __restrict__ X1l, int K1,
    const __nv_bfloat16* __restrict__ X2h, const __nv_bfloat16* __restrict__ X2l, int K2,
    const __nv_bfloat16* __restrict__ Wh,  const __nv_bfloat16* __restrict__ Wl,
    const float* __restrict__ bias, float* __restrict__ Y,
    __nv_bfloat16* __restrict__ Yh, __nv_bfloat16* __restrict__ Yl,
    const float* __restrict__ lnw, const float* __restrict__ lnb,
    const int* __restrict__ batch,
    int nrows, int ncols, int act)
{
    extern __shared__ char smem[];
    const uint32_t sb = smem_u32(smem);
    const int tid = threadIdx.x;
    const int wid = tid >> 5, lane = tid & 31;
    const int wm = wid & 1, wn = wid >> 1;
    const int g = lane >> 2, t = lane & 3;
    const int rbase = blockIdx.x * 128, cbase = blockIdx.y * 128;
    const int Ktot = K1 + K2;
    const int nch = Ktot >> 5;

    const int srow = tid >> 1;
    const int sseg = (tid & 1) * 2;

    float acc[4][4][4];
#pragma unroll
    for (int i = 0; i < 4; i++)
#pragma unroll
        for (int j = 0; j < 4; j++)
#pragma unroll
            for (int q = 0; q < 4; q++) acc[i][j][q] = 0.f;

    const int quad = lane >> 3, li = lane & 7;
    const int a_row = (quad & 1) * 8 + li;
    const int a_col = (quad >> 1) * 8;
    const int b_row = (quad >> 1) * 8 + li;
    const int b_col = (quad & 1) * 8;

    auto stage = [&](int ch, int buf) {
        const int kk = ch << 5;
        const uint32_t base = sb + buf * 40960;
        {
            const __nv_bfloat16 *Xh, *Xl; int xs, kx;
            if (kk < K1) { Xh = X1h; Xl = X1l; xs = K1; kx = kk; }
            else         { Xh = X2h; Xl = X2l; xs = K2; kx = kk - K1; }
            int gr = rbase + srow;
            uint32_t sz = (gr < nrows) ? 16u : 0u;
            if (gr >= nrows) gr = nrows - 1;
            const __nv_bfloat16* ph = Xh + (size_t)gr * xs + kx;
            const __nv_bfloat16* pl = Xl + (size_t)gr * xs + kx;
#pragma unroll
            for (int q = 0; q < 2; q++) {
                const int seg = sseg + q;
                const uint32_t so = base + srow * 80 + seg * 16;
                CP_ASYNC(so,         ph + seg * 8, sz);
                CP_ASYNC(so + 10240, pl + seg * 8, sz);
            }
        }
        {
            const int gn = cbase + srow;
            const __nv_bfloat16* ph = Wh + (size_t)gn * Ktot + kk;
            const __nv_bfloat16* pl = Wl + (size_t)gn * Ktot + kk;
#pragma unroll
            for (int q = 0; q < 2; q++) {
                const int seg = sseg + q;
                const uint32_t so = base + 20480 + srow * 80 + seg * 16;
                CP_ASYNC(so,         ph + seg * 8, 16u);
                CP_ASYNC(so + 10240, pl + seg * 8, 16u);
            }
        }
        CP_COMMIT();
    };

    stage(0, 0);
    for (int ch = 0; ch < nch; ch++) {
        const int buf = ch & 1;
        const bool more = (ch + 1 < nch);
        if (more) stage(ch + 1, buf ^ 1);
        if (more) { CP_WAIT(1); } else { CP_WAIT(0); }
        __syncthreads();

        const uint32_t base = sb + buf * 40960;
        const uint32_t aah = base + (wm * 64 + a_row) * 80 + a_col * 2;
        const uint32_t bbh = base + 20480 + (wn * 32 + b_row) * 80 + b_col * 2;
#pragma unroll
        for (int s = 0; s < 2; s++) {
            const uint32_t ks2 = s * 32;
            uint32_t ah[4][4], al[4][4];
#pragma unroll
            for (int mt = 0; mt < 4; mt++) {
                LDSM_X4(ah[mt], aah + mt * 1280 + ks2);
                LDSM_X4(al[mt], aah + 10240 + mt * 1280 + ks2);
            }
            uint32_t bh[4][2], bl[4][2];
#pragma unroll
            for (int pr = 0; pr < 2; pr++) {
                uint32_t tmp[4];
                LDSM_X4(tmp, bbh + pr * 1280 + ks2);
                bh[2 * pr][0] = tmp[0]; bh[2 * pr][1] = tmp[1];
                bh[2 * pr + 1][0] = tmp[2]; bh[2 * pr + 1][1] = tmp[3];
                LDSM_X4(tmp, bbh + 10240 + pr * 1280 + ks2);
                bl[2 * pr][0] = tmp[0]; bl[2 * pr][1] = tmp[1];
                bl[2 * pr + 1][0] = tmp[2]; bl[2 * pr + 1][1] = tmp[3];
            }
#pragma unroll
            for (int nt = 0; nt < 4; nt++)
#pragma unroll
                for (int mt = 0; mt < 4; mt++) {
                    MMA_BF16(acc[mt][nt], ah[mt], bh[nt][0], bh[nt][1]);
                    MMA_BF16(acc[mt][nt], ah[mt], bl[nt][0], bl[nt][1]);
                    MMA_BF16(acc[mt][nt], al[mt], bh[nt][0], bh[nt][1]);
                }
        }
        __syncthreads();
    }

    if (act == 2) {
        float* tb = (float*)smem;
#pragma unroll
        for (int mt = 0; mt < 4; mt++)
#pragma unroll
            for (int half = 0; half < 2; half++) {
                int row = wm * 64 + mt * 16 + g + 8 * half;
#pragma unroll
                for (int nt = 0; nt < 4; nt++) {
                    int col = wn * 32 + nt * 8 + 2 * t;
                    tb[row * 132 + col]     = acc[mt][nt][2 * half + 0] + bias[col];
                    tb[row * 132 + col + 1] = acc[mt][nt][2 * half + 1] + bias[col + 1];
                }
            }
        __syncthreads();
        float lw[4], lb[4];
#pragma unroll
        for (int j = 0; j < 4; j++) { lw[j] = lnw[lane + 32 * j]; lb[j] = lnb[lane + 32 * j]; }
#pragma unroll 1
        for (int it = 0; it < 16; it++) {
            int row = wid * 16 + it;
            int grow = rbase + row;
            float v[4];
#pragma unroll
            for (int j = 0; j < 4; j++) v[j] = tb[row * 132 + lane + 32 * j];
            float s = v[0] + v[1] + v[2] + v[3];
            float q = v[0] * v[0];
            q = fmaf(v[1], v[1], q);
            q = fmaf(v[2], v[2], q);
            q = fmaf(v[3], v[3], q);
#pragma unroll
            for (int off = 16; off > 0; off >>= 1) {
                s += __shfl_xor_sync(0xffffffffu, s, off);
                q += __shfl_xor_sync(0xffffffffu, q, off);
            }
            float mean = s * (1.f / 128.f);
            float var = q * (1.f / 128.f) - mean * mean;
            float rstd = rsqrtf(var + 1e-5f);
            if (grow < nrows) {
#pragma unroll
                for (int j = 0; j < 4; j++) {
                    float y = (v[j] - mean) * rstd * lw[j] + lb[j];
                    __nv_bfloat16 h, l; split_bf16(tanh_fast(y), h, l);
                    Yh[(size_t)grow * 128 + lane + 32 * j] = h;
                    Yl[(size_t)grow * 128 + lane + 32 * j] = l;
                }
            }
        }
        return;
    }

    if (act == 3) {
        float* rs = (float*)smem;
        if (tid < 128) rs[tid] = 0.f;
        __syncthreads();
#pragma unroll
        for (int mt = 0; mt < 4; mt++)
#pragma unroll
            for (int half = 0; half < 2; half++) {
                float p = 0.f;
#pragma unroll
                for (int nt = 0; nt < 4; nt++) {
                    int col = cbase + wn * 32 + nt * 8 + 2 * t;
                    float v0 = fmaxf(acc[mt][nt][2 * half + 0] + bias[col], 0.f);
                    float v1 = fmaxf(acc[mt][nt][2 * half + 1] + bias[col + 1], 0.f);
                    p = fmaf(v0, lnw[col], p);
                    p = fmaf(v1, lnw[col + 1], p);
                }
                p += __shfl_xor_sync(0xffffffffu, p, 1);
                p += __shfl_xor_sync(0xffffffffu, p, 2);
                if (t == 0) atomicAdd(&rs[wm * 64 + mt * 16 + g + 8 * half], p);
            }
        __syncthreads();
        if (tid < 128) {
            int grow = rbase + tid;
            if (grow < nrows) {
                float v = rs[tid];
                if (cbase == 0) v += lnb[0];
                atomicAdd(&g_gsum[batch[grow]], v);
            }
        }
        return;
    }

#pragma unroll
    for (int mt = 0; mt < 4; mt++) {
#pragma unroll
        for (int half = 0; half < 2; half++) {
            int row = rbase + wm * 64 + mt * 16 + g + 8 * half;
            if (row >= nrows) continue;
#pragma unroll
            for (int nt = 0; nt < 4; nt++) {
                int col = cbase + wn * 32 + nt * 8 + 2 * t;
                float v0 = acc[mt][nt][2 * half + 0] + bias[col];
                float v1 = acc[mt][nt][2 * half + 1] + bias[col + 1];
                if (act == 1) { v0 = fmaxf(v0, 0.f); v1 = fmaxf(v1, 0.f); }
                if (Y) {
                    float2 v; v.x = v0; v.y = v1;
                    *(float2*)(Y + (size_t)row * ncols + col) = v;
                }
                if (Yh) {
                    __nv_bfloat16 h0, l0, h1, l1;
                    split_bf16(v0, h0, l0);
                    split_bf16(v1, h1, l1);
                    __nv_bfloat162 hp; hp.x = h0; hp.y = h1;
                    __nv_bfloat162 lp; lp.x = l0; lp.y = l1;
                    *(__nv_bfloat162*)(Yh + (size_t)row * ncols + col) = hp;
                    *(__nv_bfloat162*)(Yl + (size_t)row * ncols + col) = lp;
                }
            }
        }
    }
}

// ---------------- fused message + LN + tanh + aggregate (warp per dst node) ----
// M lives in shared memory (8KB, f32x2-packed) -> ~60 regs -> 4 blocks/SM.
__global__ void __launch_bounds__(256) k_msg(
    const float* __restrict__ yab, const float* __restrict__ Mw,
    const float* __restrict__ lnw, const float* __restrict__ lnb,
    const float* __restrict__ raw,
    __nv_bfloat16* __restrict__ aggh, __nv_bfloat16* __restrict__ aggl)
{
    __shared__ unsigned long long sMp[8][128];
    const int tid = threadIdx.x;
    for (int i = tid; i < 1024; i += 256) {
        int k2 = i >> 7, c = i & 127;
        float m0 = Mw[(2 * k2) * 128 + c];
        float m1 = Mw[(2 * k2 + 1) * 128 + c];
        unsigned long long v; PACK_F32X2(v, m0, m1);
        sMp[k2][c] = v;
    }
    __syncthreads();

    int warp = (blockIdx.x * blockDim.x + tid) >> 5;
    int lane = tid & 31;
    if (warp >= NN) return;

    float bj[4], lw[4], lb[4], accj[4];
#pragma unroll
    for (int j = 0; j < 4; j++) {
        bj[j] = yab[(size_t)warp * 256 + 128 + lane + 32 * j];
        lw[j] = lnw[lane + 32 * j];
        lb[j] = lnb[lane + 32 * j];
        accj[j] = 0.f;
    }

    int p0 = g_row[warp], p1 = g_row[warp + 1];
    if (p0 < p1) {
        int eid_n = g_peid[p0];
        int src_n = g_psrc[p0];
        if (lane == 0) prefetch_l1(raw + (size_t)eid_n * 16);
        float an[4];
        {
            const float* arn = yab + (size_t)src_n * 256;
#pragma unroll
            for (int j = 0; j < 4; j++) an[j] = arn[lane + 32 * j];
        }
        for (int p = p0; p < p1; p++) {
            const int eid = eid_n;
            float ca[4] = {an[0], an[1], an[2], an[3]};
            if (p + 1 < p1) {
                src_n = g_psrc[p + 1];
                eid_n = g_peid[p + 1];
                if (lane == 0) prefetch_l1(raw + (size_t)eid_n * 16);
                const float* arn = yab + (size_t)src_n * 256;
#pragma unroll
                for (int j = 0; j < 4; j++) an[j] = arn[lane + 32 * j];
            }
            const ulonglong2* rp = (const ulonglong2*)(raw + (size_t)eid * 16);
            ulonglong2 u0 = rp[0], u1 = rp[1], u2 = rp[2], u3 = rp[3];
            unsigned long long rvp[8] = {u0.x, u0.y, u1.x, u1.y, u2.x, u2.y, u3.x, u3.y};
            unsigned long long accp[4] = {0ull, 0ull, 0ull, 0ull};
#pragma unroll
            for (int k2 = 0; k2 < 8; k2++)
#pragma unroll
                for (int j = 0; j < 4; j++)
                    FMA_F32X2(accp[j], rvp[k2], sMp[k2][lane + 32 * j]);
            float pre[4];
#pragma unroll
            for (int j = 0; j < 4; j++) {
                float e, o;
                UNPACK_F32X2(e, o, accp[j]);
                pre[j] = (bj[j] + ca[j]) + (e + o);
            }
            float s = pre[0] + pre[1] + pre[2] + pre[3];
            float q = pre[0] * pre[0];
            q = fmaf(pre[1], pre[1], q);
            q = fmaf(pre[2], pre[2], q);
            q = fmaf(pre[3], pre[3], q);
#pragma unroll
            for (int off = 16; off > 0; off >>= 1) {
                s += __shfl_xor_sync(0xffffffffu, s, off);
                q += __shfl_xor_sync(0xffffffffu, q, off);
            }
            float mean = s * (1.f / 128.f);
            float var = q * (1.f / 128.f) - mean * mean;
            float rstd = rsqrtf(var + 1e-5f);
#pragma unroll
            for (int j = 0; j < 4; j++) {
                float y = (pre[j] - mean) * rstd * lw[j] + lb[j];
                accj[j] += tanh_fast(y);
            }
        }
    }
#pragma unroll
    for (int j = 0; j < 4; j++) {
        __nv_bfloat16 h, l; split_bf16(accj[j], h, l);
        aggh[(size_t)warp * 128 + lane + 32 * j] = h;
        aggl[(size_t)warp * 128 + lane + 32 * j] = l;
    }
}

__global__ void k_final(float* __restrict__ out) {
    int g = blockIdx.x * blockDim.x + threadIdx.x;
    if (g < NG) out[g] = g_gsum[g] / fmaxf(g_gcnt[g], 1.0f);
}

// ---------------- host orchestration --------------------------------------------
extern "C" void kernel_launch(void* const* d_in, const int* in_sizes, int n_in,
                              void* d_out, int out_size)
{
    const float* x      = (const float*)d_in[0];
    const int*   ei     = (const int*)  d_in[1];
    const float* raw    = (const float*)d_in[2];
    const int*   batch  = (const int*)  d_in[3];
    const float* atomsW = (const float*)d_in[4];
    const float* atomsb = (const float*)d_in[5];
    const float* bondsW = (const float*)d_in[6];
    const float* bondsb = (const float*)d_in[7];
    const float* msgW   = (const float*)d_in[8];
    const float* msgb   = (const float*)d_in[9];
    const float* msglnw = (const float*)d_in[10];
    const float* msglnb = (const float*)d_in[11];
    const float* updW   = (const float*)d_in[12];
    const float* updb   = (const float*)d_in[13];
    const float* updlnw = (const float*)d_in[14];
    const float* updlnb = (const float*)d_in[15];
    const float* fc1W   = (const float*)d_in[16];
    const float* fc1b   = (const float*)d_in[17];
    const float* fc2w   = (const float*)d_in[18];
    const float* fc2b   = (const float*)d_in[19];
    float* out = (float*)d_out;

    const int* src = ei;
    const int* dst = ei + NE;

    cudaFuncSetAttribute(k_mgemm, cudaFuncAttributeMaxDynamicSharedMemorySize, GEMM_SMEM);

    float *p_yab, *p_bab, *p_M, *p_ub0;
    cudaGetSymbolAddress((void**)&p_yab, g_yab);
    cudaGetSymbolAddress((void**)&p_bab, g_bab);
    cudaGetSymbolAddress((void**)&p_M,   g_M);
    cudaGetSymbolAddress((void**)&p_ub0, g_ub0);
    __nv_bfloat16 *p_xh, *p_xl, *p_hh, *p_hl, *p_aggh, *p_aggl;
    __nv_bfloat16 *p_wabh, *p_wabl, *p_updh, *p_updl, *p_fc1h, *p_fc1l;
    __nv_bfloat16 *p_w0h, *p_w0l, *p_u0h, *p_u0l;
    cudaGetSymbolAddress((void**)&p_xh,   g_xh);
    cudaGetSymbolAddress((void**)&p_xl,   g_xl);
    cudaGetSymbolAddress((void**)&p_hh,   g_hh);
    cudaGetSymbolAddress((void**)&p_hl,   g_hl);
    cudaGetSymbolAddress((void**)&p_aggh, g_aggh);
    cudaGetSymbolAddress((void**)&p_aggl, g_aggl);
    cudaGetSymbolAddress((void**)&p_wabh, g_wabt_h);
    cudaGetSymbolAddress((void**)&p_wabl, g_wabt_l);
    cudaGetSymbolAddress((void**)&p_updh, g_updt_h);
    cudaGetSymbolAddress((void**)&p_updl, g_updt_l);
    cudaGetSymbolAddress((void**)&p_fc1h, g_fc1t_h);
    cudaGetSymbolAddress((void**)&p_fc1l, g_fc1t_l);
    cudaGetSymbolAddress((void**)&p_w0h,  g_w0t_h);
    cudaGetSymbolAddress((void**)&p_w0l,  g_w0t_l);
    cudaGetSymbolAddress((void**)&p_u0h,  g_u0t_h);
    cudaGetSymbolAddress((void**)&p_u0l,  g_u0t_l);

    const int SCAN_BLK = (NN + 255) / 256;   // 157
    const int RB = (NN + 127) / 128;
    dim3 g128(RB, 1), g256(RB, 2);

    // 0: packing + folding + init
    k_pack_all<<<(PACK_TOTAL + 255) / 256, 256>>>(msgW, bondsW, bondsb, msgb,
                                                  atomsW, atomsb, updW, updb, fc1W, x, batch);
    // 1-2: CSR degree + scan phase 1
    k_deg<<<(NE + 255) / 256, 256>>>(dst);
    k_scan1<<<SCAN_BLK, 256>>>();

    // 3 (ncu capture target): wab0 GEMM  A|B = x @ W0ab (K=64)
    k_mgemm<<<g256, 256, GEMM_SMEM>>>(p_xh, p_xl, 64,
                                      (const __nv_bfloat16*)0, (const __nv_bfloat16*)0, 0,
                                      p_w0h, p_w0l, p_bab, p_yab,
                                      (__nv_bfloat16*)0, (__nv_bfloat16*)0,
                                      (const float*)0, (const float*)0, (const int*)0,
                                      NN, 256, 0);

    // 4-6: finish CSR
    k_scan2<<<1, 256>>>(SCAN_BLK);
    k_scan3<<<SCAN_BLK, 256>>>();
    k_fill<<<(NE + 255) / 256, 256>>>(src, dst);

    // 7: msg0, 8: upd0 (K=192: agg | x-folded)
    k_msg<<<(NN * 32 + 255) / 256, 256>>>(p_yab, p_M, msglnw, msglnb, raw, p_aggh, p_aggl);
    k_mgemm<<<g128, 256, GEMM_SMEM>>>(p_aggh, p_aggl, 128, p_xh, p_xl, 64,
                                      p_u0h, p_u0l, p_ub0, (float*)0, p_hh, p_hl,
                                      updlnw, updlnb, (const int*)0, NN, 128, 2);

    for (int l = 1; l < 3; l++) {
        k_mgemm<<<g256, 256, GEMM_SMEM>>>(p_hh, p_hl, 128,
                                          (const __nv_bfloat16*)0, (const __nv_bfloat16*)0, 0,
                                          p_wabh + (size_t)l * 256 * 128, p_wabl + (size_t)l * 256 * 128,
                                          p_bab + l * 256, p_yab,
                                          (__nv_bfloat16*)0, (__nv_bfloat16*)0,
                                          (const float*)0, (const float*)0, (const int*)0,
                                          NN, 256, 0);
        k_msg<<<(NN * 32 + 255) / 256, 256>>>(p_yab, p_M + l * 16 * 128,
                                              msglnw + l * 128, msglnb + l * 128,
                                              raw, p_aggh, p_aggl);
        k_mgemm<<<g128, 256, GEMM_SMEM>>>(p_aggh, p_aggl, 128, p_hh, p_hl, 128,
                                          p_updh + (size_t)l * 128 * 256, p_updl + (size_t)l * 128 * 256,
                                          updb + l * 128, (float*)0, p_hh, p_hl,
                                          updlnw + l * 128, updlnb + l * 128, (const int*)0,
                                          NN, 128, 2);
    }

    // readout: fused fc1 + relu + fc2 dot + pooling
    k_mgemm<<<g256, 256, GEMM_SMEM>>>(p_hh, p_hl, 128,
                                      (const __nv_bfloat16*)0, (const __nv_bfloat16*)0, 0,
                                      p_fc1h, p_fc1l, fc1b, (float*)0,
                                      (__nv_bfloat16*)0, (__nv_bfloat16*)0,
                                      fc2w, fc2b, batch,
                                      NN, 256, 3);
    k_final<<<(NG + 255) / 256, 256>>>(out);
}